// round 11
// baseline (speedup 1.0000x reference)
#include <cuda_runtime.h>
#include <cuda_fp16.h>
#include <math.h>
#include <stdint.h>

// ---------------- problem constants ----------------
#define S 2048
#define HID 4096
#define NH 32
#define NKV 8
#define HD 128
#define GROUPS 4
#define EPS 1e-8f
#define ATT_SCALE 0.08838834764831845f   // 128^-0.5
#define LN10000 9.210340371976184f

// ---------------- scratch (device globals; no allocation allowed) ----------------
__device__ float g_qproj[S * HID];
__device__ float g_kproj[S * NKV * HD];
__device__ float g_vproj[S * NKV * HD];
__device__ float g_qn[S * HID];
__device__ float g_kn[S * NKV * HD];
__device__ float g_memout[S * HID];
__device__ float g_vdelta[S * NKV * HD];
__device__ float g_knsum[NKV * HD];
__device__ float g_knsum_part[16][NKV * HD];
__device__ float g_delta_part[8][NKV * HD * HD];
__device__ float g_nmt[NKV * HD * HD];       // norm_m transposed: [h][d][e]
// fp16 GEMM operands
__device__ __half g_hh[S * HID];
__device__ __half g_wqT[HID * HID];
__device__ __half g_wkT[NKV * HD * HID];
__device__ __half g_wvT[NKV * HD * HID];
__device__ __half g_woT[HID * HID];
__device__ __half g_ch[S * HID];
// fp16 hi/lo planes for attention
__device__ __half g_qh[S * HID];
__device__ __half g_ql[S * HID];
__device__ __half g_kh[S * NKV * HD];
__device__ __half g_kl[S * NKV * HD];
__device__ __half g_vth[NKV * HD * S];
__device__ __half g_vtl[NKV * HD * S];

// ---------------- fp16 mma + ldmatrix ----------------
__device__ __forceinline__ void mma_f16(
    float& c0, float& c1, float& c2, float& c3,
    uint32_t a0, uint32_t a1, uint32_t a2, uint32_t a3,
    uint32_t b0, uint32_t b1)
{
    asm volatile(
        "mma.sync.aligned.m16n8k16.row.col.f32.f16.f16.f32 "
        "{%0,%1,%2,%3},{%4,%5,%6,%7},{%8,%9},{%0,%1,%2,%3};"
        : "+f"(c0), "+f"(c1), "+f"(c2), "+f"(c3)
        : "r"(a0), "r"(a1), "r"(a2), "r"(a3), "r"(b0), "r"(b1));
}

#define LDSM4(r0, r1, r2, r3, addr) \
    asm volatile("ldmatrix.sync.aligned.m8n8.x4.shared.b16 {%0,%1,%2,%3}, [%4];" \
                 : "=r"(r0), "=r"(r1), "=r"(r2), "=r"(r3) : "r"(addr))

__device__ __forceinline__ uint32_t h2pack(float a, float b) {
    __half2 h = __floats2half2_rn(a, b);
    return *(uint32_t*)&h;
}
__device__ __forceinline__ void h16split(float x, __half& h, __half& l) {
    h = __float2half_rn(x);
    l = __float2half_rn(x - __half2float(h));
}

// ---------------- pre-pass: fp32 -> fp16 ----------------
__global__ __launch_bounds__(256) void h2h_kernel(
    const float* __restrict__ src, __half* __restrict__ dst, int n4)
{
    for (int i = blockIdx.x * 256 + threadIdx.x; i < n4; i += gridDim.x * 256) {
        float4 v = ((const float4*)src)[i];
        uint2 p = make_uint2(h2pack(v.x, v.y), h2pack(v.z, v.w));
        ((uint2*)dst)[i] = p;
    }
}

// transpose: w[K][N] fp32 -> wT[N][K] fp16
__global__ __launch_bounds__(256) void wtrans_kernel(
    const float* __restrict__ w, __half* __restrict__ wt, int Kd, int Nd)
{
    __shared__ float t[32][33];
    const int bx = blockIdx.x;
    const int by = blockIdx.y;
    const int x = threadIdx.x & 31;
    const int y = threadIdx.x >> 5;
#pragma unroll
    for (int j = 0; j < 4; j++) {
        int kr = y + 8 * j;
        t[kr][x] = w[(size_t)(by * 32 + kr) * Nd + bx * 32 + x];
    }
    __syncthreads();
#pragma unroll
    for (int j = 0; j < 4; j++) {
        int nr = y + 8 * j;
        wt[(size_t)(bx * 32 + nr) * Kd + by * 32 + x] = __float2half_rn(t[x][nr]);
    }
}

// transpose fp32 norm_m [h][e][d] -> nmt [h][d][e]
__global__ __launch_bounds__(256) void ntrans_kernel(
    const float* __restrict__ nm, float* __restrict__ nmt)
{
    __shared__ float t[32][33];
    const int h = blockIdx.z;
    const int bx = blockIdx.x;   // d tile
    const int by = blockIdx.y;   // e tile
    const int x = threadIdx.x & 31;
    const int y = threadIdx.x >> 5;
    const float* src = nm + h * HD * HD;
    float* dst = nmt + h * HD * HD;
#pragma unroll
    for (int j = 0; j < 4; j++) {
        int er = y + 8 * j;
        t[er][x] = src[(by * 32 + er) * HD + bx * 32 + x];
    }
    __syncthreads();
#pragma unroll
    for (int j = 0; j < 4; j++) {
        int dr = y + 8 * j;
        dst[(bx * 32 + dr) * HD + by * 32 + x] = t[x][dr];
    }
}

// ---------------- GEMM: fp16 m16n8k16 + ldmatrix, 4 warps, 64x64 warp tile, BK=32 ----------------
#define HAS_STR 40
#define HBS_STR 40
#define STG4_BYTES ((128 * HAS_STR + 128 * HBS_STR) * 2)   // 20480
#define GEMM4_SMEM (3 * STG4_BYTES)                        // 61440

#define CP16(dst_u32, src_ptr) \
    asm volatile("cp.async.cg.shared.global [%0], [%1], 16;" :: "r"(dst_u32), "l"(src_ptr))

__global__ __launch_bounds__(128, 3) void gemm_f16_kernel(
    const __half* __restrict__ A,
    const __half* __restrict__ B0, float* __restrict__ C0, int N0,
    const __half* __restrict__ B1, float* __restrict__ C1,
    const __half* __restrict__ B2, float* __restrict__ C2, int N12,
    int K)
{
    const __half* Bt;
    float* C;
    int N, bx;
    if (blockIdx.z == 0) {
        Bt = B0; C = C0; N = N0; bx = blockIdx.x;
        if (bx * 128 >= N0) return;
    } else {
        N = N12;
        const int nt12 = N12 / 128;
        if ((int)blockIdx.x < nt12) { Bt = B1; C = C1; bx = blockIdx.x; }
        else if ((int)blockIdx.x < 2 * nt12) { Bt = B2; C = C2; bx = blockIdx.x - nt12; }
        else return;
    }

    extern __shared__ __half smh[];
    const uint32_t smu = (uint32_t)__cvta_generic_to_shared(smh);

    const int tid = threadIdx.x;
    const int lane = tid & 31;
    const int wid = tid >> 5;
    const int wm = wid >> 1;
    const int wn = wid & 1;
    const int lr = lane >> 2;
    const int lc = lane & 3;
    const int by = blockIdx.y;

    const int crow = tid >> 2;
    const int cchk = (tid & 3) * 8;

    const __half* Ab = A + (size_t)(by * 128) * K;
    const __half* Bb = Bt + (size_t)(bx * 128) * K;

    const uint32_t a_lane_off =
        (uint32_t)(((lane & 15) * HAS_STR + ((lane >> 4) << 3)) * 2);
    const uint32_t b_lane_off =
        (uint32_t)((((lane & 7) + ((lane >> 4) << 3)) * HBS_STR + (((lane >> 3) & 1) << 3)) * 2);

    float acc[4][8][4];
#pragma unroll
    for (int i = 0; i < 4; i++)
#pragma unroll
        for (int j = 0; j < 8; j++)
#pragma unroll
            for (int r = 0; r < 4; r++) acc[i][j][r] = 0.f;

    const int NT = K / 32;

#define LOAD_STAGE(stg, ch)                                                           \
    {                                                                                 \
        const uint32_t sb = smu + (uint32_t)((stg) * STG4_BYTES);                     \
        const int k0 = (ch) * 32;                                                     \
        _Pragma("unroll")                                                             \
        for (int i = 0; i < 4; i++) {                                                 \
            const int r = i * 32 + crow;                                              \
            CP16(sb + (uint32_t)((r * HAS_STR + cchk) * 2), Ab + (size_t)r * K + k0 + cchk); \
        }                                                                             \
        _Pragma("unroll")                                                             \
        for (int i = 0; i < 4; i++) {                                                 \
            const int r = i * 32 + crow;                                              \
            CP16(sb + (uint32_t)((128 * HAS_STR + r * HBS_STR + cchk) * 2),           \
                 Bb + (size_t)r * K + k0 + cchk);                                     \
        }                                                                             \
    }

    LOAD_STAGE(0, 0)
    asm volatile("cp.async.commit_group;" ::: "memory");
    LOAD_STAGE(1, 1)
    asm volatile("cp.async.commit_group;" ::: "memory");

    int stage = 0;
    for (int it = 0; it < NT; it++) {
        asm volatile("cp.async.wait_group 1;" ::: "memory");
        __syncthreads();

        const int pf = it + 2;
        if (pf < NT) {
            const int ps = (stage + 2) % 3;
            LOAD_STAGE(ps, pf)
        }
        asm volatile("cp.async.commit_group;" ::: "memory");

        const uint32_t sbA = smu + (uint32_t)(stage * STG4_BYTES);
        const uint32_t sbB = sbA + (uint32_t)(128 * HAS_STR * 2);

#pragma unroll
        for (int ks = 0; ks < 2; ks++) {
            const uint32_t kbB = (uint32_t)(ks * 16 * 2);
            uint32_t af[4][4], bf[8][2];
#pragma unroll
            for (int mt = 0; mt < 4; mt++) {
                const uint32_t addr = sbA
                    + (uint32_t)(((wm * 64 + mt * 16) * HAS_STR) * 2)
                    + a_lane_off + kbB;
                LDSM4(af[mt][0], af[mt][1], af[mt][2], af[mt][3], addr);
            }
#pragma unroll
            for (int ntp = 0; ntp < 4; ntp++) {
                const uint32_t addr = sbB
                    + (uint32_t)(((wn * 64 + ntp * 16) * HBS_STR) * 2)
                    + b_lane_off + kbB;
                LDSM4(bf[2 * ntp][0], bf[2 * ntp][1], bf[2 * ntp + 1][0], bf[2 * ntp + 1][1], addr);
            }
#pragma unroll
            for (int mt = 0; mt < 4; mt++)
#pragma unroll
                for (int nt = 0; nt < 8; nt++)
                    mma_f16(acc[mt][nt][0], acc[mt][nt][1], acc[mt][nt][2], acc[mt][nt][3],
                            af[mt][0], af[mt][1], af[mt][2], af[mt][3],
                            bf[nt][0], bf[nt][1]);
        }
        stage = (stage + 1) % 3;
    }
#undef LOAD_STAGE

#pragma unroll
    for (int mt = 0; mt < 4; mt++) {
        const int row = by * 128 + wm * 64 + mt * 16 + lr;
#pragma unroll
        for (int nt = 0; nt < 8; nt++) {
            const int col = bx * 128 + wn * 64 + nt * 8 + lc * 2;
            float2 v01 = make_float2(acc[mt][nt][0], acc[mt][nt][1]);
            float2 v23 = make_float2(acc[mt][nt][2], acc[mt][nt][3]);
            *(float2*)(C + (size_t)row * N + col) = v01;
            *(float2*)(C + (size_t)(row + 8) * N + col) = v23;
        }
    }
}

// ---------------- qn / kn ----------------
__global__ __launch_bounds__(128) void qn_kernel(const float* __restrict__ qp, float* __restrict__ qn)
{
    const int s = blockIdx.x;
    const int d = threadIdx.x;
    __shared__ float wsum[4];
    for (int h = 0; h < NH; h++) {
        float x = qp[(size_t)s * HID + h * HD + d];
        float f = x > 0.f ? x + 1.f : expf(x);
        float v = f;
#pragma unroll
        for (int o = 16; o; o >>= 1) v += __shfl_xor_sync(0xffffffffu, v, o);
        if ((d & 31) == 0) wsum[d >> 5] = v;
        __syncthreads();
        float tot = wsum[0] + wsum[1] + wsum[2] + wsum[3];
        qn[(size_t)s * HID + h * HD + d] = f / (tot + EPS);
        __syncthreads();
    }
}

__global__ __launch_bounds__(128) void kn_kernel(const float* __restrict__ kp, float* __restrict__ kn)
{
    const int s = blockIdx.x;
    const int d = threadIdx.x;
    __shared__ float wsum[4];
    for (int h = 0; h < NKV; h++) {
        float x = kp[(size_t)s * (NKV * HD) + h * HD + d];
        float f = x > 0.f ? x + 1.f : expf(x);
        float v = f;
#pragma unroll
        for (int o = 16; o; o >>= 1) v += __shfl_xor_sync(0xffffffffu, v, o);
        if ((d & 31) == 0) wsum[d >> 5] = v;
        __syncthreads();
        float tot = wsum[0] + wsum[1] + wsum[2] + wsum[3];
        kn[(size_t)s * (NKV * HD) + h * HD + d] = f / (tot + EPS);
        __syncthreads();
    }
}

__global__ __launch_bounds__(128) void knsum_part_kernel(const float* __restrict__ kn, float* __restrict__ part)
{
    const int h = blockIdx.x;
    const int p = blockIdx.y;
    const int d = threadIdx.x;
    float acc = 0.f;
    const int s0 = p * 128;
#pragma unroll 4
    for (int s = s0; s < s0 + 128; s++)
        acc += kn[(size_t)s * (NKV * HD) + h * HD + d];
    part[p * (NKV * HD) + h * HD + d] = acc;
}

__global__ __launch_bounds__(1024) void knsum_final_kernel(const float* __restrict__ part, float* __restrict__ knsum)
{
    const int i = threadIdx.x;
    float acc = 0.f;
#pragma unroll
    for (int p = 0; p < 16; p++) acc += part[p * (NKV * HD) + i];
    knsum[i] = acc;
}

// ---------------- memory retrieval (r-major threading, float4 B reads) ----------------
// block 128 = 16 rows x 8 e-groups; thread: 1 row, 16 e's. Both B matrices [d][e] K-major.
__global__ __launch_bounds__(128) void retrieve_kernel(
    const float* __restrict__ qn, const float* __restrict__ memory,
    const float* __restrict__ nmt, float* __restrict__ memout)
{
    const int h = blockIdx.y;
    const int st = blockIdx.x;
    const int hm = h & (NKV - 1);
    const int tid = threadIdx.x;
    const int r = tid >> 3;
    const int e0 = (tid & 7) * 16;
    __shared__ float Qs[16][128];
    __shared__ float Ms[32][128];
    __shared__ float Ns[32][128];

    for (int i = tid; i < 16 * 128; i += 128) {
        int rr = i >> 7, d = i & 127;
        Qs[rr][d] = qn[(size_t)(st * 16 + rr) * HID + h * HD + d];
    }
    float num[16], den[16];
#pragma unroll
    for (int j = 0; j < 16; j++) { num[j] = 0.f; den[j] = 0.f; }
    const float* M = memory + hm * HD * HD;
    const float* Nm = nmt + hm * HD * HD;

    for (int d0 = 0; d0 < 128; d0 += 32) {
        __syncthreads();
        for (int i = tid; i < 32 * 128; i += 128) {
            int dd = i >> 7, ee = i & 127;
            Ms[dd][ee] = M[(d0 + dd) * HD + ee];
            Ns[dd][ee] = Nm[(d0 + dd) * HD + ee];
        }
        __syncthreads();
#pragma unroll 8
        for (int dd = 0; dd < 32; dd++) {
            const float qv = Qs[r][d0 + dd];
#pragma unroll
            for (int j4 = 0; j4 < 4; j4++) {
                float4 mv = *(const float4*)(&Ms[dd][e0 + j4 * 4]);
                float4 nv = *(const float4*)(&Ns[dd][e0 + j4 * 4]);
                num[j4 * 4 + 0] += qv * mv.x;
                num[j4 * 4 + 1] += qv * mv.y;
                num[j4 * 4 + 2] += qv * mv.z;
                num[j4 * 4 + 3] += qv * mv.w;
                den[j4 * 4 + 0] += qv * nv.x;
                den[j4 * 4 + 1] += qv * nv.y;
                den[j4 * 4 + 2] += qv * nv.z;
                den[j4 * 4 + 3] += qv * nv.w;
            }
        }
    }
    float* dst = memout + (size_t)(st * 16 + r) * HID + h * HD + e0;
#pragma unroll
    for (int j4 = 0; j4 < 4; j4++) {
        float4 o;
        o.x = num[j4 * 4 + 0] / (den[j4 * 4 + 0] + EPS);
        o.y = num[j4 * 4 + 1] / (den[j4 * 4 + 1] + EPS);
        o.z = num[j4 * 4 + 2] / (den[j4 * 4 + 2] + EPS);
        o.w = num[j4 * 4 + 3] / (den[j4 * 4 + 3] + EPS);
        *(float4*)(dst + j4 * 4) = o;
    }
}

// ---------------- v - v_ret for delta rule (same structure) ----------------
__global__ __launch_bounds__(128) void vdelta_kernel(
    const float* __restrict__ kn, const float* __restrict__ vproj,
    const float* __restrict__ memory, const float* __restrict__ nmt,
    float* __restrict__ vdelta)
{
    const int h = blockIdx.y;
    const int st = blockIdx.x;
    const int tid = threadIdx.x;
    const int r = tid >> 3;
    const int e0 = (tid & 7) * 16;
    __shared__ float Qs[16][128];
    __shared__ float Ms[32][128];
    __shared__ float Ns[32][128];

    for (int i = tid; i < 16 * 128; i += 128) {
        int rr = i >> 7, d = i & 127;
        Qs[rr][d] = kn[(size_t)(st * 16 + rr) * (NKV * HD) + h * HD + d];
    }
    float num[16], den[16];
#pragma unroll
    for (int j = 0; j < 16; j++) { num[j] = 0.f; den[j] = 0.f; }
    const float* M = memory + h * HD * HD;
    const float* Nm = nmt + h * HD * HD;

    for (int d0 = 0; d0 < 128; d0 += 32) {
        __syncthreads();
        for (int i = tid; i < 32 * 128; i += 128) {
            int dd = i >> 7, ee = i & 127;
            Ms[dd][ee] = M[(d0 + dd) * HD + ee];
            Ns[dd][ee] = Nm[(d0 + dd) * HD + ee];
        }
        __syncthreads();
#pragma unroll 8
        for (int dd = 0; dd < 32; dd++) {
            const float qv = Qs[r][d0 + dd];
#pragma unroll
            for (int j4 = 0; j4 < 4; j4++) {
                float4 mv = *(const float4*)(&Ms[dd][e0 + j4 * 4]);
                float4 nv = *(const float4*)(&Ns[dd][e0 + j4 * 4]);
                num[j4 * 4 + 0] += qv * mv.x;
                num[j4 * 4 + 1] += qv * mv.y;
                num[j4 * 4 + 2] += qv * mv.z;
                num[j4 * 4 + 3] += qv * mv.w;
                den[j4 * 4 + 0] += qv * nv.x;
                den[j4 * 4 + 1] += qv * nv.y;
                den[j4 * 4 + 2] += qv * nv.z;
                den[j4 * 4 + 3] += qv * nv.w;
            }
        }
    }
    const float* vsrc = vproj + (size_t)(st * 16 + r) * (NKV * HD) + h * HD + e0;
    float* dst = vdelta + (size_t)(st * 16 + r) * (NKV * HD) + h * HD + e0;
#pragma unroll
    for (int j4 = 0; j4 < 4; j4++) {
        float4 vv = *(const float4*)(vsrc + j4 * 4);
        float4 o;
        o.x = vv.x - num[j4 * 4 + 0] / (den[j4 * 4 + 0] + EPS);
        o.y = vv.y - num[j4 * 4 + 1] / (den[j4 * 4 + 1] + EPS);
        o.z = vv.z - num[j4 * 4 + 2] / (den[j4 * 4 + 2] + EPS);
        o.w = vv.w - num[j4 * 4 + 3] / (den[j4 * 4 + 3] + EPS);
        *(float4*)(dst + j4 * 4) = o;
    }
}

// ---------------- RoPE + fp16 hi/lo split for Q,K ----------------
__global__ __launch_bounds__(256) void rope_split_kernel(
    const float* __restrict__ q, const float* __restrict__ k, const int* __restrict__ pos,
    __half* __restrict__ qh, __half* __restrict__ ql,
    __half* __restrict__ kh, __half* __restrict__ kl)
{
    const int s = blockIdx.x;
    const int idx = blockIdx.y * 256 + threadIdx.x;
    if (idx >= (NH + NKV) * 64) return;
    const int head = idx >> 6;
    const int d = idx & 63;
    const float p = (float)pos[s];
    const float invf = expf(-(2.0f * (float)d / 128.0f) * LN10000);
    const float a = p * invf;
    const float c = cosf(a), sn = sinf(a);
    const float* base;
    __half *oh, *ol;
    if (head < NH) {
        size_t off = (size_t)s * HID + head * HD;
        base = q + off; oh = qh + off; ol = ql + off;
    } else {
        size_t off = (size_t)s * (NKV * HD) + (head - NH) * HD;
        base = k + off; oh = kh + off; ol = kl + off;
    }
    float x0 = base[d], x1 = base[d + 64];
    float r0 = x0 * c - x1 * sn;
    float r1 = x1 * c + x0 * sn;
    __half h, l;
    h16split(r0, h, l);
    oh[d] = h; ol[d] = l;
    h16split(r1, h, l);
    oh[d + 64] = h; ol[d + 64] = l;
}

// ---------------- V transpose + split ----------------
__global__ __launch_bounds__(256) void vtrans_split_kernel(
    const float* __restrict__ v, __half* __restrict__ vth, __half* __restrict__ vtl)
{
    __shared__ float t[32][33];
    const int bx = blockIdx.x;
    const int by = blockIdx.y;
    const int x = threadIdx.x & 31;
    const int y = threadIdx.x >> 5;
#pragma unroll
    for (int j = 0; j < 4; j++) {
        int sr = y + 8 * j;
        t[sr][x] = v[(size_t)(bx * 32 + sr) * (NKV * HD) + by * 32 + x];
    }
    __syncthreads();
#pragma unroll
    for (int j = 0; j < 4; j++) {
        int cr = y + 8 * j;
        float val = t[x][cr];
        __half h, l;
        h16split(val, h, l);
        size_t idx = (size_t)(by * 32 + cr) * S + bx * 32 + x;
        vth[idx] = h;
        vtl[idx] = l;
    }
}

// ---------------- fp16-split MMA flash attention ----------------
#define QH_STR 136
#define KH_STR 136
#define VT_STR 72
#define PH_STR 72
#define SM_QH 0
#define SM_QL (128 * QH_STR)
#define SM_KH (SM_QL + 128 * QH_STR)
#define SM_KL (SM_KH + 64 * KH_STR)
#define SM_VTH (SM_KL + 64 * KH_STR)
#define SM_VTL (SM_VTH + 128 * VT_STR)
#define SM_PH (SM_VTL + 128 * VT_STR)
#define SM_PL (SM_PH + 128 * PH_STR)
#define ATT2_SMEM_HALVES (SM_PL + 128 * PH_STR)
#define ATT2_SMEM_BYTES (ATT2_SMEM_HALVES * 2)

__global__ __launch_bounds__(256) void attn_f16_kernel(
    const __half* __restrict__ qh, const __half* __restrict__ ql,
    const __half* __restrict__ kh, const __half* __restrict__ kl,
    const __half* __restrict__ vth, const __half* __restrict__ vtl,
    const float* __restrict__ memout, const float* __restrict__ beta,
    __half* __restrict__ ch)
{
    const int h = blockIdx.y;
    const int qt = (int)gridDim.x - 1 - (int)blockIdx.x;
    const int kvh = h >> 2;
    const int tid = threadIdx.x;
    const int warp = tid >> 5;
    const int lane = tid & 31;
    const int lr = lane >> 2;
    const int lc = lane & 3;

    extern __shared__ __half sh[];
    __half* Qh_ = sh + SM_QH;
    __half* Ql_ = sh + SM_QL;
    __half* Kh_ = sh + SM_KH;
    __half* Kl_ = sh + SM_KL;
    __half* Vth_ = sh + SM_VTH;
    __half* Vtl_ = sh + SM_VTL;
    __half* Ph_ = sh + SM_PH;
    __half* Pl_ = sh + SM_PL;

#pragma unroll
    for (int it = 0; it < 8; it++) {
        int i = it * 256 + tid;
        int row = i >> 4, c8 = (i & 15) * 8;
        size_t gidx = (size_t)(qt * 128 + row) * HID + h * HD + c8;
        *(uint4*)(Qh_ + row * QH_STR + c8) = *(const uint4*)(qh + gidx);
        *(uint4*)(Ql_ + row * QH_STR + c8) = *(const uint4*)(ql + gidx);
    }

    const int row0 = warp * 16 + lr;
    const int row1 = row0 + 8;
    const int grow0 = qt * 128 + row0;
    const int grow1 = grow0 + 8;

    float m0 = -1e30f, m1 = -1e30f, l0 = 0.f, l1 = 0.f;
    float o[16][4];
#pragma unroll
    for (int nt = 0; nt < 16; nt++)
#pragma unroll
        for (int r = 0; r < 4; r++) o[nt][r] = 0.f;

    const int ktmax = 2 * qt + 1;
    for (int kt = 0; kt <= ktmax; kt++) {
        __syncthreads();
#pragma unroll
        for (int it = 0; it < 4; it++) {
            int i = it * 256 + tid;
            int key = i >> 4, c8 = (i & 15) * 8;
            size_t gidx = (size_t)(kt * 64 + key) * (NKV * HD) + kvh * HD + c8;
            *(uint4*)(Kh_ + key * KH_STR + c8) = *(const uint4*)(kh + gidx);
            *(uint4*)(Kl_ + key * KH_STR + c8) = *(const uint4*)(kl + gidx);
        }
#pragma unroll
        for (int it = 0; it < 4; it++) {
            int i = it * 256 + tid;
            int dr = i >> 3, kc = (i & 7) * 8;
            size_t gidx = (size_t)(kvh * HD + dr) * S + kt * 64 + kc;
            *(uint4*)(Vth_ + dr * VT_STR + kc) = *(const uint4*)(vth + gidx);
            *(uint4*)(Vtl_ + dr * VT_STR + kc) = *(const uint4*)(vtl + gidx);
        }
        __syncthreads();

        float sc[8][4];
#pragma unroll
        for (int nt = 0; nt < 8; nt++)
#pragma unroll
            for (int r = 0; r < 4; r++) sc[nt][r] = 0.f;

#pragma unroll
        for (int ks = 0; ks < 8; ks++) {
            const int kb = ks * 16;
            uint32_t ah[4], al[4];
            {
                const __half* p0 = Qh_ + row0 * QH_STR + kb + 2 * lc;
                const __half* p1 = Qh_ + row1 * QH_STR + kb + 2 * lc;
                ah[0] = *(const uint32_t*)(p0);
                ah[1] = *(const uint32_t*)(p1);
                ah[2] = *(const uint32_t*)(p0 + 8);
                ah[3] = *(const uint32_t*)(p1 + 8);
                const __half* q0 = Ql_ + row0 * QH_STR + kb + 2 * lc;
                const __half* q1 = Ql_ + row1 * QH_STR + kb + 2 * lc;
                al[0] = *(const uint32_t*)(q0);
                al[1] = *(const uint32_t*)(q1);
                al[2] = *(const uint32_t*)(q0 + 8);
                al[3] = *(const uint32_t*)(q1 + 8);
            }
#pragma unroll
            for (int nt = 0; nt < 8; nt++) {
                const int n0 = nt * 8 + lr;
                const __half* ph = Kh_ + n0 * KH_STR + kb + 2 * lc;
                const __half* pl = Kl_ + n0 * KH_STR + kb + 2 * lc;
                uint32_t bh0 = *(const uint32_t*)(ph);
                uint32_t bh1 = *(const uint32_t*)(ph + 8);
                uint32_t bl0 = *(const uint32_t*)(pl);
                uint32_t bl1 = *(const uint32_t*)(pl + 8);
                mma_f16(sc[nt][0], sc[nt][1], sc[nt][2], sc[nt][3],
                        ah[0], ah[1], ah[2], ah[3], bh0, bh1);
                mma_f16(sc[nt][0], sc[nt][1], sc[nt][2], sc[nt][3],
                        ah[0], ah[1], ah[2], ah[3], bl0, bl1);
                mma_f16(sc[nt][0], sc[nt][1], sc[nt][2], sc[nt][3],
                        al[0], al[1], al[2], al[3], bh0, bh1);
            }
        }

        const bool need_mask = (kt >= 2 * qt);
        float mx0 = -1e30f, mx1 = -1e30f;
#pragma unroll
        for (int nt = 0; nt < 8; nt++) {
#pragma unroll
            for (int j = 0; j < 2; j++) {
                int col = kt * 64 + nt * 8 + 2 * lc + j;
                float s0 = sc[nt][j] * ATT_SCALE;
                float s1 = sc[nt][2 + j] * ATT_SCALE;
                if (need_mask) {
                    if (col > grow0) s0 = -1e30f;
                    if (col > grow1) s1 = -1e30f;
                }
                sc[nt][j] = s0;
                sc[nt][2 + j] = s1;
                mx0 = fmaxf(mx0, s0);
                mx1 = fmaxf(mx1, s1);
            }
        }
        mx0 = fmaxf(mx0, __shfl_xor_sync(0xffffffffu, mx0, 1));
        mx0 = fmaxf(mx0, __shfl_xor_sync(0xffffffffu, mx0, 2));
        mx1 = fmaxf(mx1, __shfl_xor_sync(0xffffffffu, mx1, 1));
        mx1 = fmaxf(mx1, __shfl_xor_sync(0xffffffffu, mx1, 2));
        const float mn0 = fmaxf(m0, mx0);
        const float mn1 = fmaxf(m1, mx1);
        const float scl0 = __expf(m0 - mn0);
        const float scl1 = __expf(m1 - mn1);
        float ls0 = 0.f, ls1 = 0.f;
#pragma unroll
        for (int nt = 0; nt < 8; nt++) {
            float p00 = __expf(sc[nt][0] - mn0);
            float p01 = __expf(sc[nt][1] - mn0);
            float p10 = __expf(sc[nt][2] - mn1);
            float p11 = __expf(sc[nt][3] - mn1);
            ls0 += p00 + p01;
            ls1 += p10 + p11;
            __half h0, l0h, h1, l1h;
            h16split(p00, h0, l0h);
            h16split(p01, h1, l1h);
            *(uint32_t*)(Ph_ + row0 * PH_STR + nt * 8 + 2 * lc) =
                (uint32_t)__half_as_ushort(h0) | ((uint32_t)__half_as_ushort(h1) << 16);
            *(uint32_t*)(Pl_ + row0 * PH_STR + nt * 8 + 2 * lc) =
                (uint32_t)__half_as_ushort(l0h) | ((uint32_t)__half_as_ushort(l1h) << 16);
            h16split(p10, h0, l0h);
            h16split(p11, h1, l1h);
            *(uint32_t*)(Ph_ + row1 * PH_STR + nt * 8 + 2 * lc) =
                (uint32_t)__half_as_ushort(h0) | ((uint32_t)__half_as_ushort(h1) << 16);
            *(uint32_t*)(Pl_ + row1 * PH_STR + nt * 8 + 2 * lc) =
                (uint32_t)__half_as_ushort(l0h) | ((uint32_t)__half_as_ushort(l1h) << 16);
        }
        ls0 += __shfl_xor_sync(0xffffffffu, ls0, 1);
        ls0 += __shfl_xor_sync(0xffffffffu, ls0, 2);
        ls1 += __shfl_xor_sync(0xffffffffu, ls1, 1);
        ls1 += __shfl_xor_sync(0xffffffffu, ls1, 2);
        l0 = l0 * scl0 + ls0;
        l1 = l1 * scl1 + ls1;
        m0 = mn0;
        m1 = mn1;

#pragma unroll
        for (int nt = 0; nt < 16; nt++) {
            o[nt][0] *= scl0;
            o[nt][1] *= scl0;
            o[nt][2] *= scl1;
            o[nt][3] *= scl1;
        }
        __syncwarp();

#pragma unroll
        for (int ks2 = 0; ks2 < 4; ks2++) {
            const int kb = ks2 * 16;
            uint32_t ah[4], al[4];
            {
                const __half* p0 = Ph_ + row0 * PH_STR + kb + 2 * lc;
                const __half* p1 = Ph_ + row1 * PH_STR + kb + 2 * lc;
                ah[0] = *(const uint32_t*)(p0);
                ah[1] = *(const uint32_t*)(p1);
                ah[2] = *(const uint32_t*)(p0 + 8);
                ah[3] = *(const uint32_t*)(p1 + 8);
                const __half* q0 = Pl_ + row0 * PH_STR + kb + 2 * lc;
                const __half* q1 = Pl_ + row1 * PH_STR + kb + 2 * lc;
                al[0] = *(const uint32_t*)(q0);
                al[1] = *(const uint32_t*)(q1);
                al[2] = *(const uint32_t*)(q0 + 8);
                al[3] = *(const uint32_t*)(q1 + 8);
            }
#pragma unroll
            for (int nt = 0; nt < 16; nt++) {
                const int n0 = nt * 8 + lr;
                const __half* ph = Vth_ + n0 * VT_STR + kb + 2 * lc;
                const __half* pl = Vtl_ + n0 * VT_STR + kb + 2 * lc;
                uint32_t bh0 = *(const uint32_t*)(ph);
                uint32_t bh1 = *(const uint32_t*)(ph + 8);
                uint32_t bl0 = *(const uint32_t*)(pl);
                uint32_t bl1 = *(const uint32_t*)(pl + 8);
                mma_f16(o[nt][0], o[nt][1], o[nt][2], o[nt][3],
                        ah[0], ah[1], ah[2], ah[3], bh0, bh1);
                mma_f16(o[nt][0], o[nt][1], o[nt][2], o[nt][3],
                        ah[0], ah[1], ah[2], ah[3], bl0, bl1);
                mma_f16(o[nt][0], o[nt][1], o[nt][2], o[nt][3],
                        al[0], al[1], al[2], al[3], bh0, bh1);
            }
        }
    }

    // epilogue: gate-combine, emit fp16
    const float g = 1.f / (1.f + __expf(-beta[0]));
    const float og = 1.f - g;
    const float li0 = 1.f / l0;
    const float li1 = 1.f / l1;
#pragma unroll
    for (int nt = 0; nt < 16; nt++) {
        const int col = nt * 8 + 2 * lc;
        size_t i0 = (size_t)grow0 * HID + h * HD + col;
        size_t i1 = (size_t)grow1 * HID + h * HD + col;
        float2 mo0 = *(const float2*)(memout + i0);
        float2 mo1 = *(const float2*)(memout + i1);
        *(uint32_t*)(ch + i0) = h2pack(g * mo0.x + og * (o[nt][0] * li0),
                                       g * mo0.y + og * (o[nt][1] * li0));
        *(uint32_t*)(ch + i1) = h2pack(g * mo1.x + og * (o[nt][2] * li1),
                                       g * mo1.y + og * (o[nt][3] * li1));
    }
}

// ---------------- delta-rule partials ----------------
__global__ __launch_bounds__(256) void delta_part_kernel(
    const float* __restrict__ kn, const float* __restrict__ vd, float* __restrict__ part)
{
    const int h = blockIdx.x;
    const int c = blockIdx.y;
    __shared__ float Ak[32][128];
    __shared__ float Bv[32][128];
    const int trow = (threadIdx.x >> 4) * 8;
    const int tcol = (threadIdx.x & 15) * 8;
    float acc[8][8];
#pragma unroll
    for (int i = 0; i < 8; i++)
#pragma unroll
        for (int j = 0; j < 8; j++) acc[i][j] = 0.f;

    const int sbeg = c * 256;
    for (int s0 = sbeg; s0 < sbeg + 256; s0 += 32) {
        for (int i = threadIdx.x; i < 32 * 128; i += 256) {
            int ss = i >> 7, dd = i & 127;
            size_t idx = (size_t)(s0 + ss) * (NKV * HD) + h * HD + dd;
            Ak[ss][dd] = kn[idx];
            Bv[ss][dd] = vd[idx];
        }
        __syncthreads();
#pragma unroll 4
        for (int ss = 0; ss < 32; ss++) {
            float ra[8], rb[8];
#pragma unroll
            for (int i = 0; i < 8; i++) ra[i] = Ak[ss][trow + i];
#pragma unroll
            for (int j = 0; j < 8; j++) rb[j] = Bv[ss][tcol + j];
#pragma unroll
            for (int i = 0; i < 8; i++)
#pragma unroll
                for (int j = 0; j < 8; j++) acc[i][j] += ra[i] * rb[j];
        }
        __syncthreads();
    }
    float* Ph = part + (size_t)c * (NKV * HD * HD) + h * HD * HD;
#pragma unroll
    for (int i = 0; i < 8; i++)
#pragma unroll
        for (int j = 0; j < 8; j++)
            Ph[(trow + i) * HD + tcol + j] = acc[i][j];
}

__global__ __launch_bounds__(256) void delta_final_kernel(
    const float* __restrict__ part, const float* __restrict__ memory, float* __restrict__ outmem)
{
    const int i = blockIdx.x * 256 + threadIdx.x;
    float acc = memory[i];
#pragma unroll
    for (int c = 0; c < 8; c++) acc += part[(size_t)c * (NKV * HD * HD) + i];
    outmem[i] = acc;
}

// ---------------- updated_norm ----------------
__global__ __launch_bounds__(256) void norm_kernel(
    const float* __restrict__ norm_m, const float* __restrict__ knsum, float* __restrict__ out)
{
    const int i = blockIdx.x * 256 + threadIdx.x;
    const int h = i >> 14;
    const int j = i & 127;
    out[i] = norm_m[i] + knsum[h * HD + j];
}

// ---------------- launch ----------------
extern "C" void kernel_launch(void* const* d_in, const int* in_sizes, int n_in,
                              void* d_out, int out_size)
{
    const float* hidden = (const float*)d_in[0];
    const int*   pos    = (const int*)d_in[1];
    const float* wq     = (const float*)d_in[2];
    const float* wk     = (const float*)d_in[3];
    const float* wv     = (const float*)d_in[4];
    const float* wo     = (const float*)d_in[5];
    const float* memory = (const float*)d_in[6];
    const float* norm_m = (const float*)d_in[7];
    const float* beta   = (const float*)d_in[8];
    float* out = (float*)d_out;

    float *qproj, *kproj, *vproj, *qn, *kn, *memout, *vdelta, *knsum, *knpart, *dpart, *nmt;
    __half *hh, *wqT, *wkT, *wvT, *woT, *ch, *qh, *ql, *kh, *kl, *vth, *vtl;
    cudaGetSymbolAddress((void**)&qproj, g_qproj);
    cudaGetSymbolAddress((void**)&kproj, g_kproj);
    cudaGetSymbolAddress((void**)&vproj, g_vproj);
    cudaGetSymbolAddress((void**)&qn, g_qn);
    cudaGetSymbolAddress((void**)&kn, g_kn);
    cudaGetSymbolAddress((void**)&memout, g_memout);
    cudaGetSymbolAddress((void**)&vdelta, g_vdelta);
    cudaGetSymbolAddress((void**)&knsum, g_knsum);
    cudaGetSymbolAddress((void**)&knpart, g_knsum_part);
    cudaGetSymbolAddress((void**)&dpart, g_delta_part);
    cudaGetSymbolAddress((void**)&nmt, g_nmt);
    cudaGetSymbolAddress((void**)&hh, g_hh);
    cudaGetSymbolAddress((void**)&wqT, g_wqT);
    cudaGetSymbolAddress((void**)&wkT, g_wkT);
    cudaGetSymbolAddress((void**)&wvT, g_wvT);
    cudaGetSymbolAddress((void**)&woT, g_woT);
    cudaGetSymbolAddress((void**)&ch, g_ch);
    cudaGetSymbolAddress((void**)&qh, g_qh);
    cudaGetSymbolAddress((void**)&ql, g_ql);
    cudaGetSymbolAddress((void**)&kh, g_kh);
    cudaGetSymbolAddress((void**)&kl, g_kl);
    cudaGetSymbolAddress((void**)&vth, g_vth);
    cudaGetSymbolAddress((void**)&vtl, g_vtl);

    cudaFuncSetAttribute(attn_f16_kernel,
                         cudaFuncAttributeMaxDynamicSharedMemorySize, ATT2_SMEM_BYTES);
    cudaFuncSetAttribute(gemm_f16_kernel,
                         cudaFuncAttributeMaxDynamicSharedMemorySize, GEMM4_SMEM);

    // pre-pass: hidden -> fp16; weights -> transposed [N][K] fp16; norm_m -> nmt
    h2h_kernel<<<1024, 256>>>(hidden, hh, S * HID / 4);
    wtrans_kernel<<<dim3(HID / 32, HID / 32), 256>>>(wq, wqT, HID, HID);
    wtrans_kernel<<<dim3(NKV * HD / 32, HID / 32), 256>>>(wk, wkT, HID, NKV * HD);
    wtrans_kernel<<<dim3(NKV * HD / 32, HID / 32), 256>>>(wv, wvT, HID, NKV * HD);
    wtrans_kernel<<<dim3(HID / 32, HID / 32), 256>>>(wo, woT, HID, HID);
    ntrans_kernel<<<dim3(HD / 32, HD / 32, NKV), 256>>>(norm_m, nmt);

    // projections (fp16 m16n8k16 + ldmatrix, 3 blocks/SM). z=0: Q; z=1: bx<8 K, bx<16 V.
    gemm_f16_kernel<<<dim3(HID / 128, S / 128, 2), 128, GEMM4_SMEM>>>(
        hh, wqT, qproj, HID, wkT, kproj, wvT, vproj, NKV * HD, HID);

    // normalized features from PRE-RoPE q/k
    qn_kernel<<<S, 128>>>(qproj, qn);
    kn_kernel<<<S, 128>>>(kproj, kn);
    knsum_part_kernel<<<dim3(NKV, 16), 128>>>(kn, knpart);
    knsum_final_kernel<<<1, 1024>>>(knpart, knsum);

    // compressive-memory retrieval + delta-rule prep
    retrieve_kernel<<<dim3(S / 16, NH), 128>>>(qn, memory, nmt, memout);
    vdelta_kernel<<<dim3(S / 16, NKV), 128>>>(kn, vproj, memory, nmt, vdelta);

    // RoPE + fp16 hi/lo split; V transpose + split
    rope_split_kernel<<<dim3(S, 10), 256>>>(qproj, kproj, pos, qh, ql, kh, kl);
    vtrans_split_kernel<<<dim3(S / 32, NKV * HD / 32), 256>>>(vproj, vth, vtl);

    // fp16-split flash attention (fuses gated combine, emits fp16 combined)
    attn_f16_kernel<<<dim3(S / 128, NH), 256, ATT2_SMEM_BYTES>>>(
        qh, ql, kh, kl, vth, vtl, memout, beta, ch);

    // output projection (fp16)
    gemm_f16_kernel<<<dim3(HID / 128, S / 128, 1), 128, GEMM4_SMEM>>>(
        ch, woT, out, HID, woT, out, woT, out, HID, HID);

    // memory & norm updates (appended after the 8.4M-element `out`)
    delta_part_kernel<<<dim3(NKV, 8), 256>>>(kn, vdelta, dpart);
    delta_final_kernel<<<(NKV * HD * HD) / 256, 256>>>(dpart, memory, out + (size_t)S * HID);
    norm_kernel<<<(NKV * HD * HD) / 256, 256>>>(norm_m, knsum,
                                                out + (size_t)S * HID + NKV * HD * HD);
}

// round 12
// speedup vs baseline: 1.7248x; 1.7248x over previous
#include <cuda_runtime.h>
#include <cuda_fp16.h>
#include <math.h>
#include <stdint.h>

// ---------------- problem constants ----------------
#define S 2048
#define HID 4096
#define NH 32
#define NKV 8
#define HD 128
#define GROUPS 4
#define EPS 1e-8f
#define ATT_SCALE 0.08838834764831845f   // 128^-0.5
#define LN10000 9.210340371976184f

// ---------------- scratch (device globals; no allocation allowed) ----------------
__device__ float g_qproj[S * HID];
__device__ float g_kproj[S * NKV * HD];
__device__ float g_vproj[S * NKV * HD];
__device__ float g_qn[S * HID];
__device__ float g_kn[S * NKV * HD];
__device__ float g_memout[S * HID];
__device__ float g_vdelta[S * NKV * HD];
__device__ float g_knsum[NKV * HD];
__device__ float g_knsum_part[16][NKV * HD];
__device__ float g_delta_part[8][NKV * HD * HD];
// fp16 GEMM operands
__device__ __half g_hh[S * HID];             // hidden, [M][K]
__device__ __half g_wqT[HID * HID];          // [N][K]
__device__ __half g_wkT[NKV * HD * HID];
__device__ __half g_wvT[NKV * HD * HID];
__device__ __half g_woT[HID * HID];
__device__ __half g_ch[S * HID];             // combined (attention out), [M][K]
// fp16 hi/lo planes for attention
__device__ __half g_qh[S * HID];
__device__ __half g_ql[S * HID];
__device__ __half g_kh[S * NKV * HD];
__device__ __half g_kl[S * NKV * HD];
__device__ __half g_vth[NKV * HD * S];       // V^T hi: [h*HD+d][s]
__device__ __half g_vtl[NKV * HD * S];

// ---------------- fp16 mma + ldmatrix ----------------
__device__ __forceinline__ void mma_f16(
    float& c0, float& c1, float& c2, float& c3,
    uint32_t a0, uint32_t a1, uint32_t a2, uint32_t a3,
    uint32_t b0, uint32_t b1)
{
    asm volatile(
        "mma.sync.aligned.m16n8k16.row.col.f32.f16.f16.f32 "
        "{%0,%1,%2,%3},{%4,%5,%6,%7},{%8,%9},{%0,%1,%2,%3};"
        : "+f"(c0), "+f"(c1), "+f"(c2), "+f"(c3)
        : "r"(a0), "r"(a1), "r"(a2), "r"(a3), "r"(b0), "r"(b1));
}

#define LDSM4(r0, r1, r2, r3, addr) \
    asm volatile("ldmatrix.sync.aligned.m8n8.x4.shared.b16 {%0,%1,%2,%3}, [%4];" \
                 : "=r"(r0), "=r"(r1), "=r"(r2), "=r"(r3) : "r"(addr))

__device__ __forceinline__ uint32_t h2pack(float a, float b) {
    __half2 h = __floats2half2_rn(a, b);
    return *(uint32_t*)&h;
}
__device__ __forceinline__ void h16split(float x, __half& h, __half& l) {
    h = __float2half_rn(x);
    l = __float2half_rn(x - __half2float(h));
}

// ---------------- pre-pass: fp32 -> fp16 ----------------
__global__ __launch_bounds__(256) void h2h_kernel(
    const float* __restrict__ src, __half* __restrict__ dst, int n4)
{
    for (int i = blockIdx.x * 256 + threadIdx.x; i < n4; i += gridDim.x * 256) {
        float4 v = ((const float4*)src)[i];
        uint2 p = make_uint2(h2pack(v.x, v.y), h2pack(v.z, v.w));
        ((uint2*)dst)[i] = p;
    }
}

// transpose: w[K][N] fp32 -> wT[N][K] fp16
__global__ __launch_bounds__(256) void wtrans_kernel(
    const float* __restrict__ w, __half* __restrict__ wt, int Kd, int Nd)
{
    __shared__ float t[32][33];
    const int bx = blockIdx.x;
    const int by = blockIdx.y;
    const int x = threadIdx.x & 31;
    const int y = threadIdx.x >> 5;
#pragma unroll
    for (int j = 0; j < 4; j++) {
        int kr = y + 8 * j;
        t[kr][x] = w[(size_t)(by * 32 + kr) * Nd + bx * 32 + x];
    }
    __syncthreads();
#pragma unroll
    for (int j = 0; j < 4; j++) {
        int nr = y + 8 * j;
        wt[(size_t)(bx * 32 + nr) * Kd + by * 32 + x] = __float2half_rn(t[x][nr]);
    }
}

// ---------------- GEMM: fp16 m16n8k16 + ldmatrix, 4 warps, 64x64 warp tile, BK=32, 4-stage ----------------
#define HAS_STR 40
#define HBS_STR 40
#define STG4_BYTES ((128 * HAS_STR + 128 * HBS_STR) * 2)   // 20480
#define GEMM4_SMEM (4 * STG4_BYTES)                        // 81920

#define CP16(dst_u32, src_ptr) \
    asm volatile("cp.async.cg.shared.global [%0], [%1], 16;" :: "r"(dst_u32), "l"(src_ptr))

__global__ __launch_bounds__(128, 2) void gemm_f16_kernel(
    const __half* __restrict__ A,
    const __half* __restrict__ B0, float* __restrict__ C0, int N0,
    const __half* __restrict__ B1, float* __restrict__ C1,
    const __half* __restrict__ B2, float* __restrict__ C2, int N12,
    int K)
{
    const __half* Bt;
    float* C;
    int N, bx;
    if (blockIdx.z == 0) {
        Bt = B0; C = C0; N = N0; bx = blockIdx.x;
        if (bx * 128 >= N0) return;
    } else {
        N = N12;
        const int nt12 = N12 / 128;
        if ((int)blockIdx.x < nt12) { Bt = B1; C = C1; bx = blockIdx.x; }
        else if ((int)blockIdx.x < 2 * nt12) { Bt = B2; C = C2; bx = blockIdx.x - nt12; }
        else return;
    }

    extern __shared__ __half smh[];
    const uint32_t smu = (uint32_t)__cvta_generic_to_shared(smh);

    const int tid = threadIdx.x;
    const int lane = tid & 31;
    const int wid = tid >> 5;
    const int wm = wid >> 1;
    const int wn = wid & 1;
    const int lr = lane >> 2;
    const int lc = lane & 3;
    const int by = blockIdx.y;

    const int crow = tid >> 2;
    const int cchk = (tid & 3) * 8;

    const __half* Ab = A + (size_t)(by * 128) * K;
    const __half* Bb = Bt + (size_t)(bx * 128) * K;

    const uint32_t a_lane_off =
        (uint32_t)(((lane & 15) * HAS_STR + ((lane >> 4) << 3)) * 2);
    const uint32_t b_lane_off =
        (uint32_t)((((lane & 7) + ((lane >> 4) << 3)) * HBS_STR + (((lane >> 3) & 1) << 3)) * 2);

    float acc[4][8][4];
#pragma unroll
    for (int i = 0; i < 4; i++)
#pragma unroll
        for (int j = 0; j < 8; j++)
#pragma unroll
            for (int r = 0; r < 4; r++) acc[i][j][r] = 0.f;

    const int NT = K / 32;

#define LOAD_STAGE(stg, ch)                                                           \
    {                                                                                 \
        const uint32_t sb = smu + (uint32_t)((stg) * STG4_BYTES);                     \
        const int k0 = (ch) * 32;                                                     \
        _Pragma("unroll")                                                             \
        for (int i = 0; i < 4; i++) {                                                 \
            const int r = i * 32 + crow;                                              \
            CP16(sb + (uint32_t)((r * HAS_STR + cchk) * 2), Ab + (size_t)r * K + k0 + cchk); \
        }                                                                             \
        _Pragma("unroll")                                                             \
        for (int i = 0; i < 4; i++) {                                                 \
            const int r = i * 32 + crow;                                              \
            CP16(sb + (uint32_t)((128 * HAS_STR + r * HBS_STR + cchk) * 2),           \
                 Bb + (size_t)r * K + k0 + cchk);                                     \
        }                                                                             \
    }

    LOAD_STAGE(0, 0)
    asm volatile("cp.async.commit_group;" ::: "memory");
    LOAD_STAGE(1, 1)
    asm volatile("cp.async.commit_group;" ::: "memory");
    LOAD_STAGE(2, 2)
    asm volatile("cp.async.commit_group;" ::: "memory");

    int stage = 0;
    for (int it = 0; it < NT; it++) {
        asm volatile("cp.async.wait_group 2;" ::: "memory");
        __syncthreads();

        const int pf = it + 3;
        if (pf < NT) {
            const int ps = (stage + 3) & 3;
            LOAD_STAGE(ps, pf)
        }
        asm volatile("cp.async.commit_group;" ::: "memory");

        const uint32_t sbA = smu + (uint32_t)(stage * STG4_BYTES);
        const uint32_t sbB = sbA + (uint32_t)(128 * HAS_STR * 2);

#pragma unroll
        for (int ks = 0; ks < 2; ks++) {
            const uint32_t kbB = (uint32_t)(ks * 16 * 2);
            uint32_t af[4][4], bf[8][2];
#pragma unroll
            for (int mt = 0; mt < 4; mt++) {
                const uint32_t addr = sbA
                    + (uint32_t)(((wm * 64 + mt * 16) * HAS_STR) * 2)
                    + a_lane_off + kbB;
                LDSM4(af[mt][0], af[mt][1], af[mt][2], af[mt][3], addr);
            }
#pragma unroll
            for (int ntp = 0; ntp < 4; ntp++) {
                const uint32_t addr = sbB
                    + (uint32_t)(((wn * 64 + ntp * 16) * HBS_STR) * 2)
                    + b_lane_off + kbB;
                LDSM4(bf[2 * ntp][0], bf[2 * ntp][1], bf[2 * ntp + 1][0], bf[2 * ntp + 1][1], addr);
            }
#pragma unroll
            for (int mt = 0; mt < 4; mt++)
#pragma unroll
                for (int nt = 0; nt < 8; nt++)
                    mma_f16(acc[mt][nt][0], acc[mt][nt][1], acc[mt][nt][2], acc[mt][nt][3],
                            af[mt][0], af[mt][1], af[mt][2], af[mt][3],
                            bf[nt][0], bf[nt][1]);
        }
        stage = (stage + 1) & 3;
    }
#undef LOAD_STAGE

#pragma unroll
    for (int mt = 0; mt < 4; mt++) {
        const int row = by * 128 + wm * 64 + mt * 16 + lr;
#pragma unroll
        for (int nt = 0; nt < 8; nt++) {
            const int col = bx * 128 + wn * 64 + nt * 8 + lc * 2;
            float2 v01 = make_float2(acc[mt][nt][0], acc[mt][nt][1]);
            float2 v23 = make_float2(acc[mt][nt][2], acc[mt][nt][3]);
            *(float2*)(C + (size_t)row * N + col) = v01;
            *(float2*)(C + (size_t)(row + 8) * N + col) = v23;
        }
    }
}

// ---------------- qn / kn ----------------
__global__ __launch_bounds__(128) void qn_kernel(const float* __restrict__ qp, float* __restrict__ qn)
{
    const int s = blockIdx.x;
    const int d = threadIdx.x;
    __shared__ float wsum[4];
    for (int h = 0; h < NH; h++) {
        float x = qp[(size_t)s * HID + h * HD + d];
        float f = x > 0.f ? x + 1.f : expf(x);
        float v = f;
#pragma unroll
        for (int o = 16; o; o >>= 1) v += __shfl_xor_sync(0xffffffffu, v, o);
        if ((d & 31) == 0) wsum[d >> 5] = v;
        __syncthreads();
        float tot = wsum[0] + wsum[1] + wsum[2] + wsum[3];
        qn[(size_t)s * HID + h * HD + d] = f / (tot + EPS);
        __syncthreads();
    }
}

__global__ __launch_bounds__(128) void kn_kernel(const float* __restrict__ kp, float* __restrict__ kn)
{
    const int s = blockIdx.x;
    const int d = threadIdx.x;
    __shared__ float wsum[4];
    for (int h = 0; h < NKV; h++) {
        float x = kp[(size_t)s * (NKV * HD) + h * HD + d];
        float f = x > 0.f ? x + 1.f : expf(x);
        float v = f;
#pragma unroll
        for (int o = 16; o; o >>= 1) v += __shfl_xor_sync(0xffffffffu, v, o);
        if ((d & 31) == 0) wsum[d >> 5] = v;
        __syncthreads();
        float tot = wsum[0] + wsum[1] + wsum[2] + wsum[3];
        kn[(size_t)s * (NKV * HD) + h * HD + d] = f / (tot + EPS);
        __syncthreads();
    }
}

__global__ __launch_bounds__(128) void knsum_part_kernel(const float* __restrict__ kn, float* __restrict__ part)
{
    const int h = blockIdx.x;
    const int p = blockIdx.y;
    const int d = threadIdx.x;
    float acc = 0.f;
    const int s0 = p * 128;
#pragma unroll 4
    for (int s = s0; s < s0 + 128; s++)
        acc += kn[(size_t)s * (NKV * HD) + h * HD + d];
    part[p * (NKV * HD) + h * HD + d] = acc;
}

__global__ __launch_bounds__(1024) void knsum_final_kernel(const float* __restrict__ part, float* __restrict__ knsum)
{
    const int i = threadIdx.x;
    float acc = 0.f;
#pragma unroll
    for (int p = 0; p < 16; p++) acc += part[p * (NKV * HD) + i];
    knsum[i] = acc;
}

// ---------------- memory retrieval ----------------
__global__ __launch_bounds__(128) void retrieve_kernel(
    const float* __restrict__ qn, const float* __restrict__ memory,
    const float* __restrict__ norm_m, float* __restrict__ memout)
{
    const int h = blockIdx.y;
    const int st = blockIdx.x;
    const int hm = h & (NKV - 1);
    const int e = threadIdx.x;
    __shared__ float Qs[16][128];
    __shared__ float Ms[32][128];
    __shared__ float Ns[128][33];

    for (int i = e; i < 16 * 128; i += 128) {
        int r = i >> 7, d = i & 127;
        Qs[r][d] = qn[(size_t)(st * 16 + r) * HID + h * HD + d];
    }
    float num[16], den[16];
#pragma unroll
    for (int r = 0; r < 16; r++) { num[r] = 0.f; den[r] = 0.f; }
    const float* M = memory + hm * HD * HD;
    const float* Nm = norm_m + hm * HD * HD;

    for (int d0 = 0; d0 < 128; d0 += 32) {
        __syncthreads();
        for (int i = e; i < 32 * 128; i += 128) {
            int dd = i >> 7, ee = i & 127;
            Ms[dd][ee] = M[(d0 + dd) * HD + ee];
        }
        for (int i = e; i < 128 * 32; i += 128) {
            int ee = i >> 5, dd = i & 31;
            Ns[ee][dd] = Nm[ee * HD + d0 + dd];
        }
        __syncthreads();
#pragma unroll 4
        for (int dd = 0; dd < 32; dd++) {
            float mv = Ms[dd][e];
            float nv = Ns[e][dd];
#pragma unroll
            for (int r = 0; r < 16; r++) {
                float qv = Qs[r][d0 + dd];
                num[r] += qv * mv;
                den[r] += qv * nv;
            }
        }
    }
#pragma unroll
    for (int r = 0; r < 16; r++)
        memout[(size_t)(st * 16 + r) * HID + h * HD + e] = num[r] / (den[r] + EPS);
}

// ---------------- v - v_ret for delta rule ----------------
__global__ __launch_bounds__(128) void vdelta_kernel(
    const float* __restrict__ kn, const float* __restrict__ vproj,
    const float* __restrict__ memory, const float* __restrict__ norm_m,
    float* __restrict__ vdelta)
{
    const int h = blockIdx.y;
    const int st = blockIdx.x;
    const int e = threadIdx.x;
    __shared__ float Qs[16][128];
    __shared__ float Ms[32][128];
    __shared__ float Ns[128][33];

    for (int i = e; i < 16 * 128; i += 128) {
        int r = i >> 7, d = i & 127;
        Qs[r][d] = kn[(size_t)(st * 16 + r) * (NKV * HD) + h * HD + d];
    }
    float num[16], den[16];
#pragma unroll
    for (int r = 0; r < 16; r++) { num[r] = 0.f; den[r] = 0.f; }
    const float* M = memory + h * HD * HD;
    const float* Nm = norm_m + h * HD * HD;

    for (int d0 = 0; d0 < 128; d0 += 32) {
        __syncthreads();
        for (int i = e; i < 32 * 128; i += 128) {
            int dd = i >> 7, ee = i & 127;
            Ms[dd][ee] = M[(d0 + dd) * HD + ee];
        }
        for (int i = e; i < 128 * 32; i += 128) {
            int ee = i >> 5, dd = i & 31;
            Ns[ee][dd] = Nm[ee * HD + d0 + dd];
        }
        __syncthreads();
#pragma unroll 4
        for (int dd = 0; dd < 32; dd++) {
            float mv = Ms[dd][e];
            float nv = Ns[e][dd];
#pragma unroll
            for (int r = 0; r < 16; r++) {
                float qv = Qs[r][d0 + dd];
                num[r] += qv * mv;
                den[r] += qv * nv;
            }
        }
    }
#pragma unroll
    for (int r = 0; r < 16; r++) {
        size_t idx = (size_t)(st * 16 + r) * (NKV * HD) + h * HD + e;
        vdelta[idx] = vproj[idx] - num[r] / (den[r] + EPS);
    }
}

// ---------------- RoPE + fp16 hi/lo split for Q,K ----------------
__global__ __launch_bounds__(256) void rope_split_kernel(
    const float* __restrict__ q, const float* __restrict__ k, const int* __restrict__ pos,
    __half* __restrict__ qh, __half* __restrict__ ql,
    __half* __restrict__ kh, __half* __restrict__ kl)
{
    const int s = blockIdx.x;
    const int idx = blockIdx.y * 256 + threadIdx.x;
    if (idx >= (NH + NKV) * 64) return;
    const int head = idx >> 6;
    const int d = idx & 63;
    const float p = (float)pos[s];
    const float invf = expf(-(2.0f * (float)d / 128.0f) * LN10000);
    const float a = p * invf;
    const float c = cosf(a), sn = sinf(a);
    const float* base;
    __half *oh, *ol;
    if (head < NH) {
        size_t off = (size_t)s * HID + head * HD;
        base = q + off; oh = qh + off; ol = ql + off;
    } else {
        size_t off = (size_t)s * (NKV * HD) + (head - NH) * HD;
        base = k + off; oh = kh + off; ol = kl + off;
    }
    float x0 = base[d], x1 = base[d + 64];
    float r0 = x0 * c - x1 * sn;
    float r1 = x1 * c + x0 * sn;
    __half h, l;
    h16split(r0, h, l);
    oh[d] = h; ol[d] = l;
    h16split(r1, h, l);
    oh[d + 64] = h; ol[d + 64] = l;
}

// ---------------- V transpose + split ----------------
__global__ __launch_bounds__(256) void vtrans_split_kernel(
    const float* __restrict__ v, __half* __restrict__ vth, __half* __restrict__ vtl)
{
    __shared__ float t[32][33];
    const int bx = blockIdx.x;
    const int by = blockIdx.y;
    const int x = threadIdx.x & 31;
    const int y = threadIdx.x >> 5;
#pragma unroll
    for (int j = 0; j < 4; j++) {
        int sr = y + 8 * j;
        t[sr][x] = v[(size_t)(bx * 32 + sr) * (NKV * HD) + by * 32 + x];
    }
    __syncthreads();
#pragma unroll
    for (int j = 0; j < 4; j++) {
        int cr = y + 8 * j;
        float val = t[x][cr];
        __half h, l;
        h16split(val, h, l);
        size_t idx = (size_t)(by * 32 + cr) * S + bx * 32 + x;
        vth[idx] = h;
        vtl[idx] = l;
    }
}

// ---------------- fp16-split MMA flash attention ----------------
#define QH_STR 136
#define KH_STR 136
#define VT_STR 72
#define PH_STR 72
#define SM_QH 0
#define SM_QL (128 * QH_STR)
#define SM_KH (SM_QL + 128 * QH_STR)
#define SM_KL (SM_KH + 64 * KH_STR)
#define SM_VTH (SM_KL + 64 * KH_STR)
#define SM_VTL (SM_VTH + 128 * VT_STR)
#define SM_PH (SM_VTL + 128 * VT_STR)
#define SM_PL (SM_PH + 128 * PH_STR)
#define ATT2_SMEM_HALVES (SM_PL + 128 * PH_STR)
#define ATT2_SMEM_BYTES (ATT2_SMEM_HALVES * 2)

__global__ __launch_bounds__(256) void attn_f16_kernel(
    const __half* __restrict__ qh, const __half* __restrict__ ql,
    const __half* __restrict__ kh, const __half* __restrict__ kl,
    const __half* __restrict__ vth, const __half* __restrict__ vtl,
    const float* __restrict__ memout, const float* __restrict__ beta,
    __half* __restrict__ ch)
{
    const int h = blockIdx.y;
    const int qt = (int)gridDim.x - 1 - (int)blockIdx.x;
    const int kvh = h >> 2;
    const int tid = threadIdx.x;
    const int warp = tid >> 5;
    const int lane = tid & 31;
    const int lr = lane >> 2;
    const int lc = lane & 3;

    extern __shared__ __half sh[];
    __half* Qh_ = sh + SM_QH;
    __half* Ql_ = sh + SM_QL;
    __half* Kh_ = sh + SM_KH;
    __half* Kl_ = sh + SM_KL;
    __half* Vth_ = sh + SM_VTH;
    __half* Vtl_ = sh + SM_VTL;
    __half* Ph_ = sh + SM_PH;
    __half* Pl_ = sh + SM_PL;

#pragma unroll
    for (int it = 0; it < 8; it++) {
        int i = it * 256 + tid;
        int row = i >> 4, c8 = (i & 15) * 8;
        size_t gidx = (size_t)(qt * 128 + row) * HID + h * HD + c8;
        *(uint4*)(Qh_ + row * QH_STR + c8) = *(const uint4*)(qh + gidx);
        *(uint4*)(Ql_ + row * QH_STR + c8) = *(const uint4*)(ql + gidx);
    }

    const int row0 = warp * 16 + lr;
    const int row1 = row0 + 8;
    const int grow0 = qt * 128 + row0;
    const int grow1 = grow0 + 8;

    float m0 = -1e30f, m1 = -1e30f, l0 = 0.f, l1 = 0.f;
    float o[16][4];
#pragma unroll
    for (int nt = 0; nt < 16; nt++)
#pragma unroll
        for (int r = 0; r < 4; r++) o[nt][r] = 0.f;

    const int ktmax = 2 * qt + 1;
    for (int kt = 0; kt <= ktmax; kt++) {
        __syncthreads();
#pragma unroll
        for (int it = 0; it < 4; it++) {
            int i = it * 256 + tid;
            int key = i >> 4, c8 = (i & 15) * 8;
            size_t gidx = (size_t)(kt * 64 + key) * (NKV * HD) + kvh * HD + c8;
            *(uint4*)(Kh_ + key * KH_STR + c8) = *(const uint4*)(kh + gidx);
            *(uint4*)(Kl_ + key * KH_STR + c8) = *(const uint4*)(kl + gidx);
        }
#pragma unroll
        for (int it = 0; it < 4; it++) {
            int i = it * 256 + tid;
            int dr = i >> 3, kc = (i & 7) * 8;
            size_t gidx = (size_t)(kvh * HD + dr) * S + kt * 64 + kc;
            *(uint4*)(Vth_ + dr * VT_STR + kc) = *(const uint4*)(vth + gidx);
            *(uint4*)(Vtl_ + dr * VT_STR + kc) = *(const uint4*)(vtl + gidx);
        }
        __syncthreads();

        float sc[8][4];
#pragma unroll
        for (int nt = 0; nt < 8; nt++)
#pragma unroll
            for (int r = 0; r < 4; r++) sc[nt][r] = 0.f;

#pragma unroll
        for (int ks = 0; ks < 8; ks++) {
            const int kb = ks * 16;
            uint32_t ah[4], al[4];
            {
                const __half* p0 = Qh_ + row0 * QH_STR + kb + 2 * lc;
                const __half* p1 = Qh_ + row1 * QH_STR + kb + 2 * lc;
                ah[0] = *(const uint32_t*)(p0);
                ah[1] = *(const uint32_t*)(p1);
                ah[2] = *(const uint32_t*)(p0 + 8);
                ah[3] = *(const uint32_t*)(p1 + 8);
                const __half* q0 = Ql_ + row0 * QH_STR + kb + 2 * lc;
                const __half* q1 = Ql_ + row1 * QH_STR + kb + 2 * lc;
                al[0] = *(const uint32_t*)(q0);
                al[1] = *(const uint32_t*)(q1);
                al[2] = *(const uint32_t*)(q0 + 8);
                al[3] = *(const uint32_t*)(q1 + 8);
            }
#pragma unroll
            for (int nt = 0; nt < 8; nt++) {
                const int n0 = nt * 8 + lr;
                const __half* ph = Kh_ + n0 * KH_STR + kb + 2 * lc;
                const __half* pl = Kl_ + n0 * KH_STR + kb + 2 * lc;
                uint32_t bh0 = *(const uint32_t*)(ph);
                uint32_t bh1 = *(const uint32_t*)(ph + 8);
                uint32_t bl0 = *(const uint32_t*)(pl);
                uint32_t bl1 = *(const uint32_t*)(pl + 8);
                mma_f16(sc[nt][0], sc[nt][1], sc[nt][2], sc[nt][3],
                        ah[0], ah[1], ah[2], ah[3], bh0, bh1);
                mma_f16(sc[nt][0], sc[nt][1], sc[nt][2], sc[nt][3],
                        ah[0], ah[1], ah[2], ah[3], bl0, bl1);
                mma_f16(sc[nt][0], sc[nt][1], sc[nt][2], sc[nt][3],
                        al[0], al[1], al[2], al[3], bh0, bh1);
            }
        }

        const bool need_mask = (kt >= 2 * qt);
        float mx0 = -1e30f, mx1 = -1e30f;
#pragma unroll
        for (int nt = 0; nt < 8; nt++) {
#pragma unroll
            for (int j = 0; j < 2; j++) {
                int col = kt * 64 + nt * 8 + 2 * lc + j;
                float s0 = sc[nt][j] * ATT_SCALE;
                float s1 = sc[nt][2 + j] * ATT_SCALE;
                if (need_mask) {
                    if (col > grow0) s0 = -1e30f;
                    if (col > grow1) s1 = -1e30f;
                }
                sc[nt][j] = s0;
                sc[nt][2 + j] = s1;
                mx0 = fmaxf(mx0, s0);
                mx1 = fmaxf(mx1, s1);
            }
        }
        mx0 = fmaxf(mx0, __shfl_xor_sync(0xffffffffu, mx0, 1));
        mx0 = fmaxf(mx0, __shfl_xor_sync(0xffffffffu, mx0, 2));
        mx1 = fmaxf(mx1, __shfl_xor_sync(0xffffffffu, mx1, 1));
        mx1 = fmaxf(mx1, __shfl_xor_sync(0xffffffffu, mx1, 2));
        const float mn0 = fmaxf(m0, mx0);
        const float mn1 = fmaxf(m1, mx1);
        const float scl0 = __expf(m0 - mn0);
        const float scl1 = __expf(m1 - mn1);
        float ls0 = 0.f, ls1 = 0.f;
#pragma unroll
        for (int nt = 0; nt < 8; nt++) {
            float p00 = __expf(sc[nt][0] - mn0);
            float p01 = __expf(sc[nt][1] - mn0);
            float p10 = __expf(sc[nt][2] - mn1);
            float p11 = __expf(sc[nt][3] - mn1);
            ls0 += p00 + p01;
            ls1 += p10 + p11;
            __half h0, l0h, h1, l1h;
            h16split(p00, h0, l0h);
            h16split(p01, h1, l1h);
            *(uint32_t*)(Ph_ + row0 * PH_STR + nt * 8 + 2 * lc) =
                (uint32_t)__half_as_ushort(h0) | ((uint32_t)__half_as_ushort(h1) << 16);
            *(uint32_t*)(Pl_ + row0 * PH_STR + nt * 8 + 2 * lc) =
                (uint32_t)__half_as_ushort(l0h) | ((uint32_t)__half_as_ushort(l1h) << 16);
            h16split(p10, h0, l0h);
            h16split(p11, h1, l1h);
            *(uint32_t*)(Ph_ + row1 * PH_STR + nt * 8 + 2 * lc) =
                (uint32_t)__half_as_ushort(h0) | ((uint32_t)__half_as_ushort(h1) << 16);
            *(uint32_t*)(Pl_ + row1 * PH_STR + nt * 8 + 2 * lc) =
                (uint32_t)__half_as_ushort(l0h) | ((uint32_t)__half_as_ushort(l1h) << 16);
        }
        ls0 += __shfl_xor_sync(0xffffffffu, ls0, 1);
        ls0 += __shfl_xor_sync(0xffffffffu, ls0, 2);
        ls1 += __shfl_xor_sync(0xffffffffu, ls1, 1);
        ls1 += __shfl_xor_sync(0xffffffffu, ls1, 2);
        l0 = l0 * scl0 + ls0;
        l1 = l1 * scl1 + ls1;
        m0 = mn0;
        m1 = mn1;

#pragma unroll
        for (int nt = 0; nt < 16; nt++) {
            o[nt][0] *= scl0;
            o[nt][1] *= scl0;
            o[nt][2] *= scl1;
            o[nt][3] *= scl1;
        }
        __syncwarp();

#pragma unroll
        for (int ks2 = 0; ks2 < 4; ks2++) {
            const int kb = ks2 * 16;
            uint32_t ah[4], al[4];
            {
                const __half* p0 = Ph_ + row0 * PH_STR + kb + 2 * lc;
                const __half* p1 = Ph_ + row1 * PH_STR + kb + 2 * lc;
                ah[0] = *(const uint32_t*)(p0);
                ah[1] = *(const uint32_t*)(p1);
                ah[2] = *(const uint32_t*)(p0 + 8);
                ah[3] = *(const uint32_t*)(p1 + 8);
                const __half* q0 = Pl_ + row0 * PH_STR + kb + 2 * lc;
                const __half* q1 = Pl_ + row1 * PH_STR + kb + 2 * lc;
                al[0] = *(const uint32_t*)(q0);
                al[1] = *(const uint32_t*)(q1);
                al[2] = *(const uint32_t*)(q0 + 8);
                al[3] = *(const uint32_t*)(q1 + 8);
            }
#pragma unroll
            for (int nt = 0; nt < 16; nt++) {
                const int n0 = nt * 8 + lr;
                const __half* ph = Vth_ + n0 * VT_STR + kb + 2 * lc;
                const __half* pl = Vtl_ + n0 * VT_STR + kb + 2 * lc;
                uint32_t bh0 = *(const uint32_t*)(ph);
                uint32_t bh1 = *(const uint32_t*)(ph + 8);
                uint32_t bl0 = *(const uint32_t*)(pl);
                uint32_t bl1 = *(const uint32_t*)(pl + 8);
                mma_f16(o[nt][0], o[nt][1], o[nt][2], o[nt][3],
                        ah[0], ah[1], ah[2], ah[3], bh0, bh1);
                mma_f16(o[nt][0], o[nt][1], o[nt][2], o[nt][3],
                        ah[0], ah[1], ah[2], ah[3], bl0, bl1);
                mma_f16(o[nt][0], o[nt][1], o[nt][2], o[nt][3],
                        al[0], al[1], al[2], al[3], bh0, bh1);
            }
        }
    }

    // epilogue: gate-combine, emit fp16
    const float g = 1.f / (1.f + __expf(-beta[0]));
    const float og = 1.f - g;
    const float li0 = 1.f / l0;
    const float li1 = 1.f / l1;
#pragma unroll
    for (int nt = 0; nt < 16; nt++) {
        const int col = nt * 8 + 2 * lc;
        size_t i0 = (size_t)grow0 * HID + h * HD + col;
        size_t i1 = (size_t)grow1 * HID + h * HD + col;
        float2 mo0 = *(const float2*)(memout + i0);
        float2 mo1 = *(const float2*)(memout + i1);
        *(uint32_t*)(ch + i0) = h2pack(g * mo0.x + og * (o[nt][0] * li0),
                                       g * mo0.y + og * (o[nt][1] * li0));
        *(uint32_t*)(ch + i1) = h2pack(g * mo1.x + og * (o[nt][2] * li1),
                                       g * mo1.y + og * (o[nt][3] * li1));
    }
}

// ---------------- delta-rule partials ----------------
__global__ __launch_bounds__(256) void delta_part_kernel(
    const float* __restrict__ kn, const float* __restrict__ vd, float* __restrict__ part)
{
    const int h = blockIdx.x;
    const int c = blockIdx.y;
    __shared__ float Ak[32][128];
    __shared__ float Bv[32][128];
    const int trow = (threadIdx.x >> 4) * 8;
    const int tcol = (threadIdx.x & 15) * 8;
    float acc[8][8];
#pragma unroll
    for (int i = 0; i < 8; i++)
#pragma unroll
        for (int j = 0; j < 8; j++) acc[i][j] = 0.f;

    const int sbeg = c * 256;
    for (int s0 = sbeg; s0 < sbeg + 256; s0 += 32) {
        for (int i = threadIdx.x; i < 32 * 128; i += 256) {
            int ss = i >> 7, dd = i & 127;
            size_t idx = (size_t)(s0 + ss) * (NKV * HD) + h * HD + dd;
            Ak[ss][dd] = kn[idx];
            Bv[ss][dd] = vd[idx];
        }
        __syncthreads();
#pragma unroll 4
        for (int ss = 0; ss < 32; ss++) {
            float ra[8], rb[8];
#pragma unroll
            for (int i = 0; i < 8; i++) ra[i] = Ak[ss][trow + i];
#pragma unroll
            for (int j = 0; j < 8; j++) rb[j] = Bv[ss][tcol + j];
#pragma unroll
            for (int i = 0; i < 8; i++)
#pragma unroll
                for (int j = 0; j < 8; j++) acc[i][j] += ra[i] * rb[j];
        }
        __syncthreads();
    }
    float* Ph = part + (size_t)c * (NKV * HD * HD) + h * HD * HD;
#pragma unroll
    for (int i = 0; i < 8; i++)
#pragma unroll
        for (int j = 0; j < 8; j++)
            Ph[(trow + i) * HD + tcol + j] = acc[i][j];
}

__global__ __launch_bounds__(256) void delta_final_kernel(
    const float* __restrict__ part, const float* __restrict__ memory, float* __restrict__ outmem)
{
    const int i = blockIdx.x * 256 + threadIdx.x;
    float acc = memory[i];
#pragma unroll
    for (int c = 0; c < 8; c++) acc += part[(size_t)c * (NKV * HD * HD) + i];
    outmem[i] = acc;
}

// ---------------- updated_norm ----------------
__global__ __launch_bounds__(256) void norm_kernel(
    const float* __restrict__ norm_m, const float* __restrict__ knsum, float* __restrict__ out)
{
    const int i = blockIdx.x * 256 + threadIdx.x;
    const int h = i >> 14;
    const int j = i & 127;
    out[i] = norm_m[i] + knsum[h * HD + j];
}

// ---------------- launch ----------------
extern "C" void kernel_launch(void* const* d_in, const int* in_sizes, int n_in,
                              void* d_out, int out_size)
{
    const float* hidden = (const float*)d_in[0];
    const int*   pos    = (const int*)d_in[1];
    const float* wq     = (const float*)d_in[2];
    const float* wk     = (const float*)d_in[3];
    const float* wv     = (const float*)d_in[4];
    const float* wo     = (const float*)d_in[5];
    const float* memory = (const float*)d_in[6];
    const float* norm_m = (const float*)d_in[7];
    const float* beta   = (const float*)d_in[8];
    float* out = (float*)d_out;

    float *qproj, *kproj, *vproj, *qn, *kn, *memout, *vdelta, *knsum, *knpart, *dpart;
    __half *hh, *wqT, *wkT, *wvT, *woT, *ch, *qh, *ql, *kh, *kl, *vth, *vtl;
    cudaGetSymbolAddress((void**)&qproj, g_qproj);
    cudaGetSymbolAddress((void**)&kproj, g_kproj);
    cudaGetSymbolAddress((void**)&vproj, g_vproj);
    cudaGetSymbolAddress((void**)&qn, g_qn);
    cudaGetSymbolAddress((void**)&kn, g_kn);
    cudaGetSymbolAddress((void**)&memout, g_memout);
    cudaGetSymbolAddress((void**)&vdelta, g_vdelta);
    cudaGetSymbolAddress((void**)&knsum, g_knsum);
    cudaGetSymbolAddress((void**)&knpart, g_knsum_part);
    cudaGetSymbolAddress((void**)&dpart, g_delta_part);
    cudaGetSymbolAddress((void**)&hh, g_hh);
    cudaGetSymbolAddress((void**)&wqT, g_wqT);
    cudaGetSymbolAddress((void**)&wkT, g_wkT);
    cudaGetSymbolAddress((void**)&wvT, g_wvT);
    cudaGetSymbolAddress((void**)&woT, g_woT);
    cudaGetSymbolAddress((void**)&ch, g_ch);
    cudaGetSymbolAddress((void**)&qh, g_qh);
    cudaGetSymbolAddress((void**)&ql, g_ql);
    cudaGetSymbolAddress((void**)&kh, g_kh);
    cudaGetSymbolAddress((void**)&kl, g_kl);
    cudaGetSymbolAddress((void**)&vth, g_vth);
    cudaGetSymbolAddress((void**)&vtl, g_vtl);

    cudaFuncSetAttribute(attn_f16_kernel,
                         cudaFuncAttributeMaxDynamicSharedMemorySize, ATT2_SMEM_BYTES);
    cudaFuncSetAttribute(gemm_f16_kernel,
                         cudaFuncAttributeMaxDynamicSharedMemorySize, GEMM4_SMEM);

    // pre-pass: hidden -> fp16; weights -> transposed [N][K] fp16
    h2h_kernel<<<1024, 256>>>(hidden, hh, S * HID / 4);
    wtrans_kernel<<<dim3(HID / 32, HID / 32), 256>>>(wq, wqT, HID, HID);
    wtrans_kernel<<<dim3(NKV * HD / 32, HID / 32), 256>>>(wk, wkT, HID, NKV * HD);
    wtrans_kernel<<<dim3(NKV * HD / 32, HID / 32), 256>>>(wv, wvT, HID, NKV * HD);
    wtrans_kernel<<<dim3(HID / 32, HID / 32), 256>>>(wo, woT, HID, HID);

    // projections (fp16 m16n8k16 + ldmatrix, 4-stage pipeline). z=0: Q; z=1: bx<8 K, bx<16 V.
    gemm_f16_kernel<<<dim3(HID / 128, S / 128, 2), 128, GEMM4_SMEM>>>(
        hh, wqT, qproj, HID, wkT, kproj, wvT, vproj, NKV * HD, HID);

    // normalized features from PRE-RoPE q/k
    qn_kernel<<<S, 128>>>(qproj, qn);
    kn_kernel<<<S, 128>>>(kproj, kn);
    knsum_part_kernel<<<dim3(NKV, 16), 128>>>(kn, knpart);
    knsum_final_kernel<<<1, 1024>>>(knpart, knsum);

    // compressive-memory retrieval + delta-rule prep
    retrieve_kernel<<<dim3(S / 16, NH), 128>>>(qn, memory, norm_m, memout);
    vdelta_kernel<<<dim3(S / 16, NKV), 128>>>(kn, vproj, memory, norm_m, vdelta);

    // RoPE + fp16 hi/lo split; V transpose + split
    rope_split_kernel<<<dim3(S, 10), 256>>>(qproj, kproj, pos, qh, ql, kh, kl);
    vtrans_split_kernel<<<dim3(S / 32, NKV * HD / 32), 256>>>(vproj, vth, vtl);

    // fp16-split flash attention (fuses gated combine, emits fp16 combined)
    attn_f16_kernel<<<dim3(S / 128, NH), 256, ATT2_SMEM_BYTES>>>(
        qh, ql, kh, kl, vth, vtl, memout, beta, ch);

    // output projection (fp16)
    gemm_f16_kernel<<<dim3(HID / 128, S / 128, 1), 128, GEMM4_SMEM>>>(
        ch, woT, out, HID, woT, out, woT, out, HID, HID);

    // memory & norm updates (appended after the 8.4M-element `out`)
    delta_part_kernel<<<dim3(NKV, 8), 256>>>(kn, vdelta, dpart);
    delta_final_kernel<<<(NKV * HD * HD) / 256, 256>>>(dpart, memory, out + (size_t)S * HID);
    norm_kernel<<<(NKV * HD * HD) / 256, 256>>>(norm_m, knsum,
                                                out + (size_t)S * HID + NKV * HD * HD);
}

// round 14
// speedup vs baseline: 1.7644x; 1.0230x over previous
#include <cuda_runtime.h>
#include <cuda_fp16.h>
#include <math.h>
#include <stdint.h>

// ---------------- problem constants ----------------
#define S 2048
#define HID 4096
#define NH 32
#define NKV 8
#define HD 128
#define GROUPS 4
#define EPS 1e-8f
#define ATT_SCALE 0.08838834764831845f   // 128^-0.5
#define LN10000 9.210340371976184f

// ---------------- scratch (device globals; no allocation allowed) ----------------
__device__ float g_qproj[S * HID];
__device__ float g_kproj[S * NKV * HD];
__device__ float g_vproj[S * NKV * HD];
__device__ float g_qn[S * HID];
__device__ float g_kn[S * NKV * HD];
__device__ float g_memout[S * HID];
__device__ float g_vdelta[S * NKV * HD];
__device__ float g_knsum[NKV * HD];
__device__ float g_knsum_part[16][NKV * HD];
__device__ float g_delta_part[8][NKV * HD * HD];
// fp16 GEMM operands
__device__ __half g_hh[S * HID];             // hidden, [M][K]
__device__ __half g_wqT[HID * HID];          // [N][K]
__device__ __half g_wkT[NKV * HD * HID];
__device__ __half g_wvT[NKV * HD * HID];
__device__ __half g_woT[HID * HID];
__device__ __half g_ch[S * HID];             // combined (attention out), [M][K]
// fp16 hi/lo planes for attention
__device__ __half g_qh[S * HID];
__device__ __half g_ql[S * HID];
__device__ __half g_kh[S * NKV * HD];
__device__ __half g_kl[S * NKV * HD];
__device__ __half g_vth[NKV * HD * S];       // V^T hi: [h*HD+d][s]
__device__ __half g_vtl[NKV * HD * S];

// ---------------- fp16 mma + ldmatrix ----------------
__device__ __forceinline__ void mma_f16(
    float& c0, float& c1, float& c2, float& c3,
    uint32_t a0, uint32_t a1, uint32_t a2, uint32_t a3,
    uint32_t b0, uint32_t b1)
{
    asm volatile(
        "mma.sync.aligned.m16n8k16.row.col.f32.f16.f16.f32 "
        "{%0,%1,%2,%3},{%4,%5,%6,%7},{%8,%9},{%0,%1,%2,%3};"
        : "+f"(c0), "+f"(c1), "+f"(c2), "+f"(c3)
        : "r"(a0), "r"(a1), "r"(a2), "r"(a3), "r"(b0), "r"(b1));
}

#define LDSM4(r0, r1, r2, r3, addr) \
    asm volatile("ldmatrix.sync.aligned.m8n8.x4.shared.b16 {%0,%1,%2,%3}, [%4];" \
                 : "=r"(r0), "=r"(r1), "=r"(r2), "=r"(r3) : "r"(addr))

__device__ __forceinline__ uint32_t h2pack(float a, float b) {
    __half2 h = __floats2half2_rn(a, b);
    return *(uint32_t*)&h;
}
__device__ __forceinline__ void h16split(float x, __half& h, __half& l) {
    h = __float2half_rn(x);
    l = __float2half_rn(x - __half2float(h));
}

// ---------------- pre-pass: fp32 -> fp16 ----------------
__global__ __launch_bounds__(256) void h2h_kernel(
    const float* __restrict__ src, __half* __restrict__ dst, int n4)
{
    for (int i = blockIdx.x * 256 + threadIdx.x; i < n4; i += gridDim.x * 256) {
        float4 v = ((const float4*)src)[i];
        uint2 p = make_uint2(h2pack(v.x, v.y), h2pack(v.z, v.w));
        ((uint2*)dst)[i] = p;
    }
}

// transpose: w[K][N] fp32 -> wT[N][K] fp16
__global__ __launch_bounds__(256) void wtrans_kernel(
    const float* __restrict__ w, __half* __restrict__ wt, int Kd, int Nd)
{
    __shared__ float t[32][33];
    const int bx = blockIdx.x;
    const int by = blockIdx.y;
    const int x = threadIdx.x & 31;
    const int y = threadIdx.x >> 5;
#pragma unroll
    for (int j = 0; j < 4; j++) {
        int kr = y + 8 * j;
        t[kr][x] = w[(size_t)(by * 32 + kr) * Nd + bx * 32 + x];
    }
    __syncthreads();
#pragma unroll
    for (int j = 0; j < 4; j++) {
        int nr = y + 8 * j;
        wt[(size_t)(bx * 32 + nr) * Kd + by * 32 + x] = __float2half_rn(t[x][nr]);
    }
}

// ---------------- GEMM: fp16 m16n8k16 + ldmatrix, 4 warps, 64x64 warp tile, BK=32, 3-stage ----------------
#define HAS_STR 40
#define HBS_STR 40
#define STG4_BYTES ((128 * HAS_STR + 128 * HBS_STR) * 2)   // 20480
#define GEMM4_SMEM (3 * STG4_BYTES)                        // 61440

#define CP16(dst_u32, src_ptr) \
    asm volatile("cp.async.cg.shared.global [%0], [%1], 16;" :: "r"(dst_u32), "l"(src_ptr))

__global__ __launch_bounds__(128, 2) void gemm_f16_kernel(
    const __half* __restrict__ A,
    const __half* __restrict__ B0, float* __restrict__ C0, int N0,
    const __half* __restrict__ B1, float* __restrict__ C1,
    const __half* __restrict__ B2, float* __restrict__ C2, int N12,
    int K)
{
    const __half* Bt;
    float* C;
    int N, bx;
    if (blockIdx.z == 0) {
        Bt = B0; C = C0; N = N0; bx = blockIdx.x;
        if (bx * 128 >= N0) return;
    } else {
        N = N12;
        const int nt12 = N12 / 128;
        if ((int)blockIdx.x < nt12) { Bt = B1; C = C1; bx = blockIdx.x; }
        else if ((int)blockIdx.x < 2 * nt12) { Bt = B2; C = C2; bx = blockIdx.x - nt12; }
        else return;
    }

    extern __shared__ __half smh[];
    const uint32_t smu = (uint32_t)__cvta_generic_to_shared(smh);

    const int tid = threadIdx.x;
    const int lane = tid & 31;
    const int wid = tid >> 5;
    const int wm = wid >> 1;
    const int wn = wid & 1;
    const int lr = lane >> 2;
    const int lc = lane & 3;
    const int by = blockIdx.y;

    const int crow = tid >> 2;
    const int cchk = (tid & 3) * 8;

    const __half* Ab = A + (size_t)(by * 128) * K;
    const __half* Bb = Bt + (size_t)(bx * 128) * K;

    const uint32_t a_lane_off =
        (uint32_t)(((lane & 15) * HAS_STR + ((lane >> 4) << 3)) * 2);
    const uint32_t b_lane_off =
        (uint32_t)((((lane & 7) + ((lane >> 4) << 3)) * HBS_STR + (((lane >> 3) & 1) << 3)) * 2);

    float acc[4][8][4];
#pragma unroll
    for (int i = 0; i < 4; i++)
#pragma unroll
        for (int j = 0; j < 8; j++)
#pragma unroll
            for (int r = 0; r < 4; r++) acc[i][j][r] = 0.f;

    const int NT = K / 32;

#define LOAD_STAGE(stg, ch)                                                           \
    {                                                                                 \
        const uint32_t sb = smu + (uint32_t)((stg) * STG4_BYTES);                     \
        const int k0 = (ch) * 32;                                                     \
        _Pragma("unroll")                                                             \
        for (int i = 0; i < 4; i++) {                                                 \
            const int r = i * 32 + crow;                                              \
            CP16(sb + (uint32_t)((r * HAS_STR + cchk) * 2), Ab + (size_t)r * K + k0 + cchk); \
        }                                                                             \
        _Pragma("unroll")                                                             \
        for (int i = 0; i < 4; i++) {                                                 \
            const int r = i * 32 + crow;                                              \
            CP16(sb + (uint32_t)((128 * HAS_STR + r * HBS_STR + cchk) * 2),           \
                 Bb + (size_t)r * K + k0 + cchk);                                     \
        }                                                                             \
    }

    LOAD_STAGE(0, 0)
    asm volatile("cp.async.commit_group;" ::: "memory");
    LOAD_STAGE(1, 1)
    asm volatile("cp.async.commit_group;" ::: "memory");

    int stage = 0;
    for (int it = 0; it < NT; it++) {
        asm volatile("cp.async.wait_group 1;" ::: "memory");
        __syncthreads();

        const int pf = it + 2;
        if (pf < NT) {
            const int ps = (stage + 2) % 3;
            LOAD_STAGE(ps, pf)
        }
        asm volatile("cp.async.commit_group;" ::: "memory");

        const uint32_t sbA = smu + (uint32_t)(stage * STG4_BYTES);
        const uint32_t sbB = sbA + (uint32_t)(128 * HAS_STR * 2);

#pragma unroll
        for (int ks = 0; ks < 2; ks++) {
            const uint32_t kbB = (uint32_t)(ks * 16 * 2);
            uint32_t af[4][4], bf[8][2];
#pragma unroll
            for (int mt = 0; mt < 4; mt++) {
                const uint32_t addr = sbA
                    + (uint32_t)(((wm * 64 + mt * 16) * HAS_STR) * 2)
                    + a_lane_off + kbB;
                LDSM4(af[mt][0], af[mt][1], af[mt][2], af[mt][3], addr);
            }
#pragma unroll
            for (int ntp = 0; ntp < 4; ntp++) {
                const uint32_t addr = sbB
                    + (uint32_t)(((wn * 64 + ntp * 16) * HBS_STR) * 2)
                    + b_lane_off + kbB;
                LDSM4(bf[2 * ntp][0], bf[2 * ntp][1], bf[2 * ntp + 1][0], bf[2 * ntp + 1][1], addr);
            }
#pragma unroll
            for (int mt = 0; mt < 4; mt++)
#pragma unroll
                for (int nt = 0; nt < 8; nt++)
                    mma_f16(acc[mt][nt][0], acc[mt][nt][1], acc[mt][nt][2], acc[mt][nt][3],
                            af[mt][0], af[mt][1], af[mt][2], af[mt][3],
                            bf[nt][0], bf[nt][1]);
        }
        stage = (stage + 1) % 3;
    }
#undef LOAD_STAGE

#pragma unroll
    for (int mt = 0; mt < 4; mt++) {
        const int row = by * 128 + wm * 64 + mt * 16 + lr;
#pragma unroll
        for (int nt = 0; nt < 8; nt++) {
            const int col = bx * 128 + wn * 64 + nt * 8 + lc * 2;
            float2 v01 = make_float2(acc[mt][nt][0], acc[mt][nt][1]);
            float2 v23 = make_float2(acc[mt][nt][2], acc[mt][nt][3]);
            *(float2*)(C + (size_t)row * N + col) = v01;
            *(float2*)(C + (size_t)(row + 8) * N + col) = v23;
        }
    }
}

// ---------------- qn / kn: warp-per-head, no block barriers ----------------
__global__ __launch_bounds__(256) void qn2_kernel(const float* __restrict__ qp, float* __restrict__ qn)
{
    const int s = blockIdx.x;
    const int warp = threadIdx.x >> 5;
    const int lane = threadIdx.x & 31;
    for (int h = warp; h < NH; h += 8) {
        const float* src = qp + (size_t)s * HID + h * HD;
        float4 v = ((const float4*)src)[lane];
        float4 f;
        f.x = v.x > 0.f ? v.x + 1.f : __expf(v.x);
        f.y = v.y > 0.f ? v.y + 1.f : __expf(v.y);
        f.z = v.z > 0.f ? v.z + 1.f : __expf(v.z);
        f.w = v.w > 0.f ? v.w + 1.f : __expf(v.w);
        float t = f.x + f.y + f.z + f.w;
#pragma unroll
        for (int o = 16; o; o >>= 1) t += __shfl_xor_sync(0xffffffffu, t, o);
        const float inv = 1.f / (t + EPS);
        float4 r = make_float4(f.x * inv, f.y * inv, f.z * inv, f.w * inv);
        ((float4*)(qn + (size_t)s * HID + h * HD))[lane] = r;
    }
}

__global__ __launch_bounds__(256) void kn2_kernel(const float* __restrict__ kp, float* __restrict__ kn)
{
    const int s = blockIdx.x;
    const int warp = threadIdx.x >> 5;
    const int lane = threadIdx.x & 31;
    if (warp >= NKV) return;
    const float* src = kp + (size_t)s * (NKV * HD) + warp * HD;
    float4 v = ((const float4*)src)[lane];
    float4 f;
    f.x = v.x > 0.f ? v.x + 1.f : __expf(v.x);
    f.y = v.y > 0.f ? v.y + 1.f : __expf(v.y);
    f.z = v.z > 0.f ? v.z + 1.f : __expf(v.z);
    f.w = v.w > 0.f ? v.w + 1.f : __expf(v.w);
    float t = f.x + f.y + f.z + f.w;
#pragma unroll
    for (int o = 16; o; o >>= 1) t += __shfl_xor_sync(0xffffffffu, t, o);
    const float inv = 1.f / (t + EPS);
    float4 r = make_float4(f.x * inv, f.y * inv, f.z * inv, f.w * inv);
    ((float4*)(kn + (size_t)s * (NKV * HD) + warp * HD))[lane] = r;
}

__global__ __launch_bounds__(128) void knsum_part_kernel(const float* __restrict__ kn, float* __restrict__ part)
{
    const int h = blockIdx.x;
    const int p = blockIdx.y;
    const int d = threadIdx.x;
    float acc = 0.f;
    const int s0 = p * 128;
#pragma unroll 4
    for (int s = s0; s < s0 + 128; s++)
        acc += kn[(size_t)s * (NKV * HD) + h * HD + d];
    part[p * (NKV * HD) + h * HD + d] = acc;
}

__global__ __launch_bounds__(1024) void knsum_final_kernel(const float* __restrict__ part, float* __restrict__ knsum)
{
    const int i = threadIdx.x;
    float acc = 0.f;
#pragma unroll
    for (int p = 0; p < 16; p++) acc += part[p * (NKV * HD) + i];
    knsum[i] = acc;
}

// ---------------- memory retrieval ----------------
__global__ __launch_bounds__(128) void retrieve_kernel(
    const float* __restrict__ qn, const float* __restrict__ memory,
    const float* __restrict__ norm_m, float* __restrict__ memout)
{
    const int h = blockIdx.y;
    const int st = blockIdx.x;
    const int hm = h & (NKV - 1);
    const int e = threadIdx.x;
    __shared__ float Qs[16][128];
    __shared__ float Ms[32][128];
    __shared__ float Ns[128][33];

    for (int i = e; i < 16 * 128; i += 128) {
        int r = i >> 7, d = i & 127;
        Qs[r][d] = qn[(size_t)(st * 16 + r) * HID + h * HD + d];
    }
    float num[16], den[16];
#pragma unroll
    for (int r = 0; r < 16; r++) { num[r] = 0.f; den[r] = 0.f; }
    const float* M = memory + hm * HD * HD;
    const float* Nm = norm_m + hm * HD * HD;

    for (int d0 = 0; d0 < 128; d0 += 32) {
        __syncthreads();
        for (int i = e; i < 32 * 128; i += 128) {
            int dd = i >> 7, ee = i & 127;
            Ms[dd][ee] = M[(d0 + dd) * HD + ee];
        }
        for (int i = e; i < 128 * 32; i += 128) {
            int ee = i >> 5, dd = i & 31;
            Ns[ee][dd] = Nm[ee * HD + d0 + dd];
        }
        __syncthreads();
#pragma unroll 4
        for (int dd = 0; dd < 32; dd++) {
            float mv = Ms[dd][e];
            float nv = Ns[e][dd];
#pragma unroll
            for (int r = 0; r < 16; r++) {
                float qv = Qs[r][d0 + dd];
                num[r] += qv * mv;
                den[r] += qv * nv;
            }
        }
    }
#pragma unroll
    for (int r = 0; r < 16; r++)
        memout[(size_t)(st * 16 + r) * HID + h * HD + e] = num[r] / (den[r] + EPS);
}

// ---------------- v - v_ret for delta rule ----------------
__global__ __launch_bounds__(128) void vdelta_kernel(
    const float* __restrict__ kn, const float* __restrict__ vproj,
    const float* __restrict__ memory, const float* __restrict__ norm_m,
    float* __restrict__ vdelta)
{
    const int h = blockIdx.y;
    const int st = blockIdx.x;
    const int e = threadIdx.x;
    __shared__ float Qs[16][128];
    __shared__ float Ms[32][128];
    __shared__ float Ns[128][33];

    for (int i = e; i < 16 * 128; i += 128) {
        int r = i >> 7, d = i & 127;
        Qs[r][d] = kn[(size_t)(st * 16 + r) * (NKV * HD) + h * HD + d];
    }
    float num[16], den[16];
#pragma unroll
    for (int r = 0; r < 16; r++) { num[r] = 0.f; den[r] = 0.f; }
    const float* M = memory + h * HD * HD;
    const float* Nm = norm_m + h * HD * HD;

    for (int d0 = 0; d0 < 128; d0 += 32) {
        __syncthreads();
        for (int i = e; i < 32 * 128; i += 128) {
            int dd = i >> 7, ee = i & 127;
            Ms[dd][ee] = M[(d0 + dd) * HD + ee];
        }
        for (int i = e; i < 128 * 32; i += 128) {
            int ee = i >> 5, dd = i & 31;
            Ns[ee][dd] = Nm[ee * HD + d0 + dd];
        }
        __syncthreads();
#pragma unroll 4
        for (int dd = 0; dd < 32; dd++) {
            float mv = Ms[dd][e];
            float nv = Ns[e][dd];
#pragma unroll
            for (int r = 0; r < 16; r++) {
                float qv = Qs[r][d0 + dd];
                num[r] += qv * mv;
                den[r] += qv * nv;
            }
        }
    }
#pragma unroll
    for (int r = 0; r < 16; r++) {
        size_t idx = (size_t)(st * 16 + r) * (NKV * HD) + h * HD + e;
        vdelta[idx] = vproj[idx] - num[r] / (den[r] + EPS);
    }
}

// ---------------- RoPE + fp16 hi/lo split for Q,K ----------------
__global__ __launch_bounds__(256) void rope_split_kernel(
    const float* __restrict__ q, const float* __restrict__ k, const int* __restrict__ pos,
    __half* __restrict__ qh, __half* __restrict__ ql,
    __half* __restrict__ kh, __half* __restrict__ kl)
{
    const int s = blockIdx.x;
    const int idx = blockIdx.y * 256 + threadIdx.x;
    if (idx >= (NH + NKV) * 64) return;
    const int head = idx >> 6;
    const int d = idx & 63;
    const float p = (float)pos[s];
    const float invf = expf(-(2.0f * (float)d / 128.0f) * LN10000);
    const float a = p * invf;
    const float c = cosf(a), sn = sinf(a);
    const float* base;
    __half *oh, *ol;
    if (head < NH) {
        size_t off = (size_t)s * HID + head * HD;
        base = q + off; oh = qh + off; ol = ql + off;
    } else {
        size_t off = (size_t)s * (NKV * HD) + (head - NH) * HD;
        base = k + off; oh = kh + off; ol = kl + off;
    }
    float x0 = base[d], x1 = base[d + 64];
    float r0 = x0 * c - x1 * sn;
    float r1 = x1 * c + x0 * sn;
    __half h, l;
    h16split(r0, h, l);
    oh[d] = h; ol[d] = l;
    h16split(r1, h, l);
    oh[d + 64] = h; ol[d + 64] = l;
}

// ---------------- V transpose + split ----------------
__global__ __launch_bounds__(256) void vtrans_split_kernel(
    const float* __restrict__ v, __half* __restrict__ vth, __half* __restrict__ vtl)
{
    __shared__ float t[32][33];
    const int bx = blockIdx.x;
    const int by = blockIdx.y;
    const int x = threadIdx.x & 31;
    const int y = threadIdx.x >> 5;
#pragma unroll
    for (int j = 0; j < 4; j++) {
        int sr = y + 8 * j;
        t[sr][x] = v[(size_t)(bx * 32 + sr) * (NKV * HD) + by * 32 + x];
    }
    __syncthreads();
#pragma unroll
    for (int j = 0; j < 4; j++) {
        int cr = y + 8 * j;
        float val = t[x][cr];
        __half h, l;
        h16split(val, h, l);
        size_t idx = (size_t)(by * 32 + cr) * S + bx * 32 + x;
        vth[idx] = h;
        vtl[idx] = l;
    }
}

// ---------------- fp16-split MMA flash attention ----------------
#define QH_STR 136
#define KH_STR 136
#define VT_STR 72
#define PH_STR 72
#define SM_QH 0
#define SM_QL (128 * QH_STR)
#define SM_KH (SM_QL + 128 * QH_STR)
#define SM_KL (SM_KH + 64 * KH_STR)
#define SM_VTH (SM_KL + 64 * KH_STR)
#define SM_VTL (SM_VTH + 128 * VT_STR)
#define SM_PH (SM_VTL + 128 * VT_STR)
#define SM_PL (SM_PH + 128 * PH_STR)
#define ATT2_SMEM_HALVES (SM_PL + 128 * PH_STR)
#define ATT2_SMEM_BYTES (ATT2_SMEM_HALVES * 2)

__global__ __launch_bounds__(256) void attn_f16_kernel(
    const __half* __restrict__ qh, const __half* __restrict__ ql,
    const __half* __restrict__ kh, const __half* __restrict__ kl,
    const __half* __restrict__ vth, const __half* __restrict__ vtl,
    const float* __restrict__ memout, const float* __restrict__ beta,
    __half* __restrict__ ch)
{
    const int h = blockIdx.y;
    const int qt = (int)gridDim.x - 1 - (int)blockIdx.x;
    const int kvh = h >> 2;
    const int tid = threadIdx.x;
    const int warp = tid >> 5;
    const int lane = tid & 31;
    const int lr = lane >> 2;
    const int lc = lane & 3;

    extern __shared__ __half sh[];
    __half* Qh_ = sh + SM_QH;
    __half* Ql_ = sh + SM_QL;
    __half* Kh_ = sh + SM_KH;
    __half* Kl_ = sh + SM_KL;
    __half* Vth_ = sh + SM_VTH;
    __half* Vtl_ = sh + SM_VTL;
    __half* Ph_ = sh + SM_PH;
    __half* Pl_ = sh + SM_PL;

#pragma unroll
    for (int it = 0; it < 8; it++) {
        int i = it * 256 + tid;
        int row = i >> 4, c8 = (i & 15) * 8;
        size_t gidx = (size_t)(qt * 128 + row) * HID + h * HD + c8;
        *(uint4*)(Qh_ + row * QH_STR + c8) = *(const uint4*)(qh + gidx);
        *(uint4*)(Ql_ + row * QH_STR + c8) = *(const uint4*)(ql + gidx);
    }

    const int row0 = warp * 16 + lr;
    const int row1 = row0 + 8;
    const int grow0 = qt * 128 + row0;
    const int grow1 = grow0 + 8;

    float m0 = -1e30f, m1 = -1e30f, l0 = 0.f, l1 = 0.f;
    float o[16][4];
#pragma unroll
    for (int nt = 0; nt < 16; nt++)
#pragma unroll
        for (int r = 0; r < 4; r++) o[nt][r] = 0.f;

    const int ktmax = 2 * qt + 1;
    for (int kt = 0; kt <= ktmax; kt++) {
        __syncthreads();
#pragma unroll
        for (int it = 0; it < 4; it++) {
            int i = it * 256 + tid;
            int key = i >> 4, c8 = (i & 15) * 8;
            size_t gidx = (size_t)(kt * 64 + key) * (NKV * HD) + kvh * HD + c8;
            *(uint4*)(Kh_ + key * KH_STR + c8) = *(const uint4*)(kh + gidx);
            *(uint4*)(Kl_ + key * KH_STR + c8) = *(const uint4*)(kl + gidx);
        }
#pragma unroll
        for (int it = 0; it < 4; it++) {
            int i = it * 256 + tid;
            int dr = i >> 3, kc = (i & 7) * 8;
            size_t gidx = (size_t)(kvh * HD + dr) * S + kt * 64 + kc;
            *(uint4*)(Vth_ + dr * VT_STR + kc) = *(const uint4*)(vth + gidx);
            *(uint4*)(Vtl_ + dr * VT_STR + kc) = *(const uint4*)(vtl + gidx);
        }
        __syncthreads();

        float sc[8][4];
#pragma unroll
        for (int nt = 0; nt < 8; nt++)
#pragma unroll
            for (int r = 0; r < 4; r++) sc[nt][r] = 0.f;

#pragma unroll
        for (int ks = 0; ks < 8; ks++) {
            const int kb = ks * 16;
            uint32_t ah[4], al[4];
            {
                const __half* p0 = Qh_ + row0 * QH_STR + kb + 2 * lc;
                const __half* p1 = Qh_ + row1 * QH_STR + kb + 2 * lc;
                ah[0] = *(const uint32_t*)(p0);
                ah[1] = *(const uint32_t*)(p1);
                ah[2] = *(const uint32_t*)(p0 + 8);
                ah[3] = *(const uint32_t*)(p1 + 8);
                const __half* q0 = Ql_ + row0 * QH_STR + kb + 2 * lc;
                const __half* q1 = Ql_ + row1 * QH_STR + kb + 2 * lc;
                al[0] = *(const uint32_t*)(q0);
                al[1] = *(const uint32_t*)(q1);
                al[2] = *(const uint32_t*)(q0 + 8);
                al[3] = *(const uint32_t*)(q1 + 8);
            }
#pragma unroll
            for (int nt = 0; nt < 8; nt++) {
                const int n0 = nt * 8 + lr;
                const __half* ph = Kh_ + n0 * KH_STR + kb + 2 * lc;
                const __half* pl = Kl_ + n0 * KH_STR + kb + 2 * lc;
                uint32_t bh0 = *(const uint32_t*)(ph);
                uint32_t bh1 = *(const uint32_t*)(ph + 8);
                uint32_t bl0 = *(const uint32_t*)(pl);
                uint32_t bl1 = *(const uint32_t*)(pl + 8);
                mma_f16(sc[nt][0], sc[nt][1], sc[nt][2], sc[nt][3],
                        ah[0], ah[1], ah[2], ah[3], bh0, bh1);
                mma_f16(sc[nt][0], sc[nt][1], sc[nt][2], sc[nt][3],
                        ah[0], ah[1], ah[2], ah[3], bl0, bl1);
                mma_f16(sc[nt][0], sc[nt][1], sc[nt][2], sc[nt][3],
                        al[0], al[1], al[2], al[3], bh0, bh1);
            }
        }

        const bool need_mask = (kt >= 2 * qt);
        float mx0 = -1e30f, mx1 = -1e30f;
#pragma unroll
        for (int nt = 0; nt < 8; nt++) {
#pragma unroll
            for (int j = 0; j < 2; j++) {
                int col = kt * 64 + nt * 8 + 2 * lc + j;
                float s0 = sc[nt][j] * ATT_SCALE;
                float s1 = sc[nt][2 + j] * ATT_SCALE;
                if (need_mask) {
                    if (col > grow0) s0 = -1e30f;
                    if (col > grow1) s1 = -1e30f;
                }
                sc[nt][j] = s0;
                sc[nt][2 + j] = s1;
                mx0 = fmaxf(mx0, s0);
                mx1 = fmaxf(mx1, s1);
            }
        }
        mx0 = fmaxf(mx0, __shfl_xor_sync(0xffffffffu, mx0, 1));
        mx0 = fmaxf(mx0, __shfl_xor_sync(0xffffffffu, mx0, 2));
        mx1 = fmaxf(mx1, __shfl_xor_sync(0xffffffffu, mx1, 1));
        mx1 = fmaxf(mx1, __shfl_xor_sync(0xffffffffu, mx1, 2));
        const float mn0 = fmaxf(m0, mx0);
        const float mn1 = fmaxf(m1, mx1);
        const float scl0 = __expf(m0 - mn0);
        const float scl1 = __expf(m1 - mn1);
        float ls0 = 0.f, ls1 = 0.f;
#pragma unroll
        for (int nt = 0; nt < 8; nt++) {
            float p00 = __expf(sc[nt][0] - mn0);
            float p01 = __expf(sc[nt][1] - mn0);
            float p10 = __expf(sc[nt][2] - mn1);
            float p11 = __expf(sc[nt][3] - mn1);
            ls0 += p00 + p01;
            ls1 += p10 + p11;
            __half h0, l0h, h1, l1h;
            h16split(p00, h0, l0h);
            h16split(p01, h1, l1h);
            *(uint32_t*)(Ph_ + row0 * PH_STR + nt * 8 + 2 * lc) =
                (uint32_t)__half_as_ushort(h0) | ((uint32_t)__half_as_ushort(h1) << 16);
            *(uint32_t*)(Pl_ + row0 * PH_STR + nt * 8 + 2 * lc) =
                (uint32_t)__half_as_ushort(l0h) | ((uint32_t)__half_as_ushort(l1h) << 16);
            h16split(p10, h0, l0h);
            h16split(p11, h1, l1h);
            *(uint32_t*)(Ph_ + row1 * PH_STR + nt * 8 + 2 * lc) =
                (uint32_t)__half_as_ushort(h0) | ((uint32_t)__half_as_ushort(h1) << 16);
            *(uint32_t*)(Pl_ + row1 * PH_STR + nt * 8 + 2 * lc) =
                (uint32_t)__half_as_ushort(l0h) | ((uint32_t)__half_as_ushort(l1h) << 16);
        }
        ls0 += __shfl_xor_sync(0xffffffffu, ls0, 1);
        ls0 += __shfl_xor_sync(0xffffffffu, ls0, 2);
        ls1 += __shfl_xor_sync(0xffffffffu, ls1, 1);
        ls1 += __shfl_xor_sync(0xffffffffu, ls1, 2);
        l0 = l0 * scl0 + ls0;
        l1 = l1 * scl1 + ls1;
        m0 = mn0;
        m1 = mn1;

#pragma unroll
        for (int nt = 0; nt < 16; nt++) {
            o[nt][0] *= scl0;
            o[nt][1] *= scl0;
            o[nt][2] *= scl1;
            o[nt][3] *= scl1;
        }
        __syncwarp();

#pragma unroll
        for (int ks2 = 0; ks2 < 4; ks2++) {
            const int kb = ks2 * 16;
            uint32_t ah[4], al[4];
            {
                const __half* p0 = Ph_ + row0 * PH_STR + kb + 2 * lc;
                const __half* p1 = Ph_ + row1 * PH_STR + kb + 2 * lc;
                ah[0] = *(const uint32_t*)(p0);
                ah[1] = *(const uint32_t*)(p1);
                ah[2] = *(const uint32_t*)(p0 + 8);
                ah[3] = *(const uint32_t*)(p1 + 8);
                const __half* q0 = Pl_ + row0 * PH_STR + kb + 2 * lc;
                const __half* q1 = Pl_ + row1 * PH_STR + kb + 2 * lc;
                al[0] = *(const uint32_t*)(q0);
                al[1] = *(const uint32_t*)(q1);
                al[2] = *(const uint32_t*)(q0 + 8);
                al[3] = *(const uint32_t*)(q1 + 8);
            }
#pragma unroll
            for (int nt = 0; nt < 16; nt++) {
                const int n0 = nt * 8 + lr;
                const __half* ph = Vth_ + n0 * VT_STR + kb + 2 * lc;
                const __half* pl = Vtl_ + n0 * VT_STR + kb + 2 * lc;
                uint32_t bh0 = *(const uint32_t*)(ph);
                uint32_t bh1 = *(const uint32_t*)(ph + 8);
                uint32_t bl0 = *(const uint32_t*)(pl);
                uint32_t bl1 = *(const uint32_t*)(pl + 8);
                mma_f16(o[nt][0], o[nt][1], o[nt][2], o[nt][3],
                        ah[0], ah[1], ah[2], ah[3], bh0, bh1);
                mma_f16(o[nt][0], o[nt][1], o[nt][2], o[nt][3],
                        ah[0], ah[1], ah[2], ah[3], bl0, bl1);
                mma_f16(o[nt][0], o[nt][1], o[nt][2], o[nt][3],
                        al[0], al[1], al[2], al[3], bh0, bh1);
            }
        }
    }

    // epilogue: gate-combine, emit fp16
    const float g = 1.f / (1.f + __expf(-beta[0]));
    const float og = 1.f - g;
    const float li0 = 1.f / l0;
    const float li1 = 1.f / l1;
#pragma unroll
    for (int nt = 0; nt < 16; nt++) {
        const int col = nt * 8 + 2 * lc;
        size_t i0 = (size_t)grow0 * HID + h * HD + col;
        size_t i1 = (size_t)grow1 * HID + h * HD + col;
        float2 mo0 = *(const float2*)(memout + i0);
        float2 mo1 = *(const float2*)(memout + i1);
        *(uint32_t*)(ch + i0) = h2pack(g * mo0.x + og * (o[nt][0] * li0),
                                       g * mo0.y + og * (o[nt][1] * li0));
        *(uint32_t*)(ch + i1) = h2pack(g * mo1.x + og * (o[nt][2] * li1),
                                       g * mo1.y + og * (o[nt][3] * li1));
    }
}

// ---------------- delta-rule partials ----------------
__global__ __launch_bounds__(256) void delta_part_kernel(
    const float* __restrict__ kn, const float* __restrict__ vd, float* __restrict__ part)
{
    const int h = blockIdx.x;
    const int c = blockIdx.y;
    __shared__ float Ak[32][128];
    __shared__ float Bv[32][128];
    const int trow = (threadIdx.x >> 4) * 8;
    const int tcol = (threadIdx.x & 15) * 8;
    float acc[8][8];
#pragma unroll
    for (int i = 0; i < 8; i++)
#pragma unroll
        for (int j = 0; j < 8; j++) acc[i][j] = 0.f;

    const int sbeg = c * 256;
    for (int s0 = sbeg; s0 < sbeg + 256; s0 += 32) {
        for (int i = threadIdx.x; i < 32 * 128; i += 256) {
            int ss = i >> 7, dd = i & 127;
            size_t idx = (size_t)(s0 + ss) * (NKV * HD) + h * HD + dd;
            Ak[ss][dd] = kn[idx];
            Bv[ss][dd] = vd[idx];
        }
        __syncthreads();
#pragma unroll 4
        for (int ss = 0; ss < 32; ss++) {
            float ra[8], rb[8];
#pragma unroll
            for (int i = 0; i < 8; i++) ra[i] = Ak[ss][trow + i];
#pragma unroll
            for (int j = 0; j < 8; j++) rb[j] = Bv[ss][tcol + j];
#pragma unroll
            for (int i = 0; i < 8; i++)
#pragma unroll
                for (int j = 0; j < 8; j++) acc[i][j] += ra[i] * rb[j];
        }
        __syncthreads();
    }
    float* Ph = part + (size_t)c * (NKV * HD * HD) + h * HD * HD;
#pragma unroll
    for (int i = 0; i < 8; i++)
#pragma unroll
        for (int j = 0; j < 8; j++)
            Ph[(trow + i) * HD + tcol + j] = acc[i][j];
}

// fused memory-update + norm-update (same index space)
__global__ __launch_bounds__(256) void finalize_kernel(
    const float* __restrict__ part, const float* __restrict__ memory,
    const float* __restrict__ norm_m, const float* __restrict__ knsum,
    float* __restrict__ outmem, float* __restrict__ outnorm)
{
    const int i = blockIdx.x * 256 + threadIdx.x;   // < NKV*HD*HD
    float acc = memory[i];
#pragma unroll
    for (int c = 0; c < 8; c++) acc += part[(size_t)c * (NKV * HD * HD) + i];
    outmem[i] = acc;
    const int h = i >> 14;
    const int j = i & 127;
    outnorm[i] = norm_m[i] + knsum[h * HD + j];
}

// ---------------- launch ----------------
extern "C" void kernel_launch(void* const* d_in, const int* in_sizes, int n_in,
                              void* d_out, int out_size)
{
    const float* hidden = (const float*)d_in[0];
    const int*   pos    = (const int*)d_in[1];
    const float* wq     = (const float*)d_in[2];
    const float* wk     = (const float*)d_in[3];
    const float* wv     = (const float*)d_in[4];
    const float* wo     = (const float*)d_in[5];
    const float* memory = (const float*)d_in[6];
    const float* norm_m = (const float*)d_in[7];
    const float* beta   = (const float*)d_in[8];
    float* out = (float*)d_out;

    float *qproj, *kproj, *vproj, *qn, *kn, *memout, *vdelta, *knsum, *knpart, *dpart;
    __half *hh, *wqT, *wkT, *wvT, *woT, *ch, *qh, *ql, *kh, *kl, *vth, *vtl;
    cudaGetSymbolAddress((void**)&qproj, g_qproj);
    cudaGetSymbolAddress((void**)&kproj, g_kproj);
    cudaGetSymbolAddress((void**)&vproj, g_vproj);
    cudaGetSymbolAddress((void**)&qn, g_qn);
    cudaGetSymbolAddress((void**)&kn, g_kn);
    cudaGetSymbolAddress((void**)&memout, g_memout);
    cudaGetSymbolAddress((void**)&vdelta, g_vdelta);
    cudaGetSymbolAddress((void**)&knsum, g_knsum);
    cudaGetSymbolAddress((void**)&knpart, g_knsum_part);
    cudaGetSymbolAddress((void**)&dpart, g_delta_part);
    cudaGetSymbolAddress((void**)&hh, g_hh);
    cudaGetSymbolAddress((void**)&wqT, g_wqT);
    cudaGetSymbolAddress((void**)&wkT, g_wkT);
    cudaGetSymbolAddress((void**)&wvT, g_wvT);
    cudaGetSymbolAddress((void**)&woT, g_woT);
    cudaGetSymbolAddress((void**)&ch, g_ch);
    cudaGetSymbolAddress((void**)&qh, g_qh);
    cudaGetSymbolAddress((void**)&ql, g_ql);
    cudaGetSymbolAddress((void**)&kh, g_kh);
    cudaGetSymbolAddress((void**)&kl, g_kl);
    cudaGetSymbolAddress((void**)&vth, g_vth);
    cudaGetSymbolAddress((void**)&vtl, g_vtl);

    cudaFuncSetAttribute(attn_f16_kernel,
                         cudaFuncAttributeMaxDynamicSharedMemorySize, ATT2_SMEM_BYTES);
    cudaFuncSetAttribute(gemm_f16_kernel,
                         cudaFuncAttributeMaxDynamicSharedMemorySize, GEMM4_SMEM);

    // pre-pass: hidden -> fp16; weights -> transposed [N][K] fp16
    h2h_kernel<<<1024, 256>>>(hidden, hh, S * HID / 4);
    wtrans_kernel<<<dim3(HID / 32, HID / 32), 256>>>(wq, wqT, HID, HID);
    wtrans_kernel<<<dim3(NKV * HD / 32, HID / 32), 256>>>(wk, wkT, HID, NKV * HD);
    wtrans_kernel<<<dim3(NKV * HD / 32, HID / 32), 256>>>(wv, wvT, HID, NKV * HD);
    wtrans_kernel<<<dim3(HID / 32, HID / 32), 256>>>(wo, woT, HID, HID);

    // projections (fp16 m16n8k16 + ldmatrix, 3-stage). z=0: Q; z=1: bx<8 K, bx<16 V.
    gemm_f16_kernel<<<dim3(HID / 128, S / 128, 2), 128, GEMM4_SMEM>>>(
        hh, wqT, qproj, HID, wkT, kproj, wvT, vproj, NKV * HD, HID);

    // normalized features from PRE-RoPE q/k (warp-per-head, barrier-free)
    qn2_kernel<<<S, 256>>>(qproj, qn);
    kn2_kernel<<<S, 256>>>(kproj, kn);
    knsum_part_kernel<<<dim3(NKV, 16), 128>>>(kn, knpart);
    knsum_final_kernel<<<1, 1024>>>(knpart, knsum);

    // compressive-memory retrieval + delta-rule prep
    retrieve_kernel<<<dim3(S / 16, NH), 128>>>(qn, memory, norm_m, memout);
    vdelta_kernel<<<dim3(S / 16, NKV), 128>>>(kn, vproj, memory, norm_m, vdelta);

    // RoPE + fp16 hi/lo split; V transpose + split
    rope_split_kernel<<<dim3(S, 10), 256>>>(qproj, kproj, pos, qh, ql, kh, kl);
    vtrans_split_kernel<<<dim3(S / 32, NKV * HD / 32), 256>>>(vproj, vth, vtl);

    // fp16-split flash attention (fuses gated combine, emits fp16 combined)
    attn_f16_kernel<<<dim3(S / 128, NH), 256, ATT2_SMEM_BYTES>>>(
        qh, ql, kh, kl, vth, vtl, memout, beta, ch);

    // output projection (fp16)
    gemm_f16_kernel<<<dim3(HID / 128, S / 128, 1), 128, GEMM4_SMEM>>>(
        ch, woT, out, HID, woT, out, woT, out, HID, HID);

    // memory & norm updates (fused; appended after the 8.4M-element `out`)
    delta_part_kernel<<<dim3(NKV, 8), 256>>>(kn, vdelta, dpart);
    finalize_kernel<<<(NKV * HD * HD) / 256, 256>>>(
        dpart, memory, norm_m, knsum,
        out + (size_t)S * HID, out + (size_t)S * HID + NKV * HD * HD);
}

// round 15
// speedup vs baseline: 1.7668x; 1.0013x over previous
#include <cuda_runtime.h>
#include <cuda_fp16.h>
#include <math.h>
#include <stdint.h>

// ---------------- problem constants ----------------
#define S 2048
#define HID 4096
#define NH 32
#define NKV 8
#define HD 128
#define GROUPS 4
#define EPS 1e-8f
#define ATT_SCALE 0.08838834764831845f   // 128^-0.5
#define LN10000 9.210340371976184f

// ---------------- scratch (device globals; no allocation allowed) ----------------
__device__ float g_qproj[S * HID];
__device__ float g_kproj[S * NKV * HD];
__device__ float g_vproj[S * NKV * HD];
__device__ float g_qn[S * HID];
__device__ float g_kn[S * NKV * HD];
__device__ float g_memout[S * HID];
__device__ float g_vdelta[S * NKV * HD];
__device__ float g_knsum[NKV * HD];
__device__ float g_knsum_part[16][NKV * HD];
__device__ float g_delta_part[8][NKV * HD * HD];
// fp16 GEMM operands
__device__ __half g_hh[S * HID];             // hidden, [M][K]
__device__ __half g_wqT[HID * HID];          // [N][K]
__device__ __half g_wkT[NKV * HD * HID];
__device__ __half g_wvT[NKV * HD * HID];
__device__ __half g_woT[HID * HID];
__device__ __half g_ch[S * HID];             // combined (attention out), [M][K]
// fp16 hi/lo planes for attention
__device__ __half g_qh[S * HID];
__device__ __half g_ql[S * HID];
__device__ __half g_kh[S * NKV * HD];
__device__ __half g_kl[S * NKV * HD];
__device__ __half g_vth[NKV * HD * S];       // V^T hi: [h*HD+d][s]
__device__ __half g_vtl[NKV * HD * S];

// ---------------- fp16 mma + ldmatrix ----------------
__device__ __forceinline__ void mma_f16(
    float& c0, float& c1, float& c2, float& c3,
    uint32_t a0, uint32_t a1, uint32_t a2, uint32_t a3,
    uint32_t b0, uint32_t b1)
{
    asm volatile(
        "mma.sync.aligned.m16n8k16.row.col.f32.f16.f16.f32 "
        "{%0,%1,%2,%3},{%4,%5,%6,%7},{%8,%9},{%0,%1,%2,%3};"
        : "+f"(c0), "+f"(c1), "+f"(c2), "+f"(c3)
        : "r"(a0), "r"(a1), "r"(a2), "r"(a3), "r"(b0), "r"(b1));
}

#define LDSM4(r0, r1, r2, r3, addr) \
    asm volatile("ldmatrix.sync.aligned.m8n8.x4.shared.b16 {%0,%1,%2,%3}, [%4];" \
                 : "=r"(r0), "=r"(r1), "=r"(r2), "=r"(r3) : "r"(addr))

__device__ __forceinline__ uint32_t h2pack(float a, float b) {
    __half2 h = __floats2half2_rn(a, b);
    return *(uint32_t*)&h;
}
__device__ __forceinline__ void h16split(float x, __half& h, __half& l) {
    h = __float2half_rn(x);
    l = __float2half_rn(x - __half2float(h));
}

// ---------------- pre-pass: fp32 -> fp16 ----------------
__global__ __launch_bounds__(256) void h2h_kernel(
    const float* __restrict__ src, __half* __restrict__ dst, int n4)
{
    for (int i = blockIdx.x * 256 + threadIdx.x; i < n4; i += gridDim.x * 256) {
        float4 v = ((const float4*)src)[i];
        uint2 p = make_uint2(h2pack(v.x, v.y), h2pack(v.z, v.w));
        ((uint2*)dst)[i] = p;
    }
}

// transpose all four weights in ONE launch: z selects the matrix.
__global__ __launch_bounds__(256) void wtrans4_kernel(
    const float* __restrict__ wq, __half* __restrict__ wqt,
    const float* __restrict__ wk, __half* __restrict__ wkt,
    const float* __restrict__ wv, __half* __restrict__ wvt,
    const float* __restrict__ wo, __half* __restrict__ wot)
{
    const float* w;
    __half* wt;
    int Nd;
    switch (blockIdx.z) {
        case 0: w = wq; wt = wqt; Nd = HID; break;
        case 1: w = wk; wt = wkt; Nd = NKV * HD; break;
        case 2: w = wv; wt = wvt; Nd = NKV * HD; break;
        default: w = wo; wt = wot; Nd = HID; break;
    }
    const int bx = blockIdx.x;       // N tile
    if (bx * 32 >= Nd) return;
    const int by = blockIdx.y;       // K tile
    __shared__ float t[32][33];
    const int x = threadIdx.x & 31;
    const int y = threadIdx.x >> 5;
#pragma unroll
    for (int j = 0; j < 4; j++) {
        int kr = y + 8 * j;
        t[kr][x] = w[(size_t)(by * 32 + kr) * Nd + bx * 32 + x];
    }
    __syncthreads();
#pragma unroll
    for (int j = 0; j < 4; j++) {
        int nr = y + 8 * j;
        wt[(size_t)(bx * 32 + nr) * HID + by * 32 + x] = __float2half_rn(t[x][nr]);
    }
}

// ---------------- GEMM: fp16 m16n8k16 + ldmatrix, 4 warps, 64x64 warp tile, BK=32, 3-stage ----------------
#define HAS_STR 40
#define HBS_STR 40
#define STG4_BYTES ((128 * HAS_STR + 128 * HBS_STR) * 2)   // 20480
#define GEMM4_SMEM (3 * STG4_BYTES)                        // 61440

#define CP16(dst_u32, src_ptr) \
    asm volatile("cp.async.cg.shared.global [%0], [%1], 16;" :: "r"(dst_u32), "l"(src_ptr))

__global__ __launch_bounds__(128, 2) void gemm_f16_kernel(
    const __half* __restrict__ A,
    const __half* __restrict__ B0, float* __restrict__ C0, int N0,
    const __half* __restrict__ B1, float* __restrict__ C1,
    const __half* __restrict__ B2, float* __restrict__ C2, int N12,
    int K)
{
    const __half* Bt;
    float* C;
    int N, bx;
    if (blockIdx.z == 0) {
        Bt = B0; C = C0; N = N0; bx = blockIdx.x;
        if (bx * 128 >= N0) return;
    } else {
        N = N12;
        const int nt12 = N12 / 128;
        if ((int)blockIdx.x < nt12) { Bt = B1; C = C1; bx = blockIdx.x; }
        else if ((int)blockIdx.x < 2 * nt12) { Bt = B2; C = C2; bx = blockIdx.x - nt12; }
        else return;
    }

    extern __shared__ __half smh[];
    const uint32_t smu = (uint32_t)__cvta_generic_to_shared(smh);

    const int tid = threadIdx.x;
    const int lane = tid & 31;
    const int wid = tid >> 5;
    const int wm = wid >> 1;
    const int wn = wid & 1;
    const int lr = lane >> 2;
    const int lc = lane & 3;
    const int by = blockIdx.y;

    const int crow = tid >> 2;
    const int cchk = (tid & 3) * 8;

    const __half* Ab = A + (size_t)(by * 128) * K;
    const __half* Bb = Bt + (size_t)(bx * 128) * K;

    const uint32_t a_lane_off =
        (uint32_t)(((lane & 15) * HAS_STR + ((lane >> 4) << 3)) * 2);
    const uint32_t b_lane_off =
        (uint32_t)((((lane & 7) + ((lane >> 4) << 3)) * HBS_STR + (((lane >> 3) & 1) << 3)) * 2);

    float acc[4][8][4];
#pragma unroll
    for (int i = 0; i < 4; i++)
#pragma unroll
        for (int j = 0; j < 8; j++)
#pragma unroll
            for (int r = 0; r < 4; r++) acc[i][j][r] = 0.f;

    const int NT = K / 32;

#define LOAD_STAGE(stg, ch)                                                           \
    {                                                                                 \
        const uint32_t sb = smu + (uint32_t)((stg) * STG4_BYTES);                     \
        const int k0 = (ch) * 32;                                                     \
        _Pragma("unroll")                                                             \
        for (int i = 0; i < 4; i++) {                                                 \
            const int r = i * 32 + crow;                                              \
            CP16(sb + (uint32_t)((r * HAS_STR + cchk) * 2), Ab + (size_t)r * K + k0 + cchk); \
        }                                                                             \
        _Pragma("unroll")                                                             \
        for (int i = 0; i < 4; i++) {                                                 \
            const int r = i * 32 + crow;                                              \
            CP16(sb + (uint32_t)((128 * HAS_STR + r * HBS_STR + cchk) * 2),           \
                 Bb + (size_t)r * K + k0 + cchk);                                     \
        }                                                                             \
    }

    LOAD_STAGE(0, 0)
    asm volatile("cp.async.commit_group;" ::: "memory");
    LOAD_STAGE(1, 1)
    asm volatile("cp.async.commit_group;" ::: "memory");

    int stage = 0;
    for (int it = 0; it < NT; it++) {
        asm volatile("cp.async.wait_group 1;" ::: "memory");
        __syncthreads();

        const int pf = it + 2;
        if (pf < NT) {
            const int ps = (stage + 2) % 3;
            LOAD_STAGE(ps, pf)
        }
        asm volatile("cp.async.commit_group;" ::: "memory");

        const uint32_t sbA = smu + (uint32_t)(stage * STG4_BYTES);
        const uint32_t sbB = sbA + (uint32_t)(128 * HAS_STR * 2);

#pragma unroll
        for (int ks = 0; ks < 2; ks++) {
            const uint32_t kbB = (uint32_t)(ks * 16 * 2);
            uint32_t af[4][4], bf[8][2];
#pragma unroll
            for (int mt = 0; mt < 4; mt++) {
                const uint32_t addr = sbA
                    + (uint32_t)(((wm * 64 + mt * 16) * HAS_STR) * 2)
                    + a_lane_off + kbB;
                LDSM4(af[mt][0], af[mt][1], af[mt][2], af[mt][3], addr);
            }
#pragma unroll
            for (int ntp = 0; ntp < 4; ntp++) {
                const uint32_t addr = sbB
                    + (uint32_t)(((wn * 64 + ntp * 16) * HBS_STR) * 2)
                    + b_lane_off + kbB;
                LDSM4(bf[2 * ntp][0], bf[2 * ntp][1], bf[2 * ntp + 1][0], bf[2 * ntp + 1][1], addr);
            }
#pragma unroll
            for (int mt = 0; mt < 4; mt++)
#pragma unroll
                for (int nt = 0; nt < 8; nt++)
                    mma_f16(acc[mt][nt][0], acc[mt][nt][1], acc[mt][nt][2], acc[mt][nt][3],
                            af[mt][0], af[mt][1], af[mt][2], af[mt][3],
                            bf[nt][0], bf[nt][1]);
        }
        stage = (stage + 1) % 3;
    }
#undef LOAD_STAGE

#pragma unroll
    for (int mt = 0; mt < 4; mt++) {
        const int row = by * 128 + wm * 64 + mt * 16 + lr;
#pragma unroll
        for (int nt = 0; nt < 8; nt++) {
            const int col = bx * 128 + wn * 64 + nt * 8 + lc * 2;
            float2 v01 = make_float2(acc[mt][nt][0], acc[mt][nt][1]);
            float2 v23 = make_float2(acc[mt][nt][2], acc[mt][nt][3]);
            *(float2*)(C + (size_t)row * N + col) = v01;
            *(float2*)(C + (size_t)(row + 8) * N + col) = v23;
        }
    }
}

// ---------------- qn / kn: warp-per-head, no block barriers ----------------
__global__ __launch_bounds__(256) void qn2_kernel(const float* __restrict__ qp, float* __restrict__ qn)
{
    const int s = blockIdx.x;
    const int warp = threadIdx.x >> 5;
    const int lane = threadIdx.x & 31;
    for (int h = warp; h < NH; h += 8) {
        const float* src = qp + (size_t)s * HID + h * HD;
        float4 v = ((const float4*)src)[lane];
        float4 f;
        f.x = v.x > 0.f ? v.x + 1.f : __expf(v.x);
        f.y = v.y > 0.f ? v.y + 1.f : __expf(v.y);
        f.z = v.z > 0.f ? v.z + 1.f : __expf(v.z);
        f.w = v.w > 0.f ? v.w + 1.f : __expf(v.w);
        float t = f.x + f.y + f.z + f.w;
#pragma unroll
        for (int o = 16; o; o >>= 1) t += __shfl_xor_sync(0xffffffffu, t, o);
        const float inv = 1.f / (t + EPS);
        float4 r = make_float4(f.x * inv, f.y * inv, f.z * inv, f.w * inv);
        ((float4*)(qn + (size_t)s * HID + h * HD))[lane] = r;
    }
}

__global__ __launch_bounds__(256) void kn2_kernel(const float* __restrict__ kp, float* __restrict__ kn)
{
    const int s = blockIdx.x;
    const int warp = threadIdx.x >> 5;
    const int lane = threadIdx.x & 31;
    if (warp >= NKV) return;
    const float* src = kp + (size_t)s * (NKV * HD) + warp * HD;
    float4 v = ((const float4*)src)[lane];
    float4 f;
    f.x = v.x > 0.f ? v.x + 1.f : __expf(v.x);
    f.y = v.y > 0.f ? v.y + 1.f : __expf(v.y);
    f.z = v.z > 0.f ? v.z + 1.f : __expf(v.z);
    f.w = v.w > 0.f ? v.w + 1.f : __expf(v.w);
    float t = f.x + f.y + f.z + f.w;
#pragma unroll
    for (int o = 16; o; o >>= 1) t += __shfl_xor_sync(0xffffffffu, t, o);
    const float inv = 1.f / (t + EPS);
    float4 r = make_float4(f.x * inv, f.y * inv, f.z * inv, f.w * inv);
    ((float4*)(kn + (size_t)s * (NKV * HD) + warp * HD))[lane] = r;
}

__global__ __launch_bounds__(128) void knsum_part_kernel(const float* __restrict__ kn, float* __restrict__ part)
{
    const int h = blockIdx.x;
    const int p = blockIdx.y;
    const int d = threadIdx.x;
    float acc = 0.f;
    const int s0 = p * 128;
#pragma unroll 4
    for (int s = s0; s < s0 + 128; s++)
        acc += kn[(size_t)s * (NKV * HD) + h * HD + d];
    part[p * (NKV * HD) + h * HD + d] = acc;
}

__global__ __launch_bounds__(1024) void knsum_final_kernel(const float* __restrict__ part, float* __restrict__ knsum)
{
    const int i = threadIdx.x;
    float acc = 0.f;
#pragma unroll
    for (int p = 0; p < 16; p++) acc += part[p * (NKV * HD) + i];
    knsum[i] = acc;
}

// ---------------- merged retrieval + vdelta (one launch, grid y in [0, NH+NKV)) ----------------
// y < NH: retrieve head y from qn -> memout.
// y >= NH: vdelta head y-NH from kn/vproj -> vdelta.
// Bodies identical to the previous separate kernels (same accumulation order).
__global__ __launch_bounds__(128) void memops_kernel(
    const float* __restrict__ qn, const float* __restrict__ kn,
    const float* __restrict__ vproj,
    const float* __restrict__ memory, const float* __restrict__ norm_m,
    float* __restrict__ memout, float* __restrict__ vdelta)
{
    const int yy = blockIdx.y;
    const bool is_ret = (yy < NH);
    const int h = is_ret ? yy : (yy - NH);
    const int hm = is_ret ? (h & (NKV - 1)) : h;
    const int st = blockIdx.x;
    const int e = threadIdx.x;
    __shared__ float Qs[16][128];
    __shared__ float Ms[32][128];
    __shared__ float Ns[128][33];

    if (is_ret) {
        for (int i = e; i < 16 * 128; i += 128) {
            int r = i >> 7, d = i & 127;
            Qs[r][d] = qn[(size_t)(st * 16 + r) * HID + h * HD + d];
        }
    } else {
        for (int i = e; i < 16 * 128; i += 128) {
            int r = i >> 7, d = i & 127;
            Qs[r][d] = kn[(size_t)(st * 16 + r) * (NKV * HD) + h * HD + d];
        }
    }
    float num[16], den[16];
#pragma unroll
    for (int r = 0; r < 16; r++) { num[r] = 0.f; den[r] = 0.f; }
    const float* M = memory + hm * HD * HD;
    const float* Nm = norm_m + hm * HD * HD;

    for (int d0 = 0; d0 < 128; d0 += 32) {
        __syncthreads();
        for (int i = e; i < 32 * 128; i += 128) {
            int dd = i >> 7, ee = i & 127;
            Ms[dd][ee] = M[(d0 + dd) * HD + ee];
        }
        for (int i = e; i < 128 * 32; i += 128) {
            int ee = i >> 5, dd = i & 31;
            Ns[ee][dd] = Nm[ee * HD + d0 + dd];
        }
        __syncthreads();
#pragma unroll 4
        for (int dd = 0; dd < 32; dd++) {
            float mv = Ms[dd][e];
            float nv = Ns[e][dd];
#pragma unroll
            for (int r = 0; r < 16; r++) {
                float qv = Qs[r][d0 + dd];
                num[r] += qv * mv;
                den[r] += qv * nv;
            }
        }
    }
    if (is_ret) {
#pragma unroll
        for (int r = 0; r < 16; r++)
            memout[(size_t)(st * 16 + r) * HID + h * HD + e] = num[r] / (den[r] + EPS);
    } else {
#pragma unroll
        for (int r = 0; r < 16; r++) {
            size_t idx = (size_t)(st * 16 + r) * (NKV * HD) + h * HD + e;
            vdelta[idx] = vproj[idx] - num[r] / (den[r] + EPS);
        }
    }
}

// ---------------- RoPE + fp16 hi/lo split for Q,K ----------------
__global__ __launch_bounds__(256) void rope_split_kernel(
    const float* __restrict__ q, const float* __restrict__ k, const int* __restrict__ pos,
    __half* __restrict__ qh, __half* __restrict__ ql,
    __half* __restrict__ kh, __half* __restrict__ kl)
{
    const int s = blockIdx.x;
    const int idx = blockIdx.y * 256 + threadIdx.x;
    if (idx >= (NH + NKV) * 64) return;
    const int head = idx >> 6;
    const int d = idx & 63;
    const float p = (float)pos[s];
    const float invf = expf(-(2.0f * (float)d / 128.0f) * LN10000);
    const float a = p * invf;
    const float c = cosf(a), sn = sinf(a);
    const float* base;
    __half *oh, *ol;
    if (head < NH) {
        size_t off = (size_t)s * HID + head * HD;
        base = q + off; oh = qh + off; ol = ql + off;
    } else {
        size_t off = (size_t)s * (NKV * HD) + (head - NH) * HD;
        base = k + off; oh = kh + off; ol = kl + off;
    }
    float x0 = base[d], x1 = base[d + 64];
    float r0 = x0 * c - x1 * sn;
    float r1 = x1 * c + x0 * sn;
    __half h, l;
    h16split(r0, h, l);
    oh[d] = h; ol[d] = l;
    h16split(r1, h, l);
    oh[d + 64] = h; ol[d + 64] = l;
}

// ---------------- V transpose + split ----------------
__global__ __launch_bounds__(256) void vtrans_split_kernel(
    const float* __restrict__ v, __half* __restrict__ vth, __half* __restrict__ vtl)
{
    __shared__ float t[32][33];
    const int bx = blockIdx.x;
    const int by = blockIdx.y;
    const int x = threadIdx.x & 31;
    const int y = threadIdx.x >> 5;
#pragma unroll
    for (int j = 0; j < 4; j++) {
        int sr = y + 8 * j;
        t[sr][x] = v[(size_t)(bx * 32 + sr) * (NKV * HD) + by * 32 + x];
    }
    __syncthreads();
#pragma unroll
    for (int j = 0; j < 4; j++) {
        int cr = y + 8 * j;
        float val = t[x][cr];
        __half h, l;
        h16split(val, h, l);
        size_t idx = (size_t)(by * 32 + cr) * S + bx * 32 + x;
        vth[idx] = h;
        vtl[idx] = l;
    }
}

// ---------------- fp16-split MMA flash attention ----------------
#define QH_STR 136
#define KH_STR 136
#define VT_STR 72
#define PH_STR 72
#define SM_QH 0
#define SM_QL (128 * QH_STR)
#define SM_KH (SM_QL + 128 * QH_STR)
#define SM_KL (SM_KH + 64 * KH_STR)
#define SM_VTH (SM_KL + 64 * KH_STR)
#define SM_VTL (SM_VTH + 128 * VT_STR)
#define SM_PH (SM_VTL + 128 * VT_STR)
#define SM_PL (SM_PH + 128 * PH_STR)
#define ATT2_SMEM_HALVES (SM_PL + 128 * PH_STR)
#define ATT2_SMEM_BYTES (ATT2_SMEM_HALVES * 2)

__global__ __launch_bounds__(256) void attn_f16_kernel(
    const __half* __restrict__ qh, const __half* __restrict__ ql,
    const __half* __restrict__ kh, const __half* __restrict__ kl,
    const __half* __restrict__ vth, const __half* __restrict__ vtl,
    const float* __restrict__ memout, const float* __restrict__ beta,
    __half* __restrict__ ch)
{
    const int h = blockIdx.y;
    const int qt = (int)gridDim.x - 1 - (int)blockIdx.x;
    const int kvh = h >> 2;
    const int tid = threadIdx.x;
    const int warp = tid >> 5;
    const int lane = tid & 31;
    const int lr = lane >> 2;
    const int lc = lane & 3;

    extern __shared__ __half sh[];
    __half* Qh_ = sh + SM_QH;
    __half* Ql_ = sh + SM_QL;
    __half* Kh_ = sh + SM_KH;
    __half* Kl_ = sh + SM_KL;
    __half* Vth_ = sh + SM_VTH;
    __half* Vtl_ = sh + SM_VTL;
    __half* Ph_ = sh + SM_PH;
    __half* Pl_ = sh + SM_PL;

#pragma unroll
    for (int it = 0; it < 8; it++) {
        int i = it * 256 + tid;
        int row = i >> 4, c8 = (i & 15) * 8;
        size_t gidx = (size_t)(qt * 128 + row) * HID + h * HD + c8;
        *(uint4*)(Qh_ + row * QH_STR + c8) = *(const uint4*)(qh + gidx);
        *(uint4*)(Ql_ + row * QH_STR + c8) = *(const uint4*)(ql + gidx);
    }

    const int row0 = warp * 16 + lr;
    const int row1 = row0 + 8;
    const int grow0 = qt * 128 + row0;
    const int grow1 = grow0 + 8;

    float m0 = -1e30f, m1 = -1e30f, l0 = 0.f, l1 = 0.f;
    float o[16][4];
#pragma unroll
    for (int nt = 0; nt < 16; nt++)
#pragma unroll
        for (int r = 0; r < 4; r++) o[nt][r] = 0.f;

    const int ktmax = 2 * qt + 1;
    for (int kt = 0; kt <= ktmax; kt++) {
        __syncthreads();
#pragma unroll
        for (int it = 0; it < 4; it++) {
            int i = it * 256 + tid;
            int key = i >> 4, c8 = (i & 15) * 8;
            size_t gidx = (size_t)(kt * 64 + key) * (NKV * HD) + kvh * HD + c8;
            *(uint4*)(Kh_ + key * KH_STR + c8) = *(const uint4*)(kh + gidx);
            *(uint4*)(Kl_ + key * KH_STR + c8) = *(const uint4*)(kl + gidx);
        }
#pragma unroll
        for (int it = 0; it < 4; it++) {
            int i = it * 256 + tid;
            int dr = i >> 3, kc = (i & 7) * 8;
            size_t gidx = (size_t)(kvh * HD + dr) * S + kt * 64 + kc;
            *(uint4*)(Vth_ + dr * VT_STR + kc) = *(const uint4*)(vth + gidx);
            *(uint4*)(Vtl_ + dr * VT_STR + kc) = *(const uint4*)(vtl + gidx);
        }
        __syncthreads();

        float sc[8][4];
#pragma unroll
        for (int nt = 0; nt < 8; nt++)
#pragma unroll
            for (int r = 0; r < 4; r++) sc[nt][r] = 0.f;

#pragma unroll
        for (int ks = 0; ks < 8; ks++) {
            const int kb = ks * 16;
            uint32_t ah[4], al[4];
            {
                const __half* p0 = Qh_ + row0 * QH_STR + kb + 2 * lc;
                const __half* p1 = Qh_ + row1 * QH_STR + kb + 2 * lc;
                ah[0] = *(const uint32_t*)(p0);
                ah[1] = *(const uint32_t*)(p1);
                ah[2] = *(const uint32_t*)(p0 + 8);
                ah[3] = *(const uint32_t*)(p1 + 8);
                const __half* q0 = Ql_ + row0 * QH_STR + kb + 2 * lc;
                const __half* q1 = Ql_ + row1 * QH_STR + kb + 2 * lc;
                al[0] = *(const uint32_t*)(q0);
                al[1] = *(const uint32_t*)(q1);
                al[2] = *(const uint32_t*)(q0 + 8);
                al[3] = *(const uint32_t*)(q1 + 8);
            }
#pragma unroll
            for (int nt = 0; nt < 8; nt++) {
                const int n0 = nt * 8 + lr;
                const __half* ph = Kh_ + n0 * KH_STR + kb + 2 * lc;
                const __half* pl = Kl_ + n0 * KH_STR + kb + 2 * lc;
                uint32_t bh0 = *(const uint32_t*)(ph);
                uint32_t bh1 = *(const uint32_t*)(ph + 8);
                uint32_t bl0 = *(const uint32_t*)(pl);
                uint32_t bl1 = *(const uint32_t*)(pl + 8);
                mma_f16(sc[nt][0], sc[nt][1], sc[nt][2], sc[nt][3],
                        ah[0], ah[1], ah[2], ah[3], bh0, bh1);
                mma_f16(sc[nt][0], sc[nt][1], sc[nt][2], sc[nt][3],
                        ah[0], ah[1], ah[2], ah[3], bl0, bl1);
                mma_f16(sc[nt][0], sc[nt][1], sc[nt][2], sc[nt][3],
                        al[0], al[1], al[2], al[3], bh0, bh1);
            }
        }

        const bool need_mask = (kt >= 2 * qt);
        float mx0 = -1e30f, mx1 = -1e30f;
#pragma unroll
        for (int nt = 0; nt < 8; nt++) {
#pragma unroll
            for (int j = 0; j < 2; j++) {
                int col = kt * 64 + nt * 8 + 2 * lc + j;
                float s0 = sc[nt][j] * ATT_SCALE;
                float s1 = sc[nt][2 + j] * ATT_SCALE;
                if (need_mask) {
                    if (col > grow0) s0 = -1e30f;
                    if (col > grow1) s1 = -1e30f;
                }
                sc[nt][j] = s0;
                sc[nt][2 + j] = s1;
                mx0 = fmaxf(mx0, s0);
                mx1 = fmaxf(mx1, s1);
            }
        }
        mx0 = fmaxf(mx0, __shfl_xor_sync(0xffffffffu, mx0, 1));
        mx0 = fmaxf(mx0, __shfl_xor_sync(0xffffffffu, mx0, 2));
        mx1 = fmaxf(mx1, __shfl_xor_sync(0xffffffffu, mx1, 1));
        mx1 = fmaxf(mx1, __shfl_xor_sync(0xffffffffu, mx1, 2));
        const float mn0 = fmaxf(m0, mx0);
        const float mn1 = fmaxf(m1, mx1);
        const float scl0 = __expf(m0 - mn0);
        const float scl1 = __expf(m1 - mn1);
        float ls0 = 0.f, ls1 = 0.f;
#pragma unroll
        for (int nt = 0; nt < 8; nt++) {
            float p00 = __expf(sc[nt][0] - mn0);
            float p01 = __expf(sc[nt][1] - mn0);
            float p10 = __expf(sc[nt][2] - mn1);
            float p11 = __expf(sc[nt][3] - mn1);
            ls0 += p00 + p01;
            ls1 += p10 + p11;
            __half h0, l0h, h1, l1h;
            h16split(p00, h0, l0h);
            h16split(p01, h1, l1h);
            *(uint32_t*)(Ph_ + row0 * PH_STR + nt * 8 + 2 * lc) =
                (uint32_t)__half_as_ushort(h0) | ((uint32_t)__half_as_ushort(h1) << 16);
            *(uint32_t*)(Pl_ + row0 * PH_STR + nt * 8 + 2 * lc) =
                (uint32_t)__half_as_ushort(l0h) | ((uint32_t)__half_as_ushort(l1h) << 16);
            h16split(p10, h0, l0h);
            h16split(p11, h1, l1h);
            *(uint32_t*)(Ph_ + row1 * PH_STR + nt * 8 + 2 * lc) =
                (uint32_t)__half_as_ushort(h0) | ((uint32_t)__half_as_ushort(h1) << 16);
            *(uint32_t*)(Pl_ + row1 * PH_STR + nt * 8 + 2 * lc) =
                (uint32_t)__half_as_ushort(l0h) | ((uint32_t)__half_as_ushort(l1h) << 16);
        }
        ls0 += __shfl_xor_sync(0xffffffffu, ls0, 1);
        ls0 += __shfl_xor_sync(0xffffffffu, ls0, 2);
        ls1 += __shfl_xor_sync(0xffffffffu, ls1, 1);
        ls1 += __shfl_xor_sync(0xffffffffu, ls1, 2);
        l0 = l0 * scl0 + ls0;
        l1 = l1 * scl1 + ls1;
        m0 = mn0;
        m1 = mn1;

#pragma unroll
        for (int nt = 0; nt < 16; nt++) {
            o[nt][0] *= scl0;
            o[nt][1] *= scl0;
            o[nt][2] *= scl1;
            o[nt][3] *= scl1;
        }
        __syncwarp();

#pragma unroll
        for (int ks2 = 0; ks2 < 4; ks2++) {
            const int kb = ks2 * 16;
            uint32_t ah[4], al[4];
            {
                const __half* p0 = Ph_ + row0 * PH_STR + kb + 2 * lc;
                const __half* p1 = Ph_ + row1 * PH_STR + kb + 2 * lc;
                ah[0] = *(const uint32_t*)(p0);
                ah[1] = *(const uint32_t*)(p1);
                ah[2] = *(const uint32_t*)(p0 + 8);
                ah[3] = *(const uint32_t*)(p1 + 8);
                const __half* q0 = Pl_ + row0 * PH_STR + kb + 2 * lc;
                const __half* q1 = Pl_ + row1 * PH_STR + kb + 2 * lc;
                al[0] = *(const uint32_t*)(q0);
                al[1] = *(const uint32_t*)(q1);
                al[2] = *(const uint32_t*)(q0 + 8);
                al[3] = *(const uint32_t*)(q1 + 8);
            }
#pragma unroll
            for (int nt = 0; nt < 16; nt++) {
                const int n0 = nt * 8 + lr;
                const __half* ph = Vth_ + n0 * VT_STR + kb + 2 * lc;
                const __half* pl = Vtl_ + n0 * VT_STR + kb + 2 * lc;
                uint32_t bh0 = *(const uint32_t*)(ph);
                uint32_t bh1 = *(const uint32_t*)(ph + 8);
                uint32_t bl0 = *(const uint32_t*)(pl);
                uint32_t bl1 = *(const uint32_t*)(pl + 8);
                mma_f16(o[nt][0], o[nt][1], o[nt][2], o[nt][3],
                        ah[0], ah[1], ah[2], ah[3], bh0, bh1);
                mma_f16(o[nt][0], o[nt][1], o[nt][2], o[nt][3],
                        ah[0], ah[1], ah[2], ah[3], bl0, bl1);
                mma_f16(o[nt][0], o[nt][1], o[nt][2], o[nt][3],
                        al[0], al[1], al[2], al[3], bh0, bh1);
            }
        }
    }

    // epilogue: gate-combine, emit fp16
    const float g = 1.f / (1.f + __expf(-beta[0]));
    const float og = 1.f - g;
    const float li0 = 1.f / l0;
    const float li1 = 1.f / l1;
#pragma unroll
    for (int nt = 0; nt < 16; nt++) {
        const int col = nt * 8 + 2 * lc;
        size_t i0 = (size_t)grow0 * HID + h * HD + col;
        size_t i1 = (size_t)grow1 * HID + h * HD + col;
        float2 mo0 = *(const float2*)(memout + i0);
        float2 mo1 = *(const float2*)(memout + i1);
        *(uint32_t*)(ch + i0) = h2pack(g * mo0.x + og * (o[nt][0] * li0),
                                       g * mo0.y + og * (o[nt][1] * li0));
        *(uint32_t*)(ch + i1) = h2pack(g * mo1.x + og * (o[nt][2] * li1),
                                       g * mo1.y + og * (o[nt][3] * li1));
    }
}

// ---------------- delta-rule partials ----------------
__global__ __launch_bounds__(256) void delta_part_kernel(
    const float* __restrict__ kn, const float* __restrict__ vd, float* __restrict__ part)
{
    const int h = blockIdx.x;
    const int c = blockIdx.y;
    __shared__ float Ak[32][128];
    __shared__ float Bv[32][128];
    const int trow = (threadIdx.x >> 4) * 8;
    const int tcol = (threadIdx.x & 15) * 8;
    float acc[8][8];
#pragma unroll
    for (int i = 0; i < 8; i++)
#pragma unroll
        for (int j = 0; j < 8; j++) acc[i][j] = 0.f;

    const int sbeg = c * 256;
    for (int s0 = sbeg; s0 < sbeg + 256; s0 += 32) {
        for (int i = threadIdx.x; i < 32 * 128; i += 256) {
            int ss = i >> 7, dd = i & 127;
            size_t idx = (size_t)(s0 + ss) * (NKV * HD) + h * HD + dd;
            Ak[ss][dd] = kn[idx];
            Bv[ss][dd] = vd[idx];
        }
        __syncthreads();
#pragma unroll 4
        for (int ss = 0; ss < 32; ss++) {
            float ra[8], rb[8];
#pragma unroll
            for (int i = 0; i < 8; i++) ra[i] = Ak[ss][trow + i];
#pragma unroll
            for (int j = 0; j < 8; j++) rb[j] = Bv[ss][tcol + j];
#pragma unroll
            for (int i = 0; i < 8; i++)
#pragma unroll
                for (int j = 0; j < 8; j++) acc[i][j] += ra[i] * rb[j];
        }
        __syncthreads();
    }
    float* Ph = part + (size_t)c * (NKV * HD * HD) + h * HD * HD;
#pragma unroll
    for (int i = 0; i < 8; i++)
#pragma unroll
        for (int j = 0; j < 8; j++)
            Ph[(trow + i) * HD + tcol + j] = acc[i][j];
}

// fused memory-update + norm-update (same index space)
__global__ __launch_bounds__(256) void finalize_kernel(
    const float* __restrict__ part, const float* __restrict__ memory,
    const float* __restrict__ norm_m, const float* __restrict__ knsum,
    float* __restrict__ outmem, float* __restrict__ outnorm)
{
    const int i = blockIdx.x * 256 + threadIdx.x;   // < NKV*HD*HD
    float acc = memory[i];
#pragma unroll
    for (int c = 0; c < 8; c++) acc += part[(size_t)c * (NKV * HD * HD) + i];
    outmem[i] = acc;
    const int h = i >> 14;
    const int j = i & 127;
    outnorm[i] = norm_m[i] + knsum[h * HD + j];
}

// ---------------- launch ----------------
extern "C" void kernel_launch(void* const* d_in, const int* in_sizes, int n_in,
                              void* d_out, int out_size)
{
    const float* hidden = (const float*)d_in[0];
    const int*   pos    = (const int*)d_in[1];
    const float* wq     = (const float*)d_in[2];
    const float* wk     = (const float*)d_in[3];
    const float* wv     = (const float*)d_in[4];
    const float* wo     = (const float*)d_in[5];
    const float* memory = (const float*)d_in[6];
    const float* norm_m = (const float*)d_in[7];
    const float* beta   = (const float*)d_in[8];
    float* out = (float*)d_out;

    float *qproj, *kproj, *vproj, *qn, *kn, *memout, *vdelta, *knsum, *knpart, *dpart;
    __half *hh, *wqT, *wkT, *wvT, *woT, *ch, *qh, *ql, *kh, *kl, *vth, *vtl;
    cudaGetSymbolAddress((void**)&qproj, g_qproj);
    cudaGetSymbolAddress((void**)&kproj, g_kproj);
    cudaGetSymbolAddress((void**)&vproj, g_vproj);
    cudaGetSymbolAddress((void**)&qn, g_qn);
    cudaGetSymbolAddress((void**)&kn, g_kn);
    cudaGetSymbolAddress((void**)&memout, g_memout);
    cudaGetSymbolAddress((void**)&vdelta, g_vdelta);
    cudaGetSymbolAddress((void**)&knsum, g_knsum);
    cudaGetSymbolAddress((void**)&knpart, g_knsum_part);
    cudaGetSymbolAddress((void**)&dpart, g_delta_part);
    cudaGetSymbolAddress((void**)&hh, g_hh);
    cudaGetSymbolAddress((void**)&wqT, g_wqT);
    cudaGetSymbolAddress((void**)&wkT, g_wkT);
    cudaGetSymbolAddress((void**)&wvT, g_wvT);
    cudaGetSymbolAddress((void**)&woT, g_woT);
    cudaGetSymbolAddress((void**)&ch, g_ch);
    cudaGetSymbolAddress((void**)&qh, g_qh);
    cudaGetSymbolAddress((void**)&ql, g_ql);
    cudaGetSymbolAddress((void**)&kh, g_kh);
    cudaGetSymbolAddress((void**)&kl, g_kl);
    cudaGetSymbolAddress((void**)&vth, g_vth);
    cudaGetSymbolAddress((void**)&vtl, g_vtl);

    cudaFuncSetAttribute(attn_f16_kernel,
                         cudaFuncAttributeMaxDynamicSharedMemorySize, ATT2_SMEM_BYTES);
    cudaFuncSetAttribute(gemm_f16_kernel,
                         cudaFuncAttributeMaxDynamicSharedMemorySize, GEMM4_SMEM);

    // pre-pass: hidden -> fp16; all four weight transposes in ONE launch
    h2h_kernel<<<1024, 256>>>(hidden, hh, S * HID / 4);
    wtrans4_kernel<<<dim3(HID / 32, HID / 32, 4), 256>>>(
        wq, wqT, wk, wkT, wv, wvT, wo, woT);

    // projections (fp16 m16n8k16 + ldmatrix, 3-stage). z=0: Q; z=1: bx<8 K, bx<16 V.
    gemm_f16_kernel<<<dim3(HID / 128, S / 128, 2), 128, GEMM4_SMEM>>>(
        hh, wqT, qproj, HID, wkT, kproj, wvT, vproj, NKV * HD, HID);

    // normalized features from PRE-RoPE q/k (warp-per-head, barrier-free)
    qn2_kernel<<<S, 256>>>(qproj, qn);
    kn2_kernel<<<S, 256>>>(kproj, kn);
    knsum_part_kernel<<<dim3(NKV, 16), 128>>>(kn, knpart);
    knsum_final_kernel<<<1, 1024>>>(knpart, knsum);

    // compressive-memory retrieval + delta-rule prep in ONE launch
    memops_kernel<<<dim3(S / 16, NH + NKV), 128>>>(
        qn, kn, vproj, memory, norm_m, memout, vdelta);

    // RoPE + fp16 hi/lo split; V transpose + split
    rope_split_kernel<<<dim3(S, 10), 256>>>(qproj, kproj, pos, qh, ql, kh, kl);
    vtrans_split_kernel<<<dim3(S / 32, NKV * HD / 32), 256>>>(vproj, vth, vtl);

    // fp16-split flash attention (fuses gated combine, emits fp16 combined)
    attn_f16_kernel<<<dim3(S / 128, NH), 256, ATT2_SMEM_BYTES>>>(
        qh, ql, kh, kl, vth, vtl, memout, beta, ch);

    // output projection (fp16)
    gemm_f16_kernel<<<dim3(HID / 128, S / 128, 1), 128, GEMM4_SMEM>>>(
        ch, woT, out, HID, woT, out, woT, out, HID, HID);

    // memory & norm updates (fused; appended after the 8.4M-element `out`)
    delta_part_kernel<<<dim3(NKV, 8), 256>>>(kn, vdelta, dpart);
    finalize_kernel<<<(NKV * HD * HD) / 256, 256>>>(
        dpart, memory, norm_m, knsum,
        out + (size_t)S * HID, out + (size_t)S * HID + NKV * HD * HD);
}

// round 16
// speedup vs baseline: 1.8893x; 1.0694x over previous
#include <cuda_runtime.h>
#include <cuda_fp16.h>
#include <math.h>
#include <stdint.h>

// ---------------- problem constants ----------------
#define S 2048
#define HID 4096
#define NH 32
#define NKV 8
#define HD 128
#define GROUPS 4
#define EPS 1e-8f
#define ATT_SCALE 0.08838834764831845f   // 128^-0.5
#define LN10000 9.210340371976184f

// ---------------- scratch (device globals; no allocation allowed) ----------------
__device__ float g_qproj[S * HID];
__device__ float g_kproj[S * NKV * HD];
__device__ float g_vproj[S * NKV * HD];
__device__ float g_qn[S * HID];
__device__ float g_kn[S * NKV * HD];
__device__ float g_memout[S * HID];
__device__ float g_vdelta[S * NKV * HD];
__device__ float g_knsum[NKV * HD];
__device__ float g_knsum_part[16][NKV * HD];
__device__ float g_delta_part[8][NKV * HD * HD];
// fp16 GEMM operands
__device__ __half g_hh[S * HID];             // hidden, [M][K]
__device__ __half g_wqT[HID * HID];          // [N][K]
__device__ __half g_wkT[NKV * HD * HID];
__device__ __half g_wvT[NKV * HD * HID];
__device__ __half g_woT[HID * HID];
__device__ __half g_ch[S * HID];             // combined (attention out), [M][K]
// fp16 planes for attention (Q single-precision fp16; K/V hi+lo)
__device__ __half g_qh[S * HID];
__device__ __half g_kh[S * NKV * HD];
__device__ __half g_kl[S * NKV * HD];
__device__ __half g_vth[NKV * HD * S];       // V^T hi: [h*HD+d][s]
__device__ __half g_vtl[NKV * HD * S];

// ---------------- fp16 mma + ldmatrix ----------------
__device__ __forceinline__ void mma_f16(
    float& c0, float& c1, float& c2, float& c3,
    uint32_t a0, uint32_t a1, uint32_t a2, uint32_t a3,
    uint32_t b0, uint32_t b1)
{
    asm volatile(
        "mma.sync.aligned.m16n8k16.row.col.f32.f16.f16.f32 "
        "{%0,%1,%2,%3},{%4,%5,%6,%7},{%8,%9},{%0,%1,%2,%3};"
        : "+f"(c0), "+f"(c1), "+f"(c2), "+f"(c3)
        : "r"(a0), "r"(a1), "r"(a2), "r"(a3), "r"(b0), "r"(b1));
}

#define LDSM4(r0, r1, r2, r3, addr) \
    asm volatile("ldmatrix.sync.aligned.m8n8.x4.shared.b16 {%0,%1,%2,%3}, [%4];" \
                 : "=r"(r0), "=r"(r1), "=r"(r2), "=r"(r3) : "r"(addr))

__device__ __forceinline__ uint32_t h2pack(float a, float b) {
    __half2 h = __floats2half2_rn(a, b);
    return *(uint32_t*)&h;
}
__device__ __forceinline__ void h16split(float x, __half& h, __half& l) {
    h = __float2half_rn(x);
    l = __float2half_rn(x - __half2float(h));
}

// ---------------- pre-pass: fp32 -> fp16 ----------------
__global__ __launch_bounds__(256) void h2h_kernel(
    const float* __restrict__ src, __half* __restrict__ dst, int n4)
{
    for (int i = blockIdx.x * 256 + threadIdx.x; i < n4; i += gridDim.x * 256) {
        float4 v = ((const float4*)src)[i];
        uint2 p = make_uint2(h2pack(v.x, v.y), h2pack(v.z, v.w));
        ((uint2*)dst)[i] = p;
    }
}

// transpose all four weights in ONE launch: z selects the matrix.
__global__ __launch_bounds__(256) void wtrans4_kernel(
    const float* __restrict__ wq, __half* __restrict__ wqt,
    const float* __restrict__ wk, __half* __restrict__ wkt,
    const float* __restrict__ wv, __half* __restrict__ wvt,
    const float* __restrict__ wo, __half* __restrict__ wot)
{
    const float* w;
    __half* wt;
    int Nd;
    switch (blockIdx.z) {
        case 0: w = wq; wt = wqt; Nd = HID; break;
        case 1: w = wk; wt = wkt; Nd = NKV * HD; break;
        case 2: w = wv; wt = wvt; Nd = NKV * HD; break;
        default: w = wo; wt = wot; Nd = HID; break;
    }
    const int bx = blockIdx.x;       // N tile
    if (bx * 32 >= Nd) return;
    const int by = blockIdx.y;       // K tile
    __shared__ float t[32][33];
    const int x = threadIdx.x & 31;
    const int y = threadIdx.x >> 5;
#pragma unroll
    for (int j = 0; j < 4; j++) {
        int kr = y + 8 * j;
        t[kr][x] = w[(size_t)(by * 32 + kr) * Nd + bx * 32 + x];
    }
    __syncthreads();
#pragma unroll
    for (int j = 0; j < 4; j++) {
        int nr = y + 8 * j;
        wt[(size_t)(bx * 32 + nr) * HID + by * 32 + x] = __float2half_rn(t[x][nr]);
    }
}

// ---------------- GEMM: fp16 m16n8k16 + ldmatrix, 4 warps, 64x64 warp tile, BK=32, 3-stage ----------------
#define HAS_STR 40
#define HBS_STR 40
#define STG4_BYTES ((128 * HAS_STR + 128 * HBS_STR) * 2)   // 20480
#define GEMM4_SMEM (3 * STG4_BYTES)                        // 61440

#define CP16(dst_u32, src_ptr) \
    asm volatile("cp.async.cg.shared.global [%0], [%1], 16;" :: "r"(dst_u32), "l"(src_ptr))

__global__ __launch_bounds__(128, 2) void gemm_f16_kernel(
    const __half* __restrict__ A,
    const __half* __restrict__ B0, float* __restrict__ C0, int N0,
    const __half* __restrict__ B1, float* __restrict__ C1,
    const __half* __restrict__ B2, float* __restrict__ C2, int N12,
    int K)
{
    const __half* Bt;
    float* C;
    int N, bx;
    if (blockIdx.z == 0) {
        Bt = B0; C = C0; N = N0; bx = blockIdx.x;
        if (bx * 128 >= N0) return;
    } else {
        N = N12;
        const int nt12 = N12 / 128;
        if ((int)blockIdx.x < nt12) { Bt = B1; C = C1; bx = blockIdx.x; }
        else if ((int)blockIdx.x < 2 * nt12) { Bt = B2; C = C2; bx = blockIdx.x - nt12; }
        else return;
    }

    extern __shared__ __half smh[];
    const uint32_t smu = (uint32_t)__cvta_generic_to_shared(smh);

    const int tid = threadIdx.x;
    const int lane = tid & 31;
    const int wid = tid >> 5;
    const int wm = wid >> 1;
    const int wn = wid & 1;
    const int lr = lane >> 2;
    const int lc = lane & 3;
    const int by = blockIdx.y;

    const int crow = tid >> 2;
    const int cchk = (tid & 3) * 8;

    const __half* Ab = A + (size_t)(by * 128) * K;
    const __half* Bb = Bt + (size_t)(bx * 128) * K;

    const uint32_t a_lane_off =
        (uint32_t)(((lane & 15) * HAS_STR + ((lane >> 4) << 3)) * 2);
    const uint32_t b_lane_off =
        (uint32_t)((((lane & 7) + ((lane >> 4) << 3)) * HBS_STR + (((lane >> 3) & 1) << 3)) * 2);

    float acc[4][8][4];
#pragma unroll
    for (int i = 0; i < 4; i++)
#pragma unroll
        for (int j = 0; j < 8; j++)
#pragma unroll
            for (int r = 0; r < 4; r++) acc[i][j][r] = 0.f;

    const int NT = K / 32;

#define LOAD_STAGE(stg, ch)                                                           \
    {                                                                                 \
        const uint32_t sb = smu + (uint32_t)((stg) * STG4_BYTES);                     \
        const int k0 = (ch) * 32;                                                     \
        _Pragma("unroll")                                                             \
        for (int i = 0; i < 4; i++) {                                                 \
            const int r = i * 32 + crow;                                              \
            CP16(sb + (uint32_t)((r * HAS_STR + cchk) * 2), Ab + (size_t)r * K + k0 + cchk); \
        }                                                                             \
        _Pragma("unroll")                                                             \
        for (int i = 0; i < 4; i++) {                                                 \
            const int r = i * 32 + crow;                                              \
            CP16(sb + (uint32_t)((128 * HAS_STR + r * HBS_STR + cchk) * 2),           \
                 Bb + (size_t)r * K + k0 + cchk);                                     \
        }                                                                             \
    }

    LOAD_STAGE(0, 0)
    asm volatile("cp.async.commit_group;" ::: "memory");
    LOAD_STAGE(1, 1)
    asm volatile("cp.async.commit_group;" ::: "memory");

    int stage = 0;
    for (int it = 0; it < NT; it++) {
        asm volatile("cp.async.wait_group 1;" ::: "memory");
        __syncthreads();

        const int pf = it + 2;
        if (pf < NT) {
            const int ps = (stage + 2) % 3;
            LOAD_STAGE(ps, pf)
        }
        asm volatile("cp.async.commit_group;" ::: "memory");

        const uint32_t sbA = smu + (uint32_t)(stage * STG4_BYTES);
        const uint32_t sbB = sbA + (uint32_t)(128 * HAS_STR * 2);

#pragma unroll
        for (int ks = 0; ks < 2; ks++) {
            const uint32_t kbB = (uint32_t)(ks * 16 * 2);
            uint32_t af[4][4], bf[8][2];
#pragma unroll
            for (int mt = 0; mt < 4; mt++) {
                const uint32_t addr = sbA
                    + (uint32_t)(((wm * 64 + mt * 16) * HAS_STR) * 2)
                    + a_lane_off + kbB;
                LDSM4(af[mt][0], af[mt][1], af[mt][2], af[mt][3], addr);
            }
#pragma unroll
            for (int ntp = 0; ntp < 4; ntp++) {
                const uint32_t addr = sbB
                    + (uint32_t)(((wn * 64 + ntp * 16) * HBS_STR) * 2)
                    + b_lane_off + kbB;
                LDSM4(bf[2 * ntp][0], bf[2 * ntp][1], bf[2 * ntp + 1][0], bf[2 * ntp + 1][1], addr);
            }
#pragma unroll
            for (int mt = 0; mt < 4; mt++)
#pragma unroll
                for (int nt = 0; nt < 8; nt++)
                    mma_f16(acc[mt][nt][0], acc[mt][nt][1], acc[mt][nt][2], acc[mt][nt][3],
                            af[mt][0], af[mt][1], af[mt][2], af[mt][3],
                            bf[nt][0], bf[nt][1]);
        }
        stage = (stage + 1) % 3;
    }
#undef LOAD_STAGE

#pragma unroll
    for (int mt = 0; mt < 4; mt++) {
        const int row = by * 128 + wm * 64 + mt * 16 + lr;
#pragma unroll
        for (int nt = 0; nt < 8; nt++) {
            const int col = bx * 128 + wn * 64 + nt * 8 + lc * 2;
            float2 v01 = make_float2(acc[mt][nt][0], acc[mt][nt][1]);
            float2 v23 = make_float2(acc[mt][nt][2], acc[mt][nt][3]);
            *(float2*)(C + (size_t)row * N + col) = v01;
            *(float2*)(C + (size_t)(row + 8) * N + col) = v23;
        }
    }
}

// ---------------- qn / kn: warp-per-head, no block barriers ----------------
__global__ __launch_bounds__(256) void qn2_kernel(const float* __restrict__ qp, float* __restrict__ qn)
{
    const int s = blockIdx.x;
    const int warp = threadIdx.x >> 5;
    const int lane = threadIdx.x & 31;
    for (int h = warp; h < NH; h += 8) {
        const float* src = qp + (size_t)s * HID + h * HD;
        float4 v = ((const float4*)src)[lane];
        float4 f;
        f.x = v.x > 0.f ? v.x + 1.f : __expf(v.x);
        f.y = v.y > 0.f ? v.y + 1.f : __expf(v.y);
        f.z = v.z > 0.f ? v.z + 1.f : __expf(v.z);
        f.w = v.w > 0.f ? v.w + 1.f : __expf(v.w);
        float t = f.x + f.y + f.z + f.w;
#pragma unroll
        for (int o = 16; o; o >>= 1) t += __shfl_xor_sync(0xffffffffu, t, o);
        const float inv = 1.f / (t + EPS);
        float4 r = make_float4(f.x * inv, f.y * inv, f.z * inv, f.w * inv);
        ((float4*)(qn + (size_t)s * HID + h * HD))[lane] = r;
    }
}

__global__ __launch_bounds__(256) void kn2_kernel(const float* __restrict__ kp, float* __restrict__ kn)
{
    const int s = blockIdx.x;
    const int warp = threadIdx.x >> 5;
    const int lane = threadIdx.x & 31;
    if (warp >= NKV) return;
    const float* src = kp + (size_t)s * (NKV * HD) + warp * HD;
    float4 v = ((const float4*)src)[lane];
    float4 f;
    f.x = v.x > 0.f ? v.x + 1.f : __expf(v.x);
    f.y = v.y > 0.f ? v.y + 1.f : __expf(v.y);
    f.z = v.z > 0.f ? v.z + 1.f : __expf(v.z);
    f.w = v.w > 0.f ? v.w + 1.f : __expf(v.w);
    float t = f.x + f.y + f.z + f.w;
#pragma unroll
    for (int o = 16; o; o >>= 1) t += __shfl_xor_sync(0xffffffffu, t, o);
    const float inv = 1.f / (t + EPS);
    float4 r = make_float4(f.x * inv, f.y * inv, f.z * inv, f.w * inv);
    ((float4*)(kn + (size_t)s * (NKV * HD) + warp * HD))[lane] = r;
}

__global__ __launch_bounds__(128) void knsum_part_kernel(const float* __restrict__ kn, float* __restrict__ part)
{
    const int h = blockIdx.x;
    const int p = blockIdx.y;
    const int d = threadIdx.x;
    float acc = 0.f;
    const int s0 = p * 128;
#pragma unroll 4
    for (int s = s0; s < s0 + 128; s++)
        acc += kn[(size_t)s * (NKV * HD) + h * HD + d];
    part[p * (NKV * HD) + h * HD + d] = acc;
}

__global__ __launch_bounds__(1024) void knsum_final_kernel(const float* __restrict__ part, float* __restrict__ knsum)
{
    const int i = threadIdx.x;
    float acc = 0.f;
#pragma unroll
    for (int p = 0; p < 16; p++) acc += part[p * (NKV * HD) + i];
    knsum[i] = acc;
}

// ---------------- merged retrieval + vdelta ----------------
__global__ __launch_bounds__(128) void memops_kernel(
    const float* __restrict__ qn, const float* __restrict__ kn,
    const float* __restrict__ vproj,
    const float* __restrict__ memory, const float* __restrict__ norm_m,
    float* __restrict__ memout, float* __restrict__ vdelta)
{
    const int yy = blockIdx.y;
    const bool is_ret = (yy < NH);
    const int h = is_ret ? yy : (yy - NH);
    const int hm = is_ret ? (h & (NKV - 1)) : h;
    const int st = blockIdx.x;
    const int e = threadIdx.x;
    __shared__ float Qs[16][128];
    __shared__ float Ms[32][128];
    __shared__ float Ns[128][33];

    if (is_ret) {
        for (int i = e; i < 16 * 128; i += 128) {
            int r = i >> 7, d = i & 127;
            Qs[r][d] = qn[(size_t)(st * 16 + r) * HID + h * HD + d];
        }
    } else {
        for (int i = e; i < 16 * 128; i += 128) {
            int r = i >> 7, d = i & 127;
            Qs[r][d] = kn[(size_t)(st * 16 + r) * (NKV * HD) + h * HD + d];
        }
    }
    float num[16], den[16];
#pragma unroll
    for (int r = 0; r < 16; r++) { num[r] = 0.f; den[r] = 0.f; }
    const float* M = memory + hm * HD * HD;
    const float* Nm = norm_m + hm * HD * HD;

    for (int d0 = 0; d0 < 128; d0 += 32) {
        __syncthreads();
        for (int i = e; i < 32 * 128; i += 128) {
            int dd = i >> 7, ee = i & 127;
            Ms[dd][ee] = M[(d0 + dd) * HD + ee];
        }
        for (int i = e; i < 128 * 32; i += 128) {
            int ee = i >> 5, dd = i & 31;
            Ns[ee][dd] = Nm[ee * HD + d0 + dd];
        }
        __syncthreads();
#pragma unroll 4
        for (int dd = 0; dd < 32; dd++) {
            float mv = Ms[dd][e];
            float nv = Ns[e][dd];
#pragma unroll
            for (int r = 0; r < 16; r++) {
                float qv = Qs[r][d0 + dd];
                num[r] += qv * mv;
                den[r] += qv * nv;
            }
        }
    }
    if (is_ret) {
#pragma unroll
        for (int r = 0; r < 16; r++)
            memout[(size_t)(st * 16 + r) * HID + h * HD + e] = num[r] / (den[r] + EPS);
    } else {
#pragma unroll
        for (int r = 0; r < 16; r++) {
            size_t idx = (size_t)(st * 16 + r) * (NKV * HD) + h * HD + e;
            vdelta[idx] = vproj[idx] - num[r] / (den[r] + EPS);
        }
    }
}

// ---------------- RoPE + fp16 split: Q single-plane, K hi/lo ----------------
__global__ __launch_bounds__(256) void rope_split_kernel(
    const float* __restrict__ q, const float* __restrict__ k, const int* __restrict__ pos,
    __half* __restrict__ qh,
    __half* __restrict__ kh, __half* __restrict__ kl)
{
    const int s = blockIdx.x;
    const int idx = blockIdx.y * 256 + threadIdx.x;
    if (idx >= (NH + NKV) * 64) return;
    const int head = idx >> 6;
    const int d = idx & 63;
    const float p = (float)pos[s];
    const float invf = expf(-(2.0f * (float)d / 128.0f) * LN10000);
    const float a = p * invf;
    const float c = cosf(a), sn = sinf(a);
    if (head < NH) {
        size_t off = (size_t)s * HID + head * HD;
        const float* base = q + off;
        float x0 = base[d], x1 = base[d + 64];
        qh[off + d]      = __float2half_rn(x0 * c - x1 * sn);
        qh[off + d + 64] = __float2half_rn(x1 * c + x0 * sn);
    } else {
        size_t off = (size_t)s * (NKV * HD) + (head - NH) * HD;
        const float* base = k + off;
        float x0 = base[d], x1 = base[d + 64];
        float r0 = x0 * c - x1 * sn;
        float r1 = x1 * c + x0 * sn;
        __half h, l;
        h16split(r0, h, l);
        kh[off + d] = h; kl[off + d] = l;
        h16split(r1, h, l);
        kh[off + d + 64] = h; kl[off + d + 64] = l;
    }
}

// ---------------- V transpose + split ----------------
__global__ __launch_bounds__(256) void vtrans_split_kernel(
    const float* __restrict__ v, __half* __restrict__ vth, __half* __restrict__ vtl)
{
    __shared__ float t[32][33];
    const int bx = blockIdx.x;
    const int by = blockIdx.y;
    const int x = threadIdx.x & 31;
    const int y = threadIdx.x >> 5;
#pragma unroll
    for (int j = 0; j < 4; j++) {
        int sr = y + 8 * j;
        t[sr][x] = v[(size_t)(bx * 32 + sr) * (NKV * HD) + by * 32 + x];
    }
    __syncthreads();
#pragma unroll
    for (int j = 0; j < 4; j++) {
        int cr = y + 8 * j;
        float val = t[x][cr];
        __half h, l;
        h16split(val, h, l);
        size_t idx = (size_t)(by * 32 + cr) * S + bx * 32 + x;
        vth[idx] = h;
        vtl[idx] = l;
    }
}

// ---------------- fp16 MMA flash attention: Q/P single fp16, K/V 2-split ----------------
#define QH_STR 136
#define KH_STR 136
#define VT_STR 72
#define PH_STR 72
#define SM_QH 0
#define SM_KH (128 * QH_STR)
#define SM_KL (SM_KH + 64 * KH_STR)
#define SM_VTH (SM_KL + 64 * KH_STR)
#define SM_VTL (SM_VTH + 128 * VT_STR)
#define SM_PH (SM_VTL + 128 * VT_STR)
#define ATT2_SMEM_HALVES (SM_PH + 128 * PH_STR)
#define ATT2_SMEM_BYTES (ATT2_SMEM_HALVES * 2)   // 124928

__global__ __launch_bounds__(256) void attn_f16_kernel(
    const __half* __restrict__ qh,
    const __half* __restrict__ kh, const __half* __restrict__ kl,
    const __half* __restrict__ vth, const __half* __restrict__ vtl,
    const float* __restrict__ memout, const float* __restrict__ beta,
    __half* __restrict__ ch)
{
    const int h = blockIdx.y;
    const int qt = (int)gridDim.x - 1 - (int)blockIdx.x;
    const int kvh = h >> 2;
    const int tid = threadIdx.x;
    const int warp = tid >> 5;
    const int lane = tid & 31;
    const int lr = lane >> 2;
    const int lc = lane & 3;

    extern __shared__ __half sh[];
    __half* Qh_ = sh + SM_QH;
    __half* Kh_ = sh + SM_KH;
    __half* Kl_ = sh + SM_KL;
    __half* Vth_ = sh + SM_VTH;
    __half* Vtl_ = sh + SM_VTL;
    __half* Ph_ = sh + SM_PH;

    // load Q tile (single fp16 plane): 128 rows x 128 halves
#pragma unroll
    for (int it = 0; it < 4; it++) {
        int i = it * 256 + tid;
        int row = i >> 3, c8 = (i & 7) * 16;
        size_t gidx = (size_t)(qt * 128 + row) * HID + h * HD + c8;
        *(uint4*)(Qh_ + row * QH_STR + c8) = *(const uint4*)(qh + gidx);
        *(uint4*)(Qh_ + row * QH_STR + c8 + 8) = *(const uint4*)(qh + gidx + 8);
    }

    const int row0 = warp * 16 + lr;
    const int row1 = row0 + 8;
    const int grow0 = qt * 128 + row0;
    const int grow1 = grow0 + 8;

    float m0 = -1e30f, m1 = -1e30f, l0 = 0.f, l1 = 0.f;
    float o[16][4];
#pragma unroll
    for (int nt = 0; nt < 16; nt++)
#pragma unroll
        for (int r = 0; r < 4; r++) o[nt][r] = 0.f;

    const int ktmax = 2 * qt + 1;
    for (int kt = 0; kt <= ktmax; kt++) {
        __syncthreads();
#pragma unroll
        for (int it = 0; it < 4; it++) {
            int i = it * 256 + tid;
            int key = i >> 4, c8 = (i & 15) * 8;
            size_t gidx = (size_t)(kt * 64 + key) * (NKV * HD) + kvh * HD + c8;
            *(uint4*)(Kh_ + key * KH_STR + c8) = *(const uint4*)(kh + gidx);
            *(uint4*)(Kl_ + key * KH_STR + c8) = *(const uint4*)(kl + gidx);
        }
#pragma unroll
        for (int it = 0; it < 4; it++) {
            int i = it * 256 + tid;
            int dr = i >> 3, kc = (i & 7) * 8;
            size_t gidx = (size_t)(kvh * HD + dr) * S + kt * 64 + kc;
            *(uint4*)(Vth_ + dr * VT_STR + kc) = *(const uint4*)(vth + gidx);
            *(uint4*)(Vtl_ + dr * VT_STR + kc) = *(const uint4*)(vtl + gidx);
        }
        __syncthreads();

        float sc[8][4];
#pragma unroll
        for (int nt = 0; nt < 8; nt++)
#pragma unroll
            for (int r = 0; r < 4; r++) sc[nt][r] = 0.f;

#pragma unroll
        for (int ks = 0; ks < 8; ks++) {
            const int kb = ks * 16;
            uint32_t ah[4];
            {
                const __half* p0 = Qh_ + row0 * QH_STR + kb + 2 * lc;
                const __half* p1 = Qh_ + row1 * QH_STR + kb + 2 * lc;
                ah[0] = *(const uint32_t*)(p0);
                ah[1] = *(const uint32_t*)(p1);
                ah[2] = *(const uint32_t*)(p0 + 8);
                ah[3] = *(const uint32_t*)(p1 + 8);
            }
#pragma unroll
            for (int nt = 0; nt < 8; nt++) {
                const int n0 = nt * 8 + lr;
                const __half* ph = Kh_ + n0 * KH_STR + kb + 2 * lc;
                const __half* pl = Kl_ + n0 * KH_STR + kb + 2 * lc;
                uint32_t bh0 = *(const uint32_t*)(ph);
                uint32_t bh1 = *(const uint32_t*)(ph + 8);
                uint32_t bl0 = *(const uint32_t*)(pl);
                uint32_t bl1 = *(const uint32_t*)(pl + 8);
                mma_f16(sc[nt][0], sc[nt][1], sc[nt][2], sc[nt][3],
                        ah[0], ah[1], ah[2], ah[3], bh0, bh1);
                mma_f16(sc[nt][0], sc[nt][1], sc[nt][2], sc[nt][3],
                        ah[0], ah[1], ah[2], ah[3], bl0, bl1);
            }
        }

        const bool need_mask = (kt >= 2 * qt);
        float mx0 = -1e30f, mx1 = -1e30f;
#pragma unroll
        for (int nt = 0; nt < 8; nt++) {
#pragma unroll
            for (int j = 0; j < 2; j++) {
                int col = kt * 64 + nt * 8 + 2 * lc + j;
                float s0 = sc[nt][j] * ATT_SCALE;
                float s1 = sc[nt][2 + j] * ATT_SCALE;
                if (need_mask) {
                    if (col > grow0) s0 = -1e30f;
                    if (col > grow1) s1 = -1e30f;
                }
                sc[nt][j] = s0;
                sc[nt][2 + j] = s1;
                mx0 = fmaxf(mx0, s0);
                mx1 = fmaxf(mx1, s1);
            }
        }
        mx0 = fmaxf(mx0, __shfl_xor_sync(0xffffffffu, mx0, 1));
        mx0 = fmaxf(mx0, __shfl_xor_sync(0xffffffffu, mx0, 2));
        mx1 = fmaxf(mx1, __shfl_xor_sync(0xffffffffu, mx1, 1));
        mx1 = fmaxf(mx1, __shfl_xor_sync(0xffffffffu, mx1, 2));
        const float mn0 = fmaxf(m0, mx0);
        const float mn1 = fmaxf(m1, mx1);
        const float scl0 = __expf(m0 - mn0);
        const float scl1 = __expf(m1 - mn1);
        float ls0 = 0.f, ls1 = 0.f;
#pragma unroll
        for (int nt = 0; nt < 8; nt++) {
            float p00 = __expf(sc[nt][0] - mn0);
            float p01 = __expf(sc[nt][1] - mn0);
            float p10 = __expf(sc[nt][2] - mn1);
            float p11 = __expf(sc[nt][3] - mn1);
            ls0 += p00 + p01;
            ls1 += p10 + p11;
            *(uint32_t*)(Ph_ + row0 * PH_STR + nt * 8 + 2 * lc) = h2pack(p00, p01);
            *(uint32_t*)(Ph_ + row1 * PH_STR + nt * 8 + 2 * lc) = h2pack(p10, p11);
        }
        ls0 += __shfl_xor_sync(0xffffffffu, ls0, 1);
        ls0 += __shfl_xor_sync(0xffffffffu, ls0, 2);
        ls1 += __shfl_xor_sync(0xffffffffu, ls1, 1);
        ls1 += __shfl_xor_sync(0xffffffffu, ls1, 2);
        l0 = l0 * scl0 + ls0;
        l1 = l1 * scl1 + ls1;
        m0 = mn0;
        m1 = mn1;

#pragma unroll
        for (int nt = 0; nt < 16; nt++) {
            o[nt][0] *= scl0;
            o[nt][1] *= scl0;
            o[nt][2] *= scl1;
            o[nt][3] *= scl1;
        }
        __syncwarp();

#pragma unroll
        for (int ks2 = 0; ks2 < 4; ks2++) {
            const int kb = ks2 * 16;
            uint32_t ah[4];
            {
                const __half* p0 = Ph_ + row0 * PH_STR + kb + 2 * lc;
                const __half* p1 = Ph_ + row1 * PH_STR + kb + 2 * lc;
                ah[0] = *(const uint32_t*)(p0);
                ah[1] = *(const uint32_t*)(p1);
                ah[2] = *(const uint32_t*)(p0 + 8);
                ah[3] = *(const uint32_t*)(p1 + 8);
            }
#pragma unroll
            for (int nt = 0; nt < 16; nt++) {
                const int n0 = nt * 8 + lr;
                const __half* ph = Vth_ + n0 * VT_STR + kb + 2 * lc;
                const __half* pl = Vtl_ + n0 * VT_STR + kb + 2 * lc;
                uint32_t bh0 = *(const uint32_t*)(ph);
                uint32_t bh1 = *(const uint32_t*)(ph + 8);
                uint32_t bl0 = *(const uint32_t*)(pl);
                uint32_t bl1 = *(const uint32_t*)(pl + 8);
                mma_f16(o[nt][0], o[nt][1], o[nt][2], o[nt][3],
                        ah[0], ah[1], ah[2], ah[3], bh0, bh1);
                mma_f16(o[nt][0], o[nt][1], o[nt][2], o[nt][3],
                        ah[0], ah[1], ah[2], ah[3], bl0, bl1);
            }
        }
    }

    // epilogue: gate-combine, emit fp16
    const float g = 1.f / (1.f + __expf(-beta[0]));
    const float og = 1.f - g;
    const float li0 = 1.f / l0;
    const float li1 = 1.f / l1;
#pragma unroll
    for (int nt = 0; nt < 16; nt++) {
        const int col = nt * 8 + 2 * lc;
        size_t i0 = (size_t)grow0 * HID + h * HD + col;
        size_t i1 = (size_t)grow1 * HID + h * HD + col;
        float2 mo0 = *(const float2*)(memout + i0);
        float2 mo1 = *(const float2*)(memout + i1);
        *(uint32_t*)(ch + i0) = h2pack(g * mo0.x + og * (o[nt][0] * li0),
                                       g * mo0.y + og * (o[nt][1] * li0));
        *(uint32_t*)(ch + i1) = h2pack(g * mo1.x + og * (o[nt][2] * li1),
                                       g * mo1.y + og * (o[nt][3] * li1));
    }
}

// ---------------- delta-rule partials ----------------
__global__ __launch_bounds__(256) void delta_part_kernel(
    const float* __restrict__ kn, const float* __restrict__ vd, float* __restrict__ part)
{
    const int h = blockIdx.x;
    const int c = blockIdx.y;
    __shared__ float Ak[32][128];
    __shared__ float Bv[32][128];
    const int trow = (threadIdx.x >> 4) * 8;
    const int tcol = (threadIdx.x & 15) * 8;
    float acc[8][8];
#pragma unroll
    for (int i = 0; i < 8; i++)
#pragma unroll
        for (int j = 0; j < 8; j++) acc[i][j] = 0.f;

    const int sbeg = c * 256;
    for (int s0 = sbeg; s0 < sbeg + 256; s0 += 32) {
        for (int i = threadIdx.x; i < 32 * 128; i += 256) {
            int ss = i >> 7, dd = i & 127;
            size_t idx = (size_t)(s0 + ss) * (NKV * HD) + h * HD + dd;
            Ak[ss][dd] = kn[idx];
            Bv[ss][dd] = vd[idx];
        }
        __syncthreads();
#pragma unroll 4
        for (int ss = 0; ss < 32; ss++) {
            float ra[8], rb[8];
#pragma unroll
            for (int i = 0; i < 8; i++) ra[i] = Ak[ss][trow + i];
#pragma unroll
            for (int j = 0; j < 8; j++) rb[j] = Bv[ss][tcol + j];
#pragma unroll
            for (int i = 0; i < 8; i++)
#pragma unroll
                for (int j = 0; j < 8; j++) acc[i][j] += ra[i] * rb[j];
        }
        __syncthreads();
    }
    float* Ph = part + (size_t)c * (NKV * HD * HD) + h * HD * HD;
#pragma unroll
    for (int i = 0; i < 8; i++)
#pragma unroll
        for (int j = 0; j < 8; j++)
            Ph[(trow + i) * HD + tcol + j] = acc[i][j];
}

// fused memory-update + norm-update (same index space)
__global__ __launch_bounds__(256) void finalize_kernel(
    const float* __restrict__ part, const float* __restrict__ memory,
    const float* __restrict__ norm_m, const float* __restrict__ knsum,
    float* __restrict__ outmem, float* __restrict__ outnorm)
{
    const int i = blockIdx.x * 256 + threadIdx.x;   // < NKV*HD*HD
    float acc = memory[i];
#pragma unroll
    for (int c = 0; c < 8; c++) acc += part[(size_t)c * (NKV * HD * HD) + i];
    outmem[i] = acc;
    const int h = i >> 14;
    const int j = i & 127;
    outnorm[i] = norm_m[i] + knsum[h * HD + j];
}

// ---------------- launch ----------------
extern "C" void kernel_launch(void* const* d_in, const int* in_sizes, int n_in,
                              void* d_out, int out_size)
{
    const float* hidden = (const float*)d_in[0];
    const int*   pos    = (const int*)d_in[1];
    const float* wq     = (const float*)d_in[2];
    const float* wk     = (const float*)d_in[3];
    const float* wv     = (const float*)d_in[4];
    const float* wo     = (const float*)d_in[5];
    const float* memory = (const float*)d_in[6];
    const float* norm_m = (const float*)d_in[7];
    const float* beta   = (const float*)d_in[8];
    float* out = (float*)d_out;

    float *qproj, *kproj, *vproj, *qn, *kn, *memout, *vdelta, *knsum, *knpart, *dpart;
    __half *hh, *wqT, *wkT, *wvT, *woT, *ch, *qh, *kh, *kl, *vth, *vtl;
    cudaGetSymbolAddress((void**)&qproj, g_qproj);
    cudaGetSymbolAddress((void**)&kproj, g_kproj);
    cudaGetSymbolAddress((void**)&vproj, g_vproj);
    cudaGetSymbolAddress((void**)&qn, g_qn);
    cudaGetSymbolAddress((void**)&kn, g_kn);
    cudaGetSymbolAddress((void**)&memout, g_memout);
    cudaGetSymbolAddress((void**)&vdelta, g_vdelta);
    cudaGetSymbolAddress((void**)&knsum, g_knsum);
    cudaGetSymbolAddress((void**)&knpart, g_knsum_part);
    cudaGetSymbolAddress((void**)&dpart, g_delta_part);
    cudaGetSymbolAddress((void**)&hh, g_hh);
    cudaGetSymbolAddress((void**)&wqT, g_wqT);
    cudaGetSymbolAddress((void**)&wkT, g_wkT);
    cudaGetSymbolAddress((void**)&wvT, g_wvT);
    cudaGetSymbolAddress((void**)&woT, g_woT);
    cudaGetSymbolAddress((void**)&ch, g_ch);
    cudaGetSymbolAddress((void**)&qh, g_qh);
    cudaGetSymbolAddress((void**)&kh, g_kh);
    cudaGetSymbolAddress((void**)&kl, g_kl);
    cudaGetSymbolAddress((void**)&vth, g_vth);
    cudaGetSymbolAddress((void**)&vtl, g_vtl);

    cudaFuncSetAttribute(attn_f16_kernel,
                         cudaFuncAttributeMaxDynamicSharedMemorySize, ATT2_SMEM_BYTES);
    cudaFuncSetAttribute(gemm_f16_kernel,
                         cudaFuncAttributeMaxDynamicSharedMemorySize, GEMM4_SMEM);

    // pre-pass: hidden -> fp16; all four weight transposes in ONE launch
    h2h_kernel<<<1024, 256>>>(hidden, hh, S * HID / 4);
    wtrans4_kernel<<<dim3(HID / 32, HID / 32, 4), 256>>>(
        wq, wqT, wk, wkT, wv, wvT, wo, woT);

    // projections (fp16 m16n8k16 + ldmatrix, 3-stage). z=0: Q; z=1: bx<8 K, bx<16 V.
    gemm_f16_kernel<<<dim3(HID / 128, S / 128, 2), 128, GEMM4_SMEM>>>(
        hh, wqT, qproj, HID, wkT, kproj, wvT, vproj, NKV * HD, HID);

    // normalized features from PRE-RoPE q/k (warp-per-head, barrier-free)
    qn2_kernel<<<S, 256>>>(qproj, qn);
    kn2_kernel<<<S, 256>>>(kproj, kn);
    knsum_part_kernel<<<dim3(NKV, 16), 128>>>(kn, knpart);
    knsum_final_kernel<<<1, 1024>>>(knpart, knsum);

    // compressive-memory retrieval + delta-rule prep in ONE launch
    memops_kernel<<<dim3(S / 16, NH + NKV), 128>>>(
        qn, kn, vproj, memory, norm_m, memout, vdelta);

    // RoPE + fp16 split (Q single-plane; K hi/lo); V transpose + split
    rope_split_kernel<<<dim3(S, 10), 256>>>(qproj, kproj, pos, qh, kh, kl);
    vtrans_split_kernel<<<dim3(S / 32, NKV * HD / 32), 256>>>(vproj, vth, vtl);

    // fp16 flash attention (Q/P single fp16, K/V 2-split; fuses gated combine)
    attn_f16_kernel<<<dim3(S / 128, NH), 256, ATT2_SMEM_BYTES>>>(
        qh, kh, kl, vth, vtl, memout, beta, ch);

    // output projection (fp16)
    gemm_f16_kernel<<<dim3(HID / 128, S / 128, 1), 128, GEMM4_SMEM>>>(
        ch, woT, out, HID, woT, out, woT, out, HID, HID);

    // memory & norm updates (fused; appended after the 8.4M-element `out`)
    delta_part_kernel<<<dim3(NKV, 8), 256>>>(kn, vdelta, dpart);
    finalize_kernel<<<(NKV * HD * HD) / 256, 256>>>(
        dpart, memory, norm_m, knsum,
        out + (size_t)S * HID, out + (size_t)S * HID + NKV * HD * HD);
}

// round 17
// speedup vs baseline: 2.2273x; 1.1789x over previous
#include <cuda_runtime.h>
#include <cuda_fp16.h>
#include <math.h>
#include <stdint.h>

// ---------------- problem constants ----------------
#define S 2048
#define HID 4096
#define NH 32
#define NKV 8
#define HD 128
#define GROUPS 4
#define EPS 1e-8f
#define ATT_SCALE 0.08838834764831845f   // 128^-0.5
#define LN10000 9.210340371976184f

// ---------------- scratch (device globals; no allocation allowed) ----------------
__device__ float g_qproj[S * HID];
__device__ float g_kproj[S * NKV * HD];
__device__ float g_vproj[S * NKV * HD];
__device__ float g_qn[S * HID];
__device__ float g_kn[S * NKV * HD];
__device__ float g_memout[S * HID];
__device__ float g_vdelta[S * NKV * HD];
__device__ float g_knsum[NKV * HD];
__device__ float g_knsum_part[16][NKV * HD];
__device__ float g_delta_part[8][NKV * HD * HD];
// fp16 GEMM operands
__device__ __half g_hh[S * HID];             // hidden, [M][K]
__device__ __half g_wqT[HID * HID];          // [N][K]
__device__ __half g_wkT[NKV * HD * HID];
__device__ __half g_wvT[NKV * HD * HID];
__device__ __half g_woT[HID * HID];
__device__ __half g_ch[S * HID];             // combined (attention out), [M][K]
// fp16 single planes for attention
__device__ __half g_qh[S * HID];
__device__ __half g_kh[S * NKV * HD];
__device__ __half g_vth[NKV * HD * S];       // V^T: [h*HD+d][s]

// ---------------- fp16 mma + ldmatrix ----------------
__device__ __forceinline__ void mma_f16(
    float& c0, float& c1, float& c2, float& c3,
    uint32_t a0, uint32_t a1, uint32_t a2, uint32_t a3,
    uint32_t b0, uint32_t b1)
{
    asm volatile(
        "mma.sync.aligned.m16n8k16.row.col.f32.f16.f16.f32 "
        "{%0,%1,%2,%3},{%4,%5,%6,%7},{%8,%9},{%0,%1,%2,%3};"
        : "+f"(c0), "+f"(c1), "+f"(c2), "+f"(c3)
        : "r"(a0), "r"(a1), "r"(a2), "r"(a3), "r"(b0), "r"(b1));
}

#define LDSM4(r0, r1, r2, r3, addr) \
    asm volatile("ldmatrix.sync.aligned.m8n8.x4.shared.b16 {%0,%1,%2,%3}, [%4];" \
                 : "=r"(r0), "=r"(r1), "=r"(r2), "=r"(r3) : "r"(addr))

__device__ __forceinline__ uint32_t h2pack(float a, float b) {
    __half2 h = __floats2half2_rn(a, b);
    return *(uint32_t*)&h;
}

// ---------------- pre-pass: fp32 -> fp16 ----------------
__global__ __launch_bounds__(256) void h2h_kernel(
    const float* __restrict__ src, __half* __restrict__ dst, int n4)
{
    for (int i = blockIdx.x * 256 + threadIdx.x; i < n4; i += gridDim.x * 256) {
        float4 v = ((const float4*)src)[i];
        uint2 p = make_uint2(h2pack(v.x, v.y), h2pack(v.z, v.w));
        ((uint2*)dst)[i] = p;
    }
}

// transpose all four weights in ONE launch: z selects the matrix.
__global__ __launch_bounds__(256) void wtrans4_kernel(
    const float* __restrict__ wq, __half* __restrict__ wqt,
    const float* __restrict__ wk, __half* __restrict__ wkt,
    const float* __restrict__ wv, __half* __restrict__ wvt,
    const float* __restrict__ wo, __half* __restrict__ wot)
{
    const float* w;
    __half* wt;
    int Nd;
    switch (blockIdx.z) {
        case 0: w = wq; wt = wqt; Nd = HID; break;
        case 1: w = wk; wt = wkt; Nd = NKV * HD; break;
        case 2: w = wv; wt = wvt; Nd = NKV * HD; break;
        default: w = wo; wt = wot; Nd = HID; break;
    }
    const int bx = blockIdx.x;       // N tile
    if (bx * 32 >= Nd) return;
    const int by = blockIdx.y;       // K tile
    __shared__ float t[32][33];
    const int x = threadIdx.x & 31;
    const int y = threadIdx.x >> 5;
#pragma unroll
    for (int j = 0; j < 4; j++) {
        int kr = y + 8 * j;
        t[kr][x] = w[(size_t)(by * 32 + kr) * Nd + bx * 32 + x];
    }
    __syncthreads();
#pragma unroll
    for (int j = 0; j < 4; j++) {
        int nr = y + 8 * j;
        wt[(size_t)(bx * 32 + nr) * HID + by * 32 + x] = __float2half_rn(t[x][nr]);
    }
}

// ---------------- GEMM: fp16 m16n8k16 + ldmatrix, 4 warps, 64x64 warp tile, BK=32, 3-stage ----------------
#define HAS_STR 40
#define HBS_STR 40
#define STG4_BYTES ((128 * HAS_STR + 128 * HBS_STR) * 2)   // 20480
#define GEMM4_SMEM (3 * STG4_BYTES)                        // 61440

#define CP16(dst_u32, src_ptr) \
    asm volatile("cp.async.cg.shared.global [%0], [%1], 16;" :: "r"(dst_u32), "l"(src_ptr))

__global__ __launch_bounds__(128, 2) void gemm_f16_kernel(
    const __half* __restrict__ A,
    const __half* __restrict__ B0, float* __restrict__ C0, int N0,
    const __half* __restrict__ B1, float* __restrict__ C1,
    const __half* __restrict__ B2, float* __restrict__ C2, int N12,
    int K)
{
    const __half* Bt;
    float* C;
    int N, bx;
    if (blockIdx.z == 0) {
        Bt = B0; C = C0; N = N0; bx = blockIdx.x;
        if (bx * 128 >= N0) return;
    } else {
        N = N12;
        const int nt12 = N12 / 128;
        if ((int)blockIdx.x < nt12) { Bt = B1; C = C1; bx = blockIdx.x; }
        else if ((int)blockIdx.x < 2 * nt12) { Bt = B2; C = C2; bx = blockIdx.x - nt12; }
        else return;
    }

    extern __shared__ __half smh[];
    const uint32_t smu = (uint32_t)__cvta_generic_to_shared(smh);

    const int tid = threadIdx.x;
    const int lane = tid & 31;
    const int wid = tid >> 5;
    const int wm = wid >> 1;
    const int wn = wid & 1;
    const int lr = lane >> 2;
    const int lc = lane & 3;
    const int by = blockIdx.y;

    const int crow = tid >> 2;
    const int cchk = (tid & 3) * 8;

    const __half* Ab = A + (size_t)(by * 128) * K;
    const __half* Bb = Bt + (size_t)(bx * 128) * K;

    const uint32_t a_lane_off =
        (uint32_t)(((lane & 15) * HAS_STR + ((lane >> 4) << 3)) * 2);
    const uint32_t b_lane_off =
        (uint32_t)((((lane & 7) + ((lane >> 4) << 3)) * HBS_STR + (((lane >> 3) & 1) << 3)) * 2);

    float acc[4][8][4];
#pragma unroll
    for (int i = 0; i < 4; i++)
#pragma unroll
        for (int j = 0; j < 8; j++)
#pragma unroll
            for (int r = 0; r < 4; r++) acc[i][j][r] = 0.f;

    const int NT = K / 32;

#define LOAD_STAGE(stg, ch)                                                           \
    {                                                                                 \
        const uint32_t sb = smu + (uint32_t)((stg) * STG4_BYTES);                     \
        const int k0 = (ch) * 32;                                                     \
        _Pragma("unroll")                                                             \
        for (int i = 0; i < 4; i++) {                                                 \
            const int r = i * 32 + crow;                                              \
            CP16(sb + (uint32_t)((r * HAS_STR + cchk) * 2), Ab + (size_t)r * K + k0 + cchk); \
        }                                                                             \
        _Pragma("unroll")                                                             \
        for (int i = 0; i < 4; i++) {                                                 \
            const int r = i * 32 + crow;                                              \
            CP16(sb + (uint32_t)((128 * HAS_STR + r * HBS_STR + cchk) * 2),           \
                 Bb + (size_t)r * K + k0 + cchk);                                     \
        }                                                                             \
    }

    LOAD_STAGE(0, 0)
    asm volatile("cp.async.commit_group;" ::: "memory");
    LOAD_STAGE(1, 1)
    asm volatile("cp.async.commit_group;" ::: "memory");

    int stage = 0;
    for (int it = 0; it < NT; it++) {
        asm volatile("cp.async.wait_group 1;" ::: "memory");
        __syncthreads();

        const int pf = it + 2;
        if (pf < NT) {
            const int ps = (stage + 2) % 3;
            LOAD_STAGE(ps, pf)
        }
        asm volatile("cp.async.commit_group;" ::: "memory");

        const uint32_t sbA = smu + (uint32_t)(stage * STG4_BYTES);
        const uint32_t sbB = sbA + (uint32_t)(128 * HAS_STR * 2);

#pragma unroll
        for (int ks = 0; ks < 2; ks++) {
            const uint32_t kbB = (uint32_t)(ks * 16 * 2);
            uint32_t af[4][4], bf[8][2];
#pragma unroll
            for (int mt = 0; mt < 4; mt++) {
                const uint32_t addr = sbA
                    + (uint32_t)(((wm * 64 + mt * 16) * HAS_STR) * 2)
                    + a_lane_off + kbB;
                LDSM4(af[mt][0], af[mt][1], af[mt][2], af[mt][3], addr);
            }
#pragma unroll
            for (int ntp = 0; ntp < 4; ntp++) {
                const uint32_t addr = sbB
                    + (uint32_t)(((wn * 64 + ntp * 16) * HBS_STR) * 2)
                    + b_lane_off + kbB;
                LDSM4(bf[2 * ntp][0], bf[2 * ntp][1], bf[2 * ntp + 1][0], bf[2 * ntp + 1][1], addr);
            }
#pragma unroll
            for (int mt = 0; mt < 4; mt++)
#pragma unroll
                for (int nt = 0; nt < 8; nt++)
                    mma_f16(acc[mt][nt][0], acc[mt][nt][1], acc[mt][nt][2], acc[mt][nt][3],
                            af[mt][0], af[mt][1], af[mt][2], af[mt][3],
                            bf[nt][0], bf[nt][1]);
        }
        stage = (stage + 1) % 3;
    }
#undef LOAD_STAGE

#pragma unroll
    for (int mt = 0; mt < 4; mt++) {
        const int row = by * 128 + wm * 64 + mt * 16 + lr;
#pragma unroll
        for (int nt = 0; nt < 8; nt++) {
            const int col = bx * 128 + wn * 64 + nt * 8 + lc * 2;
            float2 v01 = make_float2(acc[mt][nt][0], acc[mt][nt][1]);
            float2 v23 = make_float2(acc[mt][nt][2], acc[mt][nt][3]);
            *(float2*)(C + (size_t)row * N + col) = v01;
            *(float2*)(C + (size_t)(row + 8) * N + col) = v23;
        }
    }
}

// ---------------- qn / kn: warp-per-head, no block barriers ----------------
__global__ __launch_bounds__(256) void qn2_kernel(const float* __restrict__ qp, float* __restrict__ qn)
{
    const int s = blockIdx.x;
    const int warp = threadIdx.x >> 5;
    const int lane = threadIdx.x & 31;
    for (int h = warp; h < NH; h += 8) {
        const float* src = qp + (size_t)s * HID + h * HD;
        float4 v = ((const float4*)src)[lane];
        float4 f;
        f.x = v.x > 0.f ? v.x + 1.f : __expf(v.x);
        f.y = v.y > 0.f ? v.y + 1.f : __expf(v.y);
        f.z = v.z > 0.f ? v.z + 1.f : __expf(v.z);
        f.w = v.w > 0.f ? v.w + 1.f : __expf(v.w);
        float t = f.x + f.y + f.z + f.w;
#pragma unroll
        for (int o = 16; o; o >>= 1) t += __shfl_xor_sync(0xffffffffu, t, o);
        const float inv = 1.f / (t + EPS);
        float4 r = make_float4(f.x * inv, f.y * inv, f.z * inv, f.w * inv);
        ((float4*)(qn + (size_t)s * HID + h * HD))[lane] = r;
    }
}

__global__ __launch_bounds__(256) void kn2_kernel(const float* __restrict__ kp, float* __restrict__ kn)
{
    const int s = blockIdx.x;
    const int warp = threadIdx.x >> 5;
    const int lane = threadIdx.x & 31;
    if (warp >= NKV) return;
    const float* src = kp + (size_t)s * (NKV * HD) + warp * HD;
    float4 v = ((const float4*)src)[lane];
    float4 f;
    f.x = v.x > 0.f ? v.x + 1.f : __expf(v.x);
    f.y = v.y > 0.f ? v.y + 1.f : __expf(v.y);
    f.z = v.z > 0.f ? v.z + 1.f : __expf(v.z);
    f.w = v.w > 0.f ? v.w + 1.f : __expf(v.w);
    float t = f.x + f.y + f.z + f.w;
#pragma unroll
    for (int o = 16; o; o >>= 1) t += __shfl_xor_sync(0xffffffffu, t, o);
    const float inv = 1.f / (t + EPS);
    float4 r = make_float4(f.x * inv, f.y * inv, f.z * inv, f.w * inv);
    ((float4*)(kn + (size_t)s * (NKV * HD) + warp * HD))[lane] = r;
}

__global__ __launch_bounds__(128) void knsum_part_kernel(const float* __restrict__ kn, float* __restrict__ part)
{
    const int h = blockIdx.x;
    const int p = blockIdx.y;
    const int d = threadIdx.x;
    float acc = 0.f;
    const int s0 = p * 128;
#pragma unroll 4
    for (int s = s0; s < s0 + 128; s++)
        acc += kn[(size_t)s * (NKV * HD) + h * HD + d];
    part[p * (NKV * HD) + h * HD + d] = acc;
}

__global__ __launch_bounds__(1024) void knsum_final_kernel(const float* __restrict__ part, float* __restrict__ knsum)
{
    const int i = threadIdx.x;
    float acc = 0.f;
#pragma unroll
    for (int p = 0; p < 16; p++) acc += part[p * (NKV * HD) + i];
    knsum[i] = acc;
}

// ---------------- merged retrieval + vdelta ----------------
__global__ __launch_bounds__(128) void memops_kernel(
    const float* __restrict__ qn, const float* __restrict__ kn,
    const float* __restrict__ vproj,
    const float* __restrict__ memory, const float* __restrict__ norm_m,
    float* __restrict__ memout, float* __restrict__ vdelta)
{
    const int yy = blockIdx.y;
    const bool is_ret = (yy < NH);
    const int h = is_ret ? yy : (yy - NH);
    const int hm = is_ret ? (h & (NKV - 1)) : h;
    const int st = blockIdx.x;
    const int e = threadIdx.x;
    __shared__ float Qs[16][128];
    __shared__ float Ms[32][128];
    __shared__ float Ns[128][33];

    if (is_ret) {
        for (int i = e; i < 16 * 128; i += 128) {
            int r = i >> 7, d = i & 127;
            Qs[r][d] = qn[(size_t)(st * 16 + r) * HID + h * HD + d];
        }
    } else {
        for (int i = e; i < 16 * 128; i += 128) {
            int r = i >> 7, d = i & 127;
            Qs[r][d] = kn[(size_t)(st * 16 + r) * (NKV * HD) + h * HD + d];
        }
    }
    float num[16], den[16];
#pragma unroll
    for (int r = 0; r < 16; r++) { num[r] = 0.f; den[r] = 0.f; }
    const float* M = memory + hm * HD * HD;
    const float* Nm = norm_m + hm * HD * HD;

    for (int d0 = 0; d0 < 128; d0 += 32) {
        __syncthreads();
        for (int i = e; i < 32 * 128; i += 128) {
            int dd = i >> 7, ee = i & 127;
            Ms[dd][ee] = M[(d0 + dd) * HD + ee];
        }
        for (int i = e; i < 128 * 32; i += 128) {
            int ee = i >> 5, dd = i & 31;
            Ns[ee][dd] = Nm[ee * HD + d0 + dd];
        }
        __syncthreads();
#pragma unroll 4
        for (int dd = 0; dd < 32; dd++) {
            float mv = Ms[dd][e];
            float nv = Ns[e][dd];
#pragma unroll
            for (int r = 0; r < 16; r++) {
                float qv = Qs[r][d0 + dd];
                num[r] += qv * mv;
                den[r] += qv * nv;
            }
        }
    }
    if (is_ret) {
#pragma unroll
        for (int r = 0; r < 16; r++)
            memout[(size_t)(st * 16 + r) * HID + h * HD + e] = num[r] / (den[r] + EPS);
    } else {
#pragma unroll
        for (int r = 0; r < 16; r++) {
            size_t idx = (size_t)(st * 16 + r) * (NKV * HD) + h * HD + e;
            vdelta[idx] = vproj[idx] - num[r] / (den[r] + EPS);
        }
    }
}

// ---------------- RoPE + fp16 (single plane for both Q and K) ----------------
__global__ __launch_bounds__(256) void rope_split_kernel(
    const float* __restrict__ q, const float* __restrict__ k, const int* __restrict__ pos,
    __half* __restrict__ qh, __half* __restrict__ kh)
{
    const int s = blockIdx.x;
    const int idx = blockIdx.y * 256 + threadIdx.x;
    if (idx >= (NH + NKV) * 64) return;
    const int head = idx >> 6;
    const int d = idx & 63;
    const float p = (float)pos[s];
    const float invf = expf(-(2.0f * (float)d / 128.0f) * LN10000);
    const float a = p * invf;
    const float c = cosf(a), sn = sinf(a);
    const float* base;
    __half* oh;
    if (head < NH) {
        size_t off = (size_t)s * HID + head * HD;
        base = q + off; oh = qh + off;
    } else {
        size_t off = (size_t)s * (NKV * HD) + (head - NH) * HD;
        base = k + off; oh = kh + off;
    }
    float x0 = base[d], x1 = base[d + 64];
    oh[d]      = __float2half_rn(x0 * c - x1 * sn);
    oh[d + 64] = __float2half_rn(x1 * c + x0 * sn);
}

// ---------------- V transpose (single fp16 plane) ----------------
__global__ __launch_bounds__(256) void vtrans_split_kernel(
    const float* __restrict__ v, __half* __restrict__ vth)
{
    __shared__ float t[32][33];
    const int bx = blockIdx.x;
    const int by = blockIdx.y;
    const int x = threadIdx.x & 31;
    const int y = threadIdx.x >> 5;
#pragma unroll
    for (int j = 0; j < 4; j++) {
        int sr = y + 8 * j;
        t[sr][x] = v[(size_t)(bx * 32 + sr) * (NKV * HD) + by * 32 + x];
    }
    __syncthreads();
#pragma unroll
    for (int j = 0; j < 4; j++) {
        int cr = y + 8 * j;
        size_t idx = (size_t)(by * 32 + cr) * S + bx * 32 + x;
        vth[idx] = __float2half_rn(t[x][cr]);
    }
}

// ---------------- pure-fp16 MMA flash attention (all operands single plane) ----------------
#define QH_STR 136
#define KH_STR 136
#define VT_STR 72
#define PH_STR 72
#define SM_QH 0
#define SM_KH (128 * QH_STR)
#define SM_VTH (SM_KH + 64 * KH_STR)
#define SM_PH (SM_VTH + 128 * VT_STR)
#define ATT2_SMEM_HALVES (SM_PH + 128 * PH_STR)
#define ATT2_SMEM_BYTES (ATT2_SMEM_HALVES * 2)   // 89088

__global__ __launch_bounds__(256) void attn_f16_kernel(
    const __half* __restrict__ qh, const __half* __restrict__ kh,
    const __half* __restrict__ vth,
    const float* __restrict__ memout, const float* __restrict__ beta,
    __half* __restrict__ ch)
{
    const int h = blockIdx.y;
    const int qt = (int)gridDim.x - 1 - (int)blockIdx.x;
    const int kvh = h >> 2;
    const int tid = threadIdx.x;
    const int warp = tid >> 5;
    const int lane = tid & 31;
    const int lr = lane >> 2;
    const int lc = lane & 3;

    extern __shared__ __half sh[];
    __half* Qh_ = sh + SM_QH;
    __half* Kh_ = sh + SM_KH;
    __half* Vth_ = sh + SM_VTH;
    __half* Ph_ = sh + SM_PH;

    // load Q tile: 128 rows x 128 halves
#pragma unroll
    for (int it = 0; it < 4; it++) {
        int i = it * 256 + tid;
        int row = i >> 3, c8 = (i & 7) * 16;
        size_t gidx = (size_t)(qt * 128 + row) * HID + h * HD + c8;
        *(uint4*)(Qh_ + row * QH_STR + c8) = *(const uint4*)(qh + gidx);
        *(uint4*)(Qh_ + row * QH_STR + c8 + 8) = *(const uint4*)(qh + gidx + 8);
    }

    const int row0 = warp * 16 + lr;
    const int row1 = row0 + 8;
    const int grow0 = qt * 128 + row0;
    const int grow1 = grow0 + 8;

    float m0 = -1e30f, m1 = -1e30f, l0 = 0.f, l1 = 0.f;
    float o[16][4];
#pragma unroll
    for (int nt = 0; nt < 16; nt++)
#pragma unroll
        for (int r = 0; r < 4; r++) o[nt][r] = 0.f;

    const int ktmax = 2 * qt + 1;
    for (int kt = 0; kt <= ktmax; kt++) {
        __syncthreads();
        // K tile: 64 rows x 128 halves
#pragma unroll
        for (int it = 0; it < 2; it++) {
            int i = it * 256 + tid;
            int key = i >> 3, c8 = (i & 7) * 16;
            size_t gidx = (size_t)(kt * 64 + key) * (NKV * HD) + kvh * HD + c8;
            *(uint4*)(Kh_ + key * KH_STR + c8) = *(const uint4*)(kh + gidx);
            *(uint4*)(Kh_ + key * KH_STR + c8 + 8) = *(const uint4*)(kh + gidx + 8);
        }
        // V^T tile: 128 d-rows x 64 keys
#pragma unroll
        for (int it = 0; it < 2; it++) {
            int i = it * 256 + tid;
            int dr = i >> 2, kc = (i & 3) * 16;
            size_t gidx = (size_t)(kvh * HD + dr) * S + kt * 64 + kc;
            *(uint4*)(Vth_ + dr * VT_STR + kc) = *(const uint4*)(vth + gidx);
            *(uint4*)(Vth_ + dr * VT_STR + kc + 8) = *(const uint4*)(vth + gidx + 8);
        }
        __syncthreads();

        float sc[8][4];
#pragma unroll
        for (int nt = 0; nt < 8; nt++)
#pragma unroll
            for (int r = 0; r < 4; r++) sc[nt][r] = 0.f;

#pragma unroll
        for (int ks = 0; ks < 8; ks++) {
            const int kb = ks * 16;
            uint32_t ah[4];
            {
                const __half* p0 = Qh_ + row0 * QH_STR + kb + 2 * lc;
                const __half* p1 = Qh_ + row1 * QH_STR + kb + 2 * lc;
                ah[0] = *(const uint32_t*)(p0);
                ah[1] = *(const uint32_t*)(p1);
                ah[2] = *(const uint32_t*)(p0 + 8);
                ah[3] = *(const uint32_t*)(p1 + 8);
            }
#pragma unroll
            for (int nt = 0; nt < 8; nt++) {
                const int n0 = nt * 8 + lr;
                const __half* ph = Kh_ + n0 * KH_STR + kb + 2 * lc;
                uint32_t bh0 = *(const uint32_t*)(ph);
                uint32_t bh1 = *(const uint32_t*)(ph + 8);
                mma_f16(sc[nt][0], sc[nt][1], sc[nt][2], sc[nt][3],
                        ah[0], ah[1], ah[2], ah[3], bh0, bh1);
            }
        }

        const bool need_mask = (kt >= 2 * qt);
        float mx0 = -1e30f, mx1 = -1e30f;
#pragma unroll
        for (int nt = 0; nt < 8; nt++) {
#pragma unroll
            for (int j = 0; j < 2; j++) {
                int col = kt * 64 + nt * 8 + 2 * lc + j;
                float s0 = sc[nt][j] * ATT_SCALE;
                float s1 = sc[nt][2 + j] * ATT_SCALE;
                if (need_mask) {
                    if (col > grow0) s0 = -1e30f;
                    if (col > grow1) s1 = -1e30f;
                }
                sc[nt][j] = s0;
                sc[nt][2 + j] = s1;
                mx0 = fmaxf(mx0, s0);
                mx1 = fmaxf(mx1, s1);
            }
        }
        mx0 = fmaxf(mx0, __shfl_xor_sync(0xffffffffu, mx0, 1));
        mx0 = fmaxf(mx0, __shfl_xor_sync(0xffffffffu, mx0, 2));
        mx1 = fmaxf(mx1, __shfl_xor_sync(0xffffffffu, mx1, 1));
        mx1 = fmaxf(mx1, __shfl_xor_sync(0xffffffffu, mx1, 2));
        const float mn0 = fmaxf(m0, mx0);
        const float mn1 = fmaxf(m1, mx1);
        const float scl0 = __expf(m0 - mn0);
        const float scl1 = __expf(m1 - mn1);
        float ls0 = 0.f, ls1 = 0.f;
#pragma unroll
        for (int nt = 0; nt < 8; nt++) {
            float p00 = __expf(sc[nt][0] - mn0);
            float p01 = __expf(sc[nt][1] - mn0);
            float p10 = __expf(sc[nt][2] - mn1);
            float p11 = __expf(sc[nt][3] - mn1);
            ls0 += p00 + p01;
            ls1 += p10 + p11;
            *(uint32_t*)(Ph_ + row0 * PH_STR + nt * 8 + 2 * lc) = h2pack(p00, p01);
            *(uint32_t*)(Ph_ + row1 * PH_STR + nt * 8 + 2 * lc) = h2pack(p10, p11);
        }
        ls0 += __shfl_xor_sync(0xffffffffu, ls0, 1);
        ls0 += __shfl_xor_sync(0xffffffffu, ls0, 2);
        ls1 += __shfl_xor_sync(0xffffffffu, ls1, 1);
        ls1 += __shfl_xor_sync(0xffffffffu, ls1, 2);
        l0 = l0 * scl0 + ls0;
        l1 = l1 * scl1 + ls1;
        m0 = mn0;
        m1 = mn1;

#pragma unroll
        for (int nt = 0; nt < 16; nt++) {
            o[nt][0] *= scl0;
            o[nt][1] *= scl0;
            o[nt][2] *= scl1;
            o[nt][3] *= scl1;
        }
        __syncwarp();

#pragma unroll
        for (int ks2 = 0; ks2 < 4; ks2++) {
            const int kb = ks2 * 16;
            uint32_t ah[4];
            {
                const __half* p0 = Ph_ + row0 * PH_STR + kb + 2 * lc;
                const __half* p1 = Ph_ + row1 * PH_STR + kb + 2 * lc;
                ah[0] = *(const uint32_t*)(p0);
                ah[1] = *(const uint32_t*)(p1);
                ah[2] = *(const uint32_t*)(p0 + 8);
                ah[3] = *(const uint32_t*)(p1 + 8);
            }
#pragma unroll
            for (int nt = 0; nt < 16; nt++) {
                const int n0 = nt * 8 + lr;
                const __half* ph = Vth_ + n0 * VT_STR + kb + 2 * lc;
                uint32_t bh0 = *(const uint32_t*)(ph);
                uint32_t bh1 = *(const uint32_t*)(ph + 8);
                mma_f16(o[nt][0], o[nt][1], o[nt][2], o[nt][3],
                        ah[0], ah[1], ah[2], ah[3], bh0, bh1);
            }
        }
    }

    // epilogue: gate-combine, emit fp16
    const float g = 1.f / (1.f + __expf(-beta[0]));
    const float og = 1.f - g;
    const float li0 = 1.f / l0;
    const float li1 = 1.f / l1;
#pragma unroll
    for (int nt = 0; nt < 16; nt++) {
        const int col = nt * 8 + 2 * lc;
        size_t i0 = (size_t)grow0 * HID + h * HD + col;
        size_t i1 = (size_t)grow1 * HID + h * HD + col;
        float2 mo0 = *(const float2*)(memout + i0);
        float2 mo1 = *(const float2*)(memout + i1);
        *(uint32_t*)(ch + i0) = h2pack(g * mo0.x + og * (o[nt][0] * li0),
                                       g * mo0.y + og * (o[nt][1] * li0));
        *(uint32_t*)(ch + i1) = h2pack(g * mo1.x + og * (o[nt][2] * li1),
                                       g * mo1.y + og * (o[nt][3] * li1));
    }
}

// ---------------- delta-rule partials ----------------
__global__ __launch_bounds__(256) void delta_part_kernel(
    const float* __restrict__ kn, const float* __restrict__ vd, float* __restrict__ part)
{
    const int h = blockIdx.x;
    const int c = blockIdx.y;
    __shared__ float Ak[32][128];
    __shared__ float Bv[32][128];
    const int trow = (threadIdx.x >> 4) * 8;
    const int tcol = (threadIdx.x & 15) * 8;
    float acc[8][8];
#pragma unroll
    for (int i = 0; i < 8; i++)
#pragma unroll
        for (int j = 0; j < 8; j++) acc[i][j] = 0.f;

    const int sbeg = c * 256;
    for (int s0 = sbeg; s0 < sbeg + 256; s0 += 32) {
        for (int i = threadIdx.x; i < 32 * 128; i += 256) {
            int ss = i >> 7, dd = i & 127;
            size_t idx = (size_t)(s0 + ss) * (NKV * HD) + h * HD + dd;
            Ak[ss][dd] = kn[idx];
            Bv[ss][dd] = vd[idx];
        }
        __syncthreads();
#pragma unroll 4
        for (int ss = 0; ss < 32; ss++) {
            float ra[8], rb[8];
#pragma unroll
            for (int i = 0; i < 8; i++) ra[i] = Ak[ss][trow + i];
#pragma unroll
            for (int j = 0; j < 8; j++) rb[j] = Bv[ss][tcol + j];
#pragma unroll
            for (int i = 0; i < 8; i++)
#pragma unroll
                for (int j = 0; j < 8; j++) acc[i][j] += ra[i] * rb[j];
        }
        __syncthreads();
    }
    float* Ph = part + (size_t)c * (NKV * HD * HD) + h * HD * HD;
#pragma unroll
    for (int i = 0; i < 8; i++)
#pragma unroll
        for (int j = 0; j < 8; j++)
            Ph[(trow + i) * HD + tcol + j] = acc[i][j];
}

// fused memory-update + norm-update (same index space)
__global__ __launch_bounds__(256) void finalize_kernel(
    const float* __restrict__ part, const float* __restrict__ memory,
    const float* __restrict__ norm_m, const float* __restrict__ knsum,
    float* __restrict__ outmem, float* __restrict__ outnorm)
{
    const int i = blockIdx.x * 256 + threadIdx.x;   // < NKV*HD*HD
    float acc = memory[i];
#pragma unroll
    for (int c = 0; c < 8; c++) acc += part[(size_t)c * (NKV * HD * HD) + i];
    outmem[i] = acc;
    const int h = i >> 14;
    const int j = i & 127;
    outnorm[i] = norm_m[i] + knsum[h * HD + j];
}

// ---------------- launch ----------------
extern "C" void kernel_launch(void* const* d_in, const int* in_sizes, int n_in,
                              void* d_out, int out_size)
{
    const float* hidden = (const float*)d_in[0];
    const int*   pos    = (const int*)d_in[1];
    const float* wq     = (const float*)d_in[2];
    const float* wk     = (const float*)d_in[3];
    const float* wv     = (const float*)d_in[4];
    const float* wo     = (const float*)d_in[5];
    const float* memory = (const float*)d_in[6];
    const float* norm_m = (const float*)d_in[7];
    const float* beta   = (const float*)d_in[8];
    float* out = (float*)d_out;

    float *qproj, *kproj, *vproj, *qn, *kn, *memout, *vdelta, *knsum, *knpart, *dpart;
    __half *hh, *wqT, *wkT, *wvT, *woT, *ch, *qh, *kh, *vth;
    cudaGetSymbolAddress((void**)&qproj, g_qproj);
    cudaGetSymbolAddress((void**)&kproj, g_kproj);
    cudaGetSymbolAddress((void**)&vproj, g_vproj);
    cudaGetSymbolAddress((void**)&qn, g_qn);
    cudaGetSymbolAddress((void**)&kn, g_kn);
    cudaGetSymbolAddress((void**)&memout, g_memout);
    cudaGetSymbolAddress((void**)&vdelta, g_vdelta);
    cudaGetSymbolAddress((void**)&knsum, g_knsum);
    cudaGetSymbolAddress((void**)&knpart, g_knsum_part);
    cudaGetSymbolAddress((void**)&dpart, g_delta_part);
    cudaGetSymbolAddress((void**)&hh, g_hh);
    cudaGetSymbolAddress((void**)&wqT, g_wqT);
    cudaGetSymbolAddress((void**)&wkT, g_wkT);
    cudaGetSymbolAddress((void**)&wvT, g_wvT);
    cudaGetSymbolAddress((void**)&woT, g_woT);
    cudaGetSymbolAddress((void**)&ch, g_ch);
    cudaGetSymbolAddress((void**)&qh, g_qh);
    cudaGetSymbolAddress((void**)&kh, g_kh);
    cudaGetSymbolAddress((void**)&vth, g_vth);

    cudaFuncSetAttribute(attn_f16_kernel,
                         cudaFuncAttributeMaxDynamicSharedMemorySize, ATT2_SMEM_BYTES);
    cudaFuncSetAttribute(gemm_f16_kernel,
                         cudaFuncAttributeMaxDynamicSharedMemorySize, GEMM4_SMEM);

    // pre-pass: hidden -> fp16; all four weight transposes in ONE launch
    h2h_kernel<<<1024, 256>>>(hidden, hh, S * HID / 4);
    wtrans4_kernel<<<dim3(HID / 32, HID / 32, 4), 256>>>(
        wq, wqT, wk, wkT, wv, wvT, wo, woT);

    // projections (fp16 m16n8k16 + ldmatrix, 3-stage). z=0: Q; z=1: bx<8 K, bx<16 V.
    gemm_f16_kernel<<<dim3(HID / 128, S / 128, 2), 128, GEMM4_SMEM>>>(
        hh, wqT, qproj, HID, wkT, kproj, wvT, vproj, NKV * HD, HID);

    // normalized features from PRE-RoPE q/k (warp-per-head, barrier-free)
    qn2_kernel<<<S, 256>>>(qproj, qn);
    kn2_kernel<<<S, 256>>>(kproj, kn);
    knsum_part_kernel<<<dim3(NKV, 16), 128>>>(kn, knpart);
    knsum_final_kernel<<<1, 1024>>>(knpart, knsum);

    // compressive-memory retrieval + delta-rule prep in ONE launch
    memops_kernel<<<dim3(S / 16, NH + NKV), 128>>>(
        qn, kn, vproj, memory, norm_m, memout, vdelta);

    // RoPE (single fp16 planes); V transpose (single fp16 plane)
    rope_split_kernel<<<dim3(S, 10), 256>>>(qproj, kproj, pos, qh, kh);
    vtrans_split_kernel<<<dim3(S / 32, NKV * HD / 32), 256>>>(vproj, vth);

    // pure-fp16 flash attention (fuses gated combine, emits fp16 combined)
    attn_f16_kernel<<<dim3(S / 128, NH), 256, ATT2_SMEM_BYTES>>>(
        qh, kh, vth, memout, beta, ch);

    // output projection (fp16)
    gemm_f16_kernel<<<dim3(HID / 128, S / 128, 1), 128, GEMM4_SMEM>>>(
        ch, woT, out, HID, woT, out, woT, out, HID, HID);

    // memory & norm updates (fused; appended after the 8.4M-element `out`)
    delta_part_kernel<<<dim3(NKV, 8), 256>>>(kn, vdelta, dpart);
    finalize_kernel<<<(NKV * HD * HD) / 256, 256>>>(
        dpart, memory, norm_m, knsum,
        out + (size_t)S * HID, out + (size_t)S * HID + NKV * HD * HD);
}